// round 1
// baseline (speedup 1.0000x reference)
#include <cuda_runtime.h>
#include <math.h>

#define D_MODEL 1024
#define NHEAD 16
#define HEAD_DIM 64
#define B_ 2
#define L_ 2048
#define M_TOK 4096            // B_*L_
#define D_FF 4096
#define OUT_MAIN (M_TOK * D_MODEL)

// ---------------- scratch (device globals; no allocations allowed) ----------
__device__ float g_Q[M_TOK * D_MODEL];
__device__ float g_K[M_TOK * D_MODEL];
__device__ float g_V[M_TOK * D_MODEL];
__device__ float g_attn[M_TOK * D_MODEL];
__device__ float g_x[M_TOK * D_MODEL];
__device__ float g_y[M_TOK * D_MODEL];
__device__ float g_ff[M_TOK * D_FF];
__device__ float g_qbias[M_TOK * NHEAD];
__device__ float g_kbias[M_TOK * NHEAD];
__device__ float g_entpart[1024];

// ---------------- generic SGEMM: C = A[M,K] @ W[K,N] + bias (+res / gelu) ---
// MODE 0: +bias ; MODE 1: gelu(+bias) ; MODE 2: +bias +res
template <int MODE>
__global__ void __launch_bounds__(256) gemm_kernel(
    const float* __restrict__ A, const float* __restrict__ W,
    const float* __restrict__ bias, const float* __restrict__ res,
    float* __restrict__ C, int M, int N, int K)
{
    __shared__ float As[8][132];   // transposed A tile, padded
    __shared__ float Bs[8][128];

    int tid  = threadIdx.x;
    int brow = blockIdx.y << 7;
    int bcol = blockIdx.x << 7;

    int arow = tid >> 1;           // 0..127
    int acol = (tid & 1) << 2;     // 0 or 4
    int brW  = tid >> 5;           // 0..7
    int bcW  = (tid & 31) << 2;    // 0..124

    int tx = tid & 15, ty = tid >> 4;

    const float* Aptr = A + (size_t)(brow + arow) * K + acol;
    const float* Wptr = W + (size_t)brW * N + bcol + bcW;

    float acc[8][8];
#pragma unroll
    for (int i = 0; i < 8; i++)
#pragma unroll
        for (int j = 0; j < 8; j++) acc[i][j] = 0.0f;

    for (int k0 = 0; k0 < K; k0 += 8) {
        float4 av = *(const float4*)(Aptr + k0);
        As[acol + 0][arow] = av.x;
        As[acol + 1][arow] = av.y;
        As[acol + 2][arow] = av.z;
        As[acol + 3][arow] = av.w;
        *(float4*)&Bs[brW][bcW] = *(const float4*)(Wptr + (size_t)k0 * N);
        __syncthreads();

#pragma unroll
        for (int kk = 0; kk < 8; kk++) {
            float a[8], bb[8];
            *(float4*)(a)      = *(const float4*)&As[kk][ty * 8];
            *(float4*)(a + 4)  = *(const float4*)&As[kk][ty * 8 + 4];
            *(float4*)(bb)     = *(const float4*)&Bs[kk][tx * 8];
            *(float4*)(bb + 4) = *(const float4*)&Bs[kk][tx * 8 + 4];
#pragma unroll
            for (int i = 0; i < 8; i++)
#pragma unroll
                for (int j = 0; j < 8; j++) acc[i][j] += a[i] * bb[j];
        }
        __syncthreads();
    }

    float bv[8];
#pragma unroll
    for (int j = 0; j < 8; j++) bv[j] = bias[bcol + tx * 8 + j];

#pragma unroll
    for (int i = 0; i < 8; i++) {
        size_t r = (size_t)(brow + ty * 8 + i);
        float* crow = C + r * N + bcol + tx * 8;
        const float* rrow = (MODE == 2) ? (res + r * N + bcol + tx * 8) : (const float*)0;
#pragma unroll
        for (int j4 = 0; j4 < 8; j4 += 4) {
            float4 o;
            float v[4];
#pragma unroll
            for (int j = 0; j < 4; j++) {
                float t = acc[i][j4 + j] + bv[j4 + j];
                if (MODE == 1) t = 0.5f * t * (1.0f + erff(t * 0.70710678118654752f));
                if (MODE == 2) t += rrow[j4 + j];
                v[j] = t;
            }
            o.x = v[0]; o.y = v[1]; o.z = v[2]; o.w = v[3];
            *(float4*)(crow + j4) = o;
        }
    }
}

// ---------------- POS bias MLPs: relu(pos@w1+b1)@w2+b2 for q and k ----------
__global__ void __launch_bounds__(128) posbias_kernel(
    const float* __restrict__ pos,
    const float* __restrict__ qw1, const float* __restrict__ qb1,
    const float* __restrict__ qw2, const float* __restrict__ qb2,
    const float* __restrict__ kw1, const float* __restrict__ kb1,
    const float* __restrict__ kw2, const float* __restrict__ kb2,
    float* __restrict__ qbias, float* __restrict__ kbias)
{
    __shared__ float sw1q[32 * 32], sw2q[32 * 16], sb1q[32], sb2q[16];
    __shared__ float sw1k[32 * 32], sw2k[32 * 16], sb1k[32], sb2k[16];
    int tid = threadIdx.x;
    for (int i = tid; i < 1024; i += 128) { sw1q[i] = qw1[i]; sw1k[i] = kw1[i]; }
    for (int i = tid; i < 512;  i += 128) { sw2q[i] = qw2[i]; sw2k[i] = kw2[i]; }
    if (tid < 32) { sb1q[tid] = qb1[tid]; sb1k[tid] = kb1[tid]; }
    if (tid < 16) { sb2q[tid] = qb2[tid]; sb2k[tid] = kb2[tid]; }
    __syncthreads();

    int token = blockIdx.x * 128 + tid;
    float pf[32];
#pragma unroll
    for (int i = 0; i < 32; i++) pf[i] = pos[(size_t)token * 32 + i];

    float hq[32], hk[32];
#pragma unroll
    for (int j = 0; j < 32; j++) { hq[j] = sb1q[j]; hk[j] = sb1k[j]; }
    for (int i = 0; i < 32; i++) {
        float p = pf[i];
#pragma unroll
        for (int j = 0; j < 32; j++) {
            hq[j] += p * sw1q[i * 32 + j];
            hk[j] += p * sw1k[i * 32 + j];
        }
    }
#pragma unroll
    for (int j = 0; j < 32; j++) {
        hq[j] = fmaxf(hq[j], 0.0f);
        hk[j] = fmaxf(hk[j], 0.0f);
    }
#pragma unroll
    for (int h = 0; h < 16; h++) {
        float oq = sb2q[h], ok = sb2k[h];
        for (int j = 0; j < 32; j++) {
            oq += hq[j] * sw2q[j * 16 + h];
            ok += hk[j] * sw2k[j * 16 + h];
        }
        qbias[(size_t)token * NHEAD + h] = oq;
        kbias[(size_t)token * NHEAD + h] = ok;
    }
}

// ---------------- fused attention (flash-style, online softmax + entropy) ---
#define QT 64
#define KT 64
#define SSTR 68
#define ATTN_SMEM_FLOATS (4 * 64 * SSTR + 64 + 64 + 16)

__global__ void __launch_bounds__(256) attn_kernel(
    const float* __restrict__ Q, const float* __restrict__ K, const float* __restrict__ V,
    const float* __restrict__ qb, const float* __restrict__ kb,
    const float* __restrict__ temp,
    float* __restrict__ O, float* __restrict__ ent_part)
{
    extern __shared__ float sm[];
    float* Qs  = sm;
    float* Ks  = Qs + QT * SSTR;
    float* Vs  = Ks + KT * SSTR;
    float* Ps  = Vs + KT * SSTR;
    float* kbs = Ps + QT * SSTR;
    float* qbs = kbs + KT;
    float* red = qbs + QT;

    int tid = threadIdx.x;
    int tx = tid & 15, ty = tid >> 4;
    int q0 = blockIdx.x * QT;
    int h  = blockIdx.y;
    int b  = blockIdx.z;
    size_t tokbase = (size_t)b * L_;

    float tmph   = fminf(fmaxf(temp[h], 0.1f), 5.0f);
    float inv_t  = 1.0f / tmph;
    float qscale = inv_t * 0.125f;   // 1/sqrt(64) * 1/temp

    for (int i = tid; i < QT * 16; i += 256) {
        int row = i >> 4, c4 = (i & 15) << 2;
        float4 v = *(const float4*)&Q[(tokbase + q0 + row) * D_MODEL + h * HEAD_DIM + c4];
        float* dst = &Qs[row * SSTR + c4];
        dst[0] = v.x * qscale; dst[1] = v.y * qscale;
        dst[2] = v.z * qscale; dst[3] = v.w * qscale;
    }
    if (tid < QT) qbs[tid] = qb[(tokbase + q0 + tid) * NHEAD + h] * inv_t;
    __syncthreads();

    float qbr[4];
#pragma unroll
    for (int i = 0; i < 4; i++) qbr[i] = qbs[ty * 4 + i];

    float m_i[4], z_i[4], t_i[4], o[4][4];
#pragma unroll
    for (int i = 0; i < 4; i++) {
        m_i[i] = -1e30f; z_i[i] = 0.0f; t_i[i] = 0.0f;
#pragma unroll
        for (int j = 0; j < 4; j++) o[i][j] = 0.0f;
    }

    for (int c0 = 0; c0 < L_; c0 += KT) {
        for (int i = tid; i < KT * 16; i += 256) {
            int row = i >> 4, c4 = (i & 15) << 2;
            size_t g = (tokbase + c0 + row) * D_MODEL + h * HEAD_DIM + c4;
            *(float4*)&Ks[row * SSTR + c4] = *(const float4*)&K[g];
            *(float4*)&Vs[row * SSTR + c4] = *(const float4*)&V[g];
        }
        if (tid < KT) kbs[tid] = kb[(tokbase + c0 + tid) * NHEAD + h] * inv_t;
        __syncthreads();

        float kbc[4];
#pragma unroll
        for (int j = 0; j < 4; j++) kbc[j] = kbs[tx * 4 + j];

        float s[4][4];
#pragma unroll
        for (int i = 0; i < 4; i++)
#pragma unroll
            for (int j = 0; j < 4; j++) s[i][j] = qbr[i] + kbc[j];

#pragma unroll
        for (int kk = 0; kk < HEAD_DIM; kk += 4) {
            float4 qv[4], kv[4];
#pragma unroll
            for (int i = 0; i < 4; i++) qv[i] = *(const float4*)&Qs[(ty * 4 + i) * SSTR + kk];
#pragma unroll
            for (int j = 0; j < 4; j++) kv[j] = *(const float4*)&Ks[(tx * 4 + j) * SSTR + kk];
#pragma unroll
            for (int i = 0; i < 4; i++)
#pragma unroll
                for (int j = 0; j < 4; j++) {
                    s[i][j] += qv[i].x * kv[j].x;
                    s[i][j] += qv[i].y * kv[j].y;
                    s[i][j] += qv[i].z * kv[j].z;
                    s[i][j] += qv[i].w * kv[j].w;
                }
        }

        float nm[4], scale[4], sz[4], st[4];
#pragma unroll
        for (int i = 0; i < 4; i++) {
            float cm = fmaxf(fmaxf(s[i][0], s[i][1]), fmaxf(s[i][2], s[i][3]));
#pragma unroll
            for (int off = 1; off < 16; off <<= 1)
                cm = fmaxf(cm, __shfl_xor_sync(0xffffffffu, cm, off));
            nm[i]    = fmaxf(m_i[i], cm);
            scale[i] = __expf(m_i[i] - nm[i]);
            sz[i] = 0.0f; st[i] = 0.0f;
        }
#pragma unroll
        for (int i = 0; i < 4; i++)
#pragma unroll
            for (int j = 0; j < 4; j++) {
                float p = __expf(s[i][j] - nm[i]);
                sz[i] += p;
                st[i] += p * s[i][j];
                Ps[(ty * 4 + i) * SSTR + tx * 4 + j] = p;
            }
#pragma unroll
        for (int i = 0; i < 4; i++) {
#pragma unroll
            for (int off = 1; off < 16; off <<= 1) {
                sz[i] += __shfl_xor_sync(0xffffffffu, sz[i], off);
                st[i] += __shfl_xor_sync(0xffffffffu, st[i], off);
            }
            m_i[i] = nm[i];
            z_i[i] = z_i[i] * scale[i] + sz[i];
            t_i[i] = t_i[i] * scale[i] + st[i];
#pragma unroll
            for (int j = 0; j < 4; j++) o[i][j] *= scale[i];
        }
        __syncthreads();   // Ps visible to all

#pragma unroll 8
        for (int c = 0; c < KT; c++) {
            float4 vv = *(const float4*)&Vs[c * SSTR + tx * 4];
            float pr[4];
#pragma unroll
            for (int i = 0; i < 4; i++) pr[i] = Ps[(ty * 4 + i) * SSTR + c];
#pragma unroll
            for (int i = 0; i < 4; i++) {
                o[i][0] += pr[i] * vv.x;
                o[i][1] += pr[i] * vv.y;
                o[i][2] += pr[i] * vv.z;
                o[i][3] += pr[i] * vv.w;
            }
        }
        __syncthreads();   // done with Ks/Vs/Ps before next chunk
    }

#pragma unroll
    for (int i = 0; i < 4; i++) {
        float invz = 1.0f / z_i[i];
        float4 ov;
        ov.x = o[i][0] * invz; ov.y = o[i][1] * invz;
        ov.z = o[i][2] * invz; ov.w = o[i][3] * invz;
        *(float4*)&O[(tokbase + q0 + ty * 4 + i) * D_MODEL + h * HEAD_DIM + tx * 4] = ov;
    }

    if (tx == 0) {
        float es = 0.0f;
#pragma unroll
        for (int i = 0; i < 4; i++)
            es += m_i[i] + logf(z_i[i]) - t_i[i] / z_i[i];
        red[ty] = es;
    }
    __syncthreads();
    if (tid == 0) {
        float es = 0.0f;
        for (int i = 0; i < 16; i++) es += red[i];
        ent_part[(blockIdx.z * gridDim.y + blockIdx.y) * gridDim.x + blockIdx.x] = es;
    }
}

// ---------------- layernorm over last dim (1024) -----------------------------
__global__ void __launch_bounds__(256) ln_kernel(
    const float* __restrict__ in, const float* __restrict__ gam,
    const float* __restrict__ bet, float* __restrict__ out)
{
    int row = blockIdx.x, tid = threadIdx.x;
    float4 v = ((const float4*)(in + (size_t)row * D_MODEL))[tid];
    float s = v.x + v.y + v.z + v.w;
    float q = v.x * v.x + v.y * v.y + v.z * v.z + v.w * v.w;
#pragma unroll
    for (int off = 16; off; off >>= 1) {
        s += __shfl_xor_sync(0xffffffffu, s, off);
        q += __shfl_xor_sync(0xffffffffu, q, off);
    }
    __shared__ float ws[8], wq[8], stats[2];
    int lane = tid & 31, w = tid >> 5;
    if (lane == 0) { ws[w] = s; wq[w] = q; }
    __syncthreads();
    if (tid == 0) {
        float S = 0.0f, Qq = 0.0f;
        for (int i = 0; i < 8; i++) { S += ws[i]; Qq += wq[i]; }
        float mu  = S * (1.0f / D_MODEL);
        float var = Qq * (1.0f / D_MODEL) - mu * mu;
        stats[0] = mu;
        stats[1] = rsqrtf(var + 1e-5f);
    }
    __syncthreads();
    float mu = stats[0], rs = stats[1];
    float4 gv = ((const float4*)gam)[tid];
    float4 bv = ((const float4*)bet)[tid];
    float4 ov;
    ov.x = (v.x - mu) * rs * gv.x + bv.x;
    ov.y = (v.y - mu) * rs * gv.y + bv.y;
    ov.z = (v.z - mu) * rs * gv.z + bv.z;
    ov.w = (v.w - mu) * rs * gv.w + bv.w;
    ((float4*)(out + (size_t)row * D_MODEL))[tid] = ov;
}

// ---------------- deterministic entropy reduction ---------------------------
__global__ void __launch_bounds__(256) ent_final_kernel(
    const float* __restrict__ part, float* __restrict__ out, int out_size)
{
    __shared__ float sm[256];
    int tid = threadIdx.x;
    float s = part[tid] + part[tid + 256] + part[tid + 512] + part[tid + 768];
    sm[tid] = s;
    __syncthreads();
    for (int off = 128; off; off >>= 1) {
        if (tid < off) sm[tid] += sm[tid + off];
        __syncthreads();
    }
    if (tid == 0 && out_size > OUT_MAIN)
        out[OUT_MAIN] = sm[0] * (1.0f / (B_ * NHEAD * L_));
}

// ---------------- launch -----------------------------------------------------
extern "C" void kernel_launch(void* const* d_in, const int* in_sizes, int n_in,
                              void* d_out, int out_size)
{
    const float* src   = (const float*)d_in[0];
    const float* pos   = (const float*)d_in[1];
    const float* Wq    = (const float*)d_in[2];
    const float* bq    = (const float*)d_in[3];
    const float* Wk    = (const float*)d_in[4];
    const float* bk    = (const float*)d_in[5];
    const float* Wv    = (const float*)d_in[6];
    const float* bv    = (const float*)d_in[7];
    const float* Wo    = (const float*)d_in[8];
    const float* bo    = (const float*)d_in[9];
    const float* pq_w1 = (const float*)d_in[10];
    const float* pq_b1 = (const float*)d_in[11];
    const float* pq_w2 = (const float*)d_in[12];
    const float* pq_b2 = (const float*)d_in[13];
    const float* pk_w1 = (const float*)d_in[14];
    const float* pk_b1 = (const float*)d_in[15];
    const float* pk_w2 = (const float*)d_in[16];
    const float* pk_b2 = (const float*)d_in[17];
    const float* temp  = (const float*)d_in[18];
    const float* ln1g  = (const float*)d_in[19];
    const float* ln1b  = (const float*)d_in[20];
    const float* ln2g  = (const float*)d_in[21];
    const float* ln2b  = (const float*)d_in[22];
    const float* W1    = (const float*)d_in[23];
    const float* b1    = (const float*)d_in[24];
    const float* W2    = (const float*)d_in[25];
    const float* b2    = (const float*)d_in[26];
    float* out = (float*)d_out;

    float *Qb, *Kb, *Vb, *attnb, *xb, *yb, *ffb, *qbb, *kbb, *entp;
    cudaGetSymbolAddress((void**)&Qb, g_Q);
    cudaGetSymbolAddress((void**)&Kb, g_K);
    cudaGetSymbolAddress((void**)&Vb, g_V);
    cudaGetSymbolAddress((void**)&attnb, g_attn);
    cudaGetSymbolAddress((void**)&xb, g_x);
    cudaGetSymbolAddress((void**)&yb, g_y);
    cudaGetSymbolAddress((void**)&ffb, g_ff);
    cudaGetSymbolAddress((void**)&qbb, g_qbias);
    cudaGetSymbolAddress((void**)&kbb, g_kbias);
    cudaGetSymbolAddress((void**)&entp, g_entpart);

    // POS bias MLPs
    posbias_kernel<<<M_TOK / 128, 128>>>(pos, pq_w1, pq_b1, pq_w2, pq_b2,
                                         pk_w1, pk_b1, pk_w2, pk_b2, qbb, kbb);

    // QKV projections
    dim3 gD(D_MODEL / 128, M_TOK / 128);   // (8, 32)
    gemm_kernel<0><<<gD, 256>>>(src, Wq, bq, (const float*)0, Qb, M_TOK, D_MODEL, D_MODEL);
    gemm_kernel<0><<<gD, 256>>>(src, Wk, bk, (const float*)0, Kb, M_TOK, D_MODEL, D_MODEL);
    gemm_kernel<0><<<gD, 256>>>(src, Wv, bv, (const float*)0, Vb, M_TOK, D_MODEL, D_MODEL);

    // fused attention + entropy partials
    int attn_smem = ATTN_SMEM_FLOATS * (int)sizeof(float);
    cudaFuncSetAttribute(attn_kernel, cudaFuncAttributeMaxDynamicSharedMemorySize, attn_smem);
    attn_kernel<<<dim3(L_ / QT, NHEAD, B_), 256, attn_smem>>>(Qb, Kb, Vb, qbb, kbb, temp,
                                                              attnb, entp);

    // out proj + residual, LN1
    gemm_kernel<2><<<gD, 256>>>(attnb, Wo, bo, src, yb, M_TOK, D_MODEL, D_MODEL);
    ln_kernel<<<M_TOK, 256>>>(yb, ln1g, ln1b, xb);

    // FFN
    dim3 gF(D_FF / 128, M_TOK / 128);      // (32, 32)
    gemm_kernel<1><<<gF, 256>>>(xb, W1, b1, (const float*)0, ffb, M_TOK, D_FF, D_MODEL);
    gemm_kernel<2><<<gD, 256>>>(ffb, W2, b2, xb, yb, M_TOK, D_MODEL, D_FF);
    ln_kernel<<<M_TOK, 256>>>(yb, ln2g, ln2b, out);

    // entropy mean (deterministic fixed-order reduction)
    ent_final_kernel<<<1, 256>>>(entp, out, out_size);
}

// round 3
// speedup vs baseline: 1.4085x; 1.4085x over previous
#include <cuda_runtime.h>
#include <cuda_bf16.h>
#include <math.h>
#include <stdint.h>

#define D_MODEL 1024
#define NHEAD 16
#define HEAD_DIM 64
#define B_ 2
#define L_ 2048
#define M_TOK 4096
#define D_FF 4096
#define OUT_MAIN (M_TOK * D_MODEL)

// ---------------- scratch (device globals; no allocations allowed) ----------
__device__ float g_Q[M_TOK * D_MODEL];
__device__ float g_K[M_TOK * D_MODEL];
__device__ float g_V[M_TOK * D_MODEL];
__device__ float g_attn[M_TOK * D_MODEL];
__device__ float g_x[M_TOK * D_MODEL];
__device__ float g_y[M_TOK * D_MODEL];
__device__ float g_qbias[M_TOK * NHEAD];
__device__ float g_kbias[M_TOK * NHEAD];
__device__ float g_entpart[1024];
// bf16 split activations
__device__ __nv_bfloat16 g_src_h[M_TOK * D_MODEL];
__device__ __nv_bfloat16 g_src_l[M_TOK * D_MODEL];
__device__ __nv_bfloat16 g_at_h[M_TOK * D_MODEL];
__device__ __nv_bfloat16 g_at_l[M_TOK * D_MODEL];
__device__ __nv_bfloat16 g_x_h[M_TOK * D_MODEL];
__device__ __nv_bfloat16 g_x_l[M_TOK * D_MODEL];
__device__ __nv_bfloat16 g_ff_h[M_TOK * D_FF];
__device__ __nv_bfloat16 g_ff_l[M_TOK * D_FF];
// bf16 split transposed weights [N, K]
__device__ __nv_bfloat16 g_wq_h[D_MODEL * D_MODEL];
__device__ __nv_bfloat16 g_wq_l[D_MODEL * D_MODEL];
__device__ __nv_bfloat16 g_wk_h[D_MODEL * D_MODEL];
__device__ __nv_bfloat16 g_wk_l[D_MODEL * D_MODEL];
__device__ __nv_bfloat16 g_wv_h[D_MODEL * D_MODEL];
__device__ __nv_bfloat16 g_wv_l[D_MODEL * D_MODEL];
__device__ __nv_bfloat16 g_wo_h[D_MODEL * D_MODEL];
__device__ __nv_bfloat16 g_wo_l[D_MODEL * D_MODEL];
__device__ __nv_bfloat16 g_w1_h[D_FF * D_MODEL];
__device__ __nv_bfloat16 g_w1_l[D_FF * D_MODEL];
__device__ __nv_bfloat16 g_w2_h[D_MODEL * D_FF];
__device__ __nv_bfloat16 g_w2_l[D_MODEL * D_FF];

// ======================= PTX helpers (baseline sm_103-legal only) ===========
__device__ __forceinline__ uint32_t smem_u32(const void* p) {
    uint32_t a;
    asm("{ .reg .u64 t; cvta.to.shared.u64 t, %1; cvt.u32.u64 %0, t; }" : "=r"(a) : "l"(p));
    return a;
}
__device__ __forceinline__ void cp16(uint32_t s, const void* g) {
    asm volatile("cp.async.cg.shared.global [%0], [%1], 16;" :: "r"(s), "l"(g));
}
#define CP_COMMIT() asm volatile("cp.async.commit_group;" ::: "memory")

__device__ __forceinline__ void ldsm4(uint32_t* r, uint32_t addr) {
    asm volatile("ldmatrix.sync.aligned.m8n8.x4.shared.b16 {%0,%1,%2,%3}, [%4];"
                 : "=r"(r[0]), "=r"(r[1]), "=r"(r[2]), "=r"(r[3]) : "r"(addr));
}
__device__ __forceinline__ void mma16816(float* d, const uint32_t* a, uint32_t b0, uint32_t b1) {
    asm volatile(
        "mma.sync.aligned.m16n8k16.row.col.f32.bf16.bf16.f32 "
        "{%0,%1,%2,%3}, {%4,%5,%6,%7}, {%8,%9}, {%0,%1,%2,%3};"
        : "+f"(d[0]), "+f"(d[1]), "+f"(d[2]), "+f"(d[3])
        : "r"(a[0]), "r"(a[1]), "r"(a[2]), "r"(a[3]), "r"(b0), "r"(b1));
}

// ======================= warp-MMA split-bf16 GEMM ===========================
// C[M,N] = A[M,K] @ B[N,K]^T, A=Ah+Al, B=Bh+Bl, acc = AhBh + AhBl + AlBh (fp32)
// MODE 0: C = acc + bias          MODE 1: gelu(acc+bias) -> Ch/Cl (bf16 split)
// MODE 2: C = acc + bias + res
#define BM 128
#define BN 128
#define BKC 32
#define RSTR 80                    // bytes per smem row (32 bf16 + 8 pad)
#define TILE_B (128 * RSTR)        // 10240
#define STAGE_B (4 * TILE_B)       // 40960 : Ah, Al, Bh, Bl
#define NSTAGE 3
#define GEMM_SMEM (NSTAGE * STAGE_B)

__device__ __forceinline__ void g_load_chunk(
    uint32_t smem, int ci, int m0, int n0, int K, int tid,
    const __nv_bfloat16* __restrict__ Ah, const __nv_bfloat16* __restrict__ Al,
    const __nv_bfloat16* __restrict__ Bh, const __nv_bfloat16* __restrict__ Bl)
{
    uint32_t sb = smem + (uint32_t)(ci % NSTAGE) * STAGE_B;
    size_t kbase = (size_t)ci * BKC;
#pragma unroll
    for (int t = 0; t < 4; t++) {
        const __nv_bfloat16* P = (t == 0) ? Ah : (t == 1) ? Al : (t == 2) ? Bh : Bl;
        int r0 = (t < 2) ? m0 : n0;
        uint32_t tb = sb + (uint32_t)t * TILE_B;
#pragma unroll
        for (int rep = 0; rep < 2; rep++) {
            int seg = tid + (rep << 8);        // 0..511
            int row = seg >> 2;
            int s4  = seg & 3;
            cp16(tb + (uint32_t)row * RSTR + (uint32_t)s4 * 16,
                 P + (size_t)(r0 + row) * K + kbase + s4 * 8);
        }
    }
}

template <int MODE>
__global__ void __launch_bounds__(256, 1) tcgemm_kernel(
    const __nv_bfloat16* __restrict__ Ah, const __nv_bfloat16* __restrict__ Al,
    const __nv_bfloat16* __restrict__ Bh, const __nv_bfloat16* __restrict__ Bl,
    const float* __restrict__ bias, const float* __restrict__ res,
    float* __restrict__ C, __nv_bfloat16* __restrict__ Ch, __nv_bfloat16* __restrict__ Cl,
    int M, int N, int K)
{
    extern __shared__ char dsm[];
    uint32_t smem = smem_u32(dsm);

    int tid = threadIdx.x;
    int wid = tid >> 5;
    int lane = tid & 31;
    int m0 = blockIdx.y * BM;
    int n0 = blockIdx.x * BN;
    int nchunk = K / BKC;

    int wm = wid & 1;          // 2 M-groups of 64
    int wn = wid >> 1;         // 4 N-groups of 32

    // ldmatrix lane addressing: lanes 0-15 -> rows 0-15, lanes 16-31 -> k+8 half
    int lr = lane & 15;
    uint32_t lk = (uint32_t)((lane >> 4) << 4);

    float acc[4][4][4];
#pragma unroll
    for (int i = 0; i < 4; i++)
#pragma unroll
        for (int j = 0; j < 4; j++)
#pragma unroll
            for (int c = 0; c < 4; c++) acc[i][j][c] = 0.0f;

    g_load_chunk(smem, 0, m0, n0, K, tid, Ah, Al, Bh, Bl);
    CP_COMMIT();
    g_load_chunk(smem, 1, m0, n0, K, tid, Ah, Al, Bh, Bl);
    CP_COMMIT();

    for (int i = 0; i < nchunk; i++) {
        if (i < nchunk - 1)
            asm volatile("cp.async.wait_group 1;" ::: "memory");
        else
            asm volatile("cp.async.wait_group 0;" ::: "memory");
        __syncthreads();

        if (i + 2 < nchunk) {
            g_load_chunk(smem, i + 2, m0, n0, K, tid, Ah, Al, Bh, Bl);
            CP_COMMIT();
        }

        uint32_t sb = smem + (uint32_t)(i % NSTAGE) * STAGE_B;
        uint32_t aBase = sb + (uint32_t)(wm * 64 + lr) * RSTR + lk;                 // Ah
        uint32_t bBase = sb + 2u * TILE_B + (uint32_t)(wn * 32 + lr) * RSTR + lk;   // Bh

#pragma unroll
        for (int ks = 0; ks < 2; ks++) {
            uint32_t koff = (uint32_t)ks * 32;
            uint32_t ah[4][4], al[4][4], bh[2][4], bl[2][4];
#pragma unroll
            for (int mt = 0; mt < 4; mt++) {
                ldsm4(ah[mt], aBase + (uint32_t)(mt * 16) * RSTR + koff);
                ldsm4(al[mt], aBase + TILE_B + (uint32_t)(mt * 16) * RSTR + koff);
            }
#pragma unroll
            for (int nt = 0; nt < 2; nt++) {
                ldsm4(bh[nt], bBase + (uint32_t)(nt * 16) * RSTR + koff);
                ldsm4(bl[nt], bBase + TILE_B + (uint32_t)(nt * 16) * RSTR + koff);
            }
#pragma unroll
            for (int mt = 0; mt < 4; mt++)
#pragma unroll
                for (int nt = 0; nt < 2; nt++) {
                    mma16816(acc[mt][nt * 2],     ah[mt], bh[nt][0], bh[nt][2]);
                    mma16816(acc[mt][nt * 2 + 1], ah[mt], bh[nt][1], bh[nt][3]);
                    mma16816(acc[mt][nt * 2],     ah[mt], bl[nt][0], bl[nt][2]);
                    mma16816(acc[mt][nt * 2 + 1], ah[mt], bl[nt][1], bl[nt][3]);
                    mma16816(acc[mt][nt * 2],     al[mt], bh[nt][0], bh[nt][2]);
                    mma16816(acc[mt][nt * 2 + 1], al[mt], bh[nt][1], bh[nt][3]);
                }
        }
    }

    // epilogue: C frag m16n8 -> c0,c1: row=lane>>2, cols 2*(lane&3)(+1); c2,c3: row+8
    int rbase = m0 + wm * 64 + (lane >> 2);
    int cbase = n0 + wn * 32 + (lane & 3) * 2;
#pragma unroll
    for (int mt = 0; mt < 4; mt++) {
#pragma unroll
        for (int n8 = 0; n8 < 4; n8++) {
            int col = cbase + n8 * 8;
            float b0 = bias[col], b1 = bias[col + 1];
#pragma unroll
            for (int half = 0; half < 2; half++) {
                int row = rbase + mt * 16 + half * 8;
                float v0 = acc[mt][n8][half * 2] + b0;
                float v1 = acc[mt][n8][half * 2 + 1] + b1;
                if (MODE == 1) {
                    v0 = 0.5f * v0 * (1.0f + erff(v0 * 0.70710678118654752f));
                    v1 = 0.5f * v1 * (1.0f + erff(v1 * 0.70710678118654752f));
                }
                if (MODE == 2) {
                    const float2 rv = *(const float2*)(res + (size_t)row * N + col);
                    v0 += rv.x; v1 += rv.y;
                }
                if (MODE == 0 || MODE == 2) {
                    float2 o; o.x = v0; o.y = v1;
                    *(float2*)(C + (size_t)row * N + col) = o;
                } else {
                    __nv_bfloat16 h0 = __float2bfloat16(v0);
                    __nv_bfloat16 h1 = __float2bfloat16(v1);
                    __nv_bfloat16 l0 = __float2bfloat16(v0 - __bfloat162float(h0));
                    __nv_bfloat16 l1 = __float2bfloat16(v1 - __bfloat162float(h1));
                    *(__nv_bfloat162*)(Ch + (size_t)row * N + col) = __nv_bfloat162(h0, h1);
                    *(__nv_bfloat162*)(Cl + (size_t)row * N + col) = __nv_bfloat162(l0, l1);
                }
            }
        }
    }
}

// ======================= weight transpose + split ===========================
__global__ void __launch_bounds__(256) convT_kernel(
    const float* __restrict__ W, __nv_bfloat16* __restrict__ hi, __nv_bfloat16* __restrict__ lo,
    int K, int N)
{
    __shared__ float t[32][33];
    int n0 = blockIdx.x * 32, k0 = blockIdx.y * 32;
    int tx = threadIdx.x & 31, ty = threadIdx.x >> 5;
#pragma unroll
    for (int i = 0; i < 32; i += 8)
        t[ty + i][tx] = W[(size_t)(k0 + ty + i) * N + n0 + tx];
    __syncthreads();
#pragma unroll
    for (int i = 0; i < 32; i += 8) {
        float v = t[tx][ty + i];
        __nv_bfloat16 h = __float2bfloat16(v);
        __nv_bfloat16 l = __float2bfloat16(v - __bfloat162float(h));
        size_t o = (size_t)(n0 + ty + i) * K + k0 + tx;
        hi[o] = h; lo[o] = l;
    }
}

__global__ void __launch_bounds__(256) conv_kernel(
    const float* __restrict__ in, __nv_bfloat16* __restrict__ hi, __nv_bfloat16* __restrict__ lo, int n4)
{
    int i = blockIdx.x * 256 + threadIdx.x;
    if (i >= n4) return;
    float4 v = ((const float4*)in)[i];
    __nv_bfloat16 h0 = __float2bfloat16(v.x), h1 = __float2bfloat16(v.y);
    __nv_bfloat16 h2 = __float2bfloat16(v.z), h3 = __float2bfloat16(v.w);
    __nv_bfloat16 l0 = __float2bfloat16(v.x - __bfloat162float(h0));
    __nv_bfloat16 l1 = __float2bfloat16(v.y - __bfloat162float(h1));
    __nv_bfloat16 l2 = __float2bfloat16(v.z - __bfloat162float(h2));
    __nv_bfloat16 l3 = __float2bfloat16(v.w - __bfloat162float(h3));
    ((__nv_bfloat162*)hi)[i * 2]     = __nv_bfloat162(h0, h1);
    ((__nv_bfloat162*)hi)[i * 2 + 1] = __nv_bfloat162(h2, h3);
    ((__nv_bfloat162*)lo)[i * 2]     = __nv_bfloat162(l0, l1);
    ((__nv_bfloat162*)lo)[i * 2 + 1] = __nv_bfloat162(l2, l3);
}

// ---------------- POS bias MLPs ----------------------------------------------
__global__ void __launch_bounds__(128) posbias_kernel(
    const float* __restrict__ pos,
    const float* __restrict__ qw1, const float* __restrict__ qb1,
    const float* __restrict__ qw2, const float* __restrict__ qb2,
    const float* __restrict__ kw1, const float* __restrict__ kb1,
    const float* __restrict__ kw2, const float* __restrict__ kb2,
    float* __restrict__ qbias, float* __restrict__ kbias)
{
    __shared__ float sw1q[32 * 32], sw2q[32 * 16], sb1q[32], sb2q[16];
    __shared__ float sw1k[32 * 32], sw2k[32 * 16], sb1k[32], sb2k[16];
    int tid = threadIdx.x;
    for (int i = tid; i < 1024; i += 128) { sw1q[i] = qw1[i]; sw1k[i] = kw1[i]; }
    for (int i = tid; i < 512;  i += 128) { sw2q[i] = qw2[i]; sw2k[i] = kw2[i]; }
    if (tid < 32) { sb1q[tid] = qb1[tid]; sb1k[tid] = kb1[tid]; }
    if (tid < 16) { sb2q[tid] = qb2[tid]; sb2k[tid] = kb2[tid]; }
    __syncthreads();

    int token = blockIdx.x * 128 + tid;
    float pf[32];
#pragma unroll
    for (int i = 0; i < 32; i++) pf[i] = pos[(size_t)token * 32 + i];

    float hq[32], hk[32];
#pragma unroll
    for (int j = 0; j < 32; j++) { hq[j] = sb1q[j]; hk[j] = sb1k[j]; }
    for (int i = 0; i < 32; i++) {
        float p = pf[i];
#pragma unroll
        for (int j = 0; j < 32; j++) {
            hq[j] += p * sw1q[i * 32 + j];
            hk[j] += p * sw1k[i * 32 + j];
        }
    }
#pragma unroll
    for (int j = 0; j < 32; j++) {
        hq[j] = fmaxf(hq[j], 0.0f);
        hk[j] = fmaxf(hk[j], 0.0f);
    }
#pragma unroll
    for (int h = 0; h < 16; h++) {
        float oq = sb2q[h], ok = sb2k[h];
        for (int j = 0; j < 32; j++) {
            oq += hq[j] * sw2q[j * 16 + h];
            ok += hk[j] * sw2k[j * 16 + h];
        }
        qbias[(size_t)token * NHEAD + h] = oq;
        kbias[(size_t)token * NHEAD + h] = ok;
    }
}

// ---------------- fused attention (fp32, unchanged) --------------------------
#define QT 64
#define KT 64
#define SSTR 68
#define ATTN_SMEM_FLOATS (4 * 64 * SSTR + 64 + 64 + 16)

__global__ void __launch_bounds__(256) attn_kernel(
    const float* __restrict__ Q, const float* __restrict__ K, const float* __restrict__ V,
    const float* __restrict__ qb, const float* __restrict__ kb,
    const float* __restrict__ temp,
    float* __restrict__ O, float* __restrict__ ent_part)
{
    extern __shared__ float sm[];
    float* Qs  = sm;
    float* Ks  = Qs + QT * SSTR;
    float* Vs  = Ks + KT * SSTR;
    float* Ps  = Vs + KT * SSTR;
    float* kbs = Ps + QT * SSTR;
    float* qbs = kbs + KT;
    float* red = qbs + QT;

    int tid = threadIdx.x;
    int tx = tid & 15, ty = tid >> 4;
    int q0 = blockIdx.x * QT;
    int h  = blockIdx.y;
    int b  = blockIdx.z;
    size_t tokbase = (size_t)b * L_;

    float tmph   = fminf(fmaxf(temp[h], 0.1f), 5.0f);
    float inv_t  = 1.0f / tmph;
    float qscale = inv_t * 0.125f;

    for (int i = tid; i < QT * 16; i += 256) {
        int row = i >> 4, c4 = (i & 15) << 2;
        float4 v = *(const float4*)&Q[(tokbase + q0 + row) * D_MODEL + h * HEAD_DIM + c4];
        float* dst = &Qs[row * SSTR + c4];
        dst[0] = v.x * qscale; dst[1] = v.y * qscale;
        dst[2] = v.z * qscale; dst[3] = v.w * qscale;
    }
    if (tid < QT) qbs[tid] = qb[(tokbase + q0 + tid) * NHEAD + h] * inv_t;
    __syncthreads();

    float qbr[4];
#pragma unroll
    for (int i = 0; i < 4; i++) qbr[i] = qbs[ty * 4 + i];

    float m_i[4], z_i[4], t_i[4], o[4][4];
#pragma unroll
    for (int i = 0; i < 4; i++) {
        m_i[i] = -1e30f; z_i[i] = 0.0f; t_i[i] = 0.0f;
#pragma unroll
        for (int j = 0; j < 4; j++) o[i][j] = 0.0f;
    }

    for (int c0 = 0; c0 < L_; c0 += KT) {
        for (int i = tid; i < KT * 16; i += 256) {
            int row = i >> 4, c4 = (i & 15) << 2;
            size_t g = (tokbase + c0 + row) * D_MODEL + h * HEAD_DIM + c4;
            *(float4*)&Ks[row * SSTR + c4] = *(const float4*)&K[g];
            *(float4*)&Vs[row * SSTR + c4] = *(const float4*)&V[g];
        }
        if (tid < KT) kbs[tid] = kb[(tokbase + c0 + tid) * NHEAD + h] * inv_t;
        __syncthreads();

        float kbc[4];
#pragma unroll
        for (int j = 0; j < 4; j++) kbc[j] = kbs[tx * 4 + j];

        float s[4][4];
#pragma unroll
        for (int i = 0; i < 4; i++)
#pragma unroll
            for (int j = 0; j < 4; j++) s[i][j] = qbr[i] + kbc[j];

#pragma unroll
        for (int kk = 0; kk < HEAD_DIM; kk += 4) {
            float4 qv[4], kv[4];
#pragma unroll
            for (int i = 0; i < 4; i++) qv[i] = *(const float4*)&Qs[(ty * 4 + i) * SSTR + kk];
#pragma unroll
            for (int j = 0; j < 4; j++) kv[j] = *(const float4*)&Ks[(tx * 4 + j) * SSTR + kk];
#pragma unroll
            for (int i = 0; i < 4; i++)
#pragma unroll
                for (int j = 0; j < 4; j++) {
                    s[i][j] += qv[i].x * kv[j].x;
                    s[i][j] += qv[i].y * kv[j].y;
                    s[i][j] += qv[i].z * kv[j].z;
                    s[i][j] += qv[i].w * kv[j].w;
                }
        }

        float nm[4], scale[4], sz[4], st[4];
#pragma unroll
        for (int i = 0; i < 4; i++) {
            float cm = fmaxf(fmaxf(s[i][0], s[i][1]), fmaxf(s[i][2], s[i][3]));
#pragma unroll
            for (int off = 1; off < 16; off <<= 1)
                cm = fmaxf(cm, __shfl_xor_sync(0xffffffffu, cm, off));
            nm[i]    = fmaxf(m_i[i], cm);
            scale[i] = __expf(m_i[i] - nm[i]);
            sz[i] = 0.0f; st[i] = 0.0f;
        }
#pragma unroll
        for (int i = 0; i < 4; i++)
#pragma unroll
            for (int j = 0; j < 4; j++) {
                float p = __expf(s[i][j] - nm[i]);
                sz[i] += p;
                st[i] += p * s[i][j];
                Ps[(ty * 4 + i) * SSTR + tx * 4 + j] = p;
            }
#pragma unroll
        for (int i = 0; i < 4; i++) {
#pragma unroll
            for (int off = 1; off < 16; off <<= 1) {
                sz[i] += __shfl_xor_sync(0xffffffffu, sz[i], off);
                st[i] += __shfl_xor_sync(0xffffffffu, st[i], off);
            }
            m_i[i] = nm[i];
            z_i[i] = z_i[i] * scale[i] + sz[i];
            t_i[i] = t_i[i] * scale[i] + st[i];
#pragma unroll
            for (int j = 0; j < 4; j++) o[i][j] *= scale[i];
        }
        __syncthreads();

#pragma unroll 8
        for (int c = 0; c < KT; c++) {
            float4 vv = *(const float4*)&Vs[c * SSTR + tx * 4];
            float pr[4];
#pragma unroll
            for (int i = 0; i < 4; i++) pr[i] = Ps[(ty * 4 + i) * SSTR + c];
#pragma unroll
            for (int i = 0; i < 4; i++) {
                o[i][0] += pr[i] * vv.x;
                o[i][1] += pr[i] * vv.y;
                o[i][2] += pr[i] * vv.z;
                o[i][3] += pr[i] * vv.w;
            }
        }
        __syncthreads();
    }

#pragma unroll
    for (int i = 0; i < 4; i++) {
        float invz = 1.0f / z_i[i];
        float4 ov;
        ov.x = o[i][0] * invz; ov.y = o[i][1] * invz;
        ov.z = o[i][2] * invz; ov.w = o[i][3] * invz;
        *(float4*)&O[(tokbase + q0 + ty * 4 + i) * D_MODEL + h * HEAD_DIM + tx * 4] = ov;
    }

    if (tx == 0) {
        float es = 0.0f;
#pragma unroll
        for (int i = 0; i < 4; i++)
            es += m_i[i] + logf(z_i[i]) - t_i[i] / z_i[i];
        red[ty] = es;
    }
    __syncthreads();
    if (tid == 0) {
        float es = 0.0f;
        for (int i = 0; i < 16; i++) es += red[i];
        ent_part[(blockIdx.z * gridDim.y + blockIdx.y) * gridDim.x + blockIdx.x] = es;
    }
}

// ---------------- layernorm (optionally emits bf16 hi/lo split) --------------
template <int SPLIT>
__global__ void __launch_bounds__(256) ln_kernel(
    const float* __restrict__ in, const float* __restrict__ gam,
    const float* __restrict__ bet, float* __restrict__ out,
    __nv_bfloat16* __restrict__ oh, __nv_bfloat16* __restrict__ ol)
{
    int row = blockIdx.x, tid = threadIdx.x;
    float4 v = ((const float4*)(in + (size_t)row * D_MODEL))[tid];
    float s = v.x + v.y + v.z + v.w;
    float q = v.x * v.x + v.y * v.y + v.z * v.z + v.w * v.w;
#pragma unroll
    for (int off = 16; off; off >>= 1) {
        s += __shfl_xor_sync(0xffffffffu, s, off);
        q += __shfl_xor_sync(0xffffffffu, q, off);
    }
    __shared__ float ws[8], wq[8], stats[2];
    int lane = tid & 31, w = tid >> 5;
    if (lane == 0) { ws[w] = s; wq[w] = q; }
    __syncthreads();
    if (tid == 0) {
        float S = 0.0f, Qq = 0.0f;
        for (int i = 0; i < 8; i++) { S += ws[i]; Qq += wq[i]; }
        float mu  = S * (1.0f / D_MODEL);
        float var = Qq * (1.0f / D_MODEL) - mu * mu;
        stats[0] = mu;
        stats[1] = rsqrtf(var + 1e-5f);
    }
    __syncthreads();
    float mu = stats[0], rs = stats[1];
    float4 gv = ((const float4*)gam)[tid];
    float4 bv = ((const float4*)bet)[tid];
    float4 ov;
    ov.x = (v.x - mu) * rs * gv.x + bv.x;
    ov.y = (v.y - mu) * rs * gv.y + bv.y;
    ov.z = (v.z - mu) * rs * gv.z + bv.z;
    ov.w = (v.w - mu) * rs * gv.w + bv.w;
    ((float4*)(out + (size_t)row * D_MODEL))[tid] = ov;
    if (SPLIT) {
        __nv_bfloat16 h0 = __float2bfloat16(ov.x), h1 = __float2bfloat16(ov.y);
        __nv_bfloat16 h2 = __float2bfloat16(ov.z), h3 = __float2bfloat16(ov.w);
        __nv_bfloat16 l0 = __float2bfloat16(ov.x - __bfloat162float(h0));
        __nv_bfloat16 l1 = __float2bfloat16(ov.y - __bfloat162float(h1));
        __nv_bfloat16 l2 = __float2bfloat16(ov.z - __bfloat162float(h2));
        __nv_bfloat16 l3 = __float2bfloat16(ov.w - __bfloat162float(h3));
        size_t base = (size_t)row * D_MODEL + tid * 4;
        *(__nv_bfloat162*)(oh + base)     = __nv_bfloat162(h0, h1);
        *(__nv_bfloat162*)(oh + base + 2) = __nv_bfloat162(h2, h3);
        *(__nv_bfloat162*)(ol + base)     = __nv_bfloat162(l0, l1);
        *(__nv_bfloat162*)(ol + base + 2) = __nv_bfloat162(l2, l3);
    }
}

// ---------------- deterministic entropy reduction ----------------------------
__global__ void __launch_bounds__(256) ent_final_kernel(
    const float* __restrict__ part, float* __restrict__ out, int out_size)
{
    __shared__ float sm[256];
    int tid = threadIdx.x;
    float s = part[tid] + part[tid + 256] + part[tid + 512] + part[tid + 768];
    sm[tid] = s;
    __syncthreads();
    for (int off = 128; off; off >>= 1) {
        if (tid < off) sm[tid] += sm[tid + off];
        __syncthreads();
    }
    if (tid == 0 && out_size > OUT_MAIN)
        out[OUT_MAIN] = sm[0] * (1.0f / (B_ * NHEAD * L_));
}

// ---------------- launch -----------------------------------------------------
extern "C" void kernel_launch(void* const* d_in, const int* in_sizes, int n_in,
                              void* d_out, int out_size)
{
    const float* src   = (const float*)d_in[0];
    const float* pos   = (const float*)d_in[1];
    const float* Wq    = (const float*)d_in[2];
    const float* bq    = (const float*)d_in[3];
    const float* Wk    = (const float*)d_in[4];
    const float* bk    = (const float*)d_in[5];
    const float* Wv    = (const float*)d_in[6];
    const float* bv    = (const float*)d_in[7];
    const float* Wo    = (const float*)d_in[8];
    const float* bo    = (const float*)d_in[9];
    const float* pq_w1 = (const float*)d_in[10];
    const float* pq_b1 = (const float*)d_in[11];
    const float* pq_w2 = (const float*)d_in[12];
    const float* pq_b2 = (const float*)d_in[13];
    const float* pk_w1 = (const float*)d_in[14];
    const float* pk_b1 = (const float*)d_in[15];
    const float* pk_w2 = (const float*)d_in[16];
    const float* pk_b2 = (const float*)d_in[17];
    const float* temp  = (const float*)d_in[18];
    const float* ln1g  = (const float*)d_in[19];
    const float* ln1b  = (const float*)d_in[20];
    const float* ln2g  = (const float*)d_in[21];
    const float* ln2b  = (const float*)d_in[22];
    const float* W1    = (const float*)d_in[23];
    const float* b1    = (const float*)d_in[24];
    const float* W2    = (const float*)d_in[25];
    const float* b2    = (const float*)d_in[26];
    float* out = (float*)d_out;

    float *Qb, *Kb, *Vb, *attnb, *xb, *yb, *qbb, *kbb, *entp;
    cudaGetSymbolAddress((void**)&Qb, g_Q);
    cudaGetSymbolAddress((void**)&Kb, g_K);
    cudaGetSymbolAddress((void**)&Vb, g_V);
    cudaGetSymbolAddress((void**)&attnb, g_attn);
    cudaGetSymbolAddress((void**)&xb, g_x);
    cudaGetSymbolAddress((void**)&yb, g_y);
    cudaGetSymbolAddress((void**)&qbb, g_qbias);
    cudaGetSymbolAddress((void**)&kbb, g_kbias);
    cudaGetSymbolAddress((void**)&entp, g_entpart);

    __nv_bfloat16 *srch, *srcl, *ath, *atl, *xh, *xl, *ffh, *ffl;
    __nv_bfloat16 *wqh, *wql, *wkh, *wkl, *wvh, *wvl, *woh, *wol, *w1h, *w1l, *w2h, *w2l;
    cudaGetSymbolAddress((void**)&srch, g_src_h); cudaGetSymbolAddress((void**)&srcl, g_src_l);
    cudaGetSymbolAddress((void**)&ath, g_at_h);   cudaGetSymbolAddress((void**)&atl, g_at_l);
    cudaGetSymbolAddress((void**)&xh, g_x_h);     cudaGetSymbolAddress((void**)&xl, g_x_l);
    cudaGetSymbolAddress((void**)&ffh, g_ff_h);   cudaGetSymbolAddress((void**)&ffl, g_ff_l);
    cudaGetSymbolAddress((void**)&wqh, g_wq_h);   cudaGetSymbolAddress((void**)&wql, g_wq_l);
    cudaGetSymbolAddress((void**)&wkh, g_wk_h);   cudaGetSymbolAddress((void**)&wkl, g_wk_l);
    cudaGetSymbolAddress((void**)&wvh, g_wv_h);   cudaGetSymbolAddress((void**)&wvl, g_wv_l);
    cudaGetSymbolAddress((void**)&woh, g_wo_h);   cudaGetSymbolAddress((void**)&wol, g_wo_l);
    cudaGetSymbolAddress((void**)&w1h, g_w1_h);   cudaGetSymbolAddress((void**)&w1l, g_w1_l);
    cudaGetSymbolAddress((void**)&w2h, g_w2_h);   cudaGetSymbolAddress((void**)&w2l, g_w2_l);

    cudaFuncSetAttribute(tcgemm_kernel<0>, cudaFuncAttributeMaxDynamicSharedMemorySize, GEMM_SMEM);
    cudaFuncSetAttribute(tcgemm_kernel<1>, cudaFuncAttributeMaxDynamicSharedMemorySize, GEMM_SMEM);
    cudaFuncSetAttribute(tcgemm_kernel<2>, cudaFuncAttributeMaxDynamicSharedMemorySize, GEMM_SMEM);
    int attn_smem = ATTN_SMEM_FLOATS * (int)sizeof(float);
    cudaFuncSetAttribute(attn_kernel, cudaFuncAttributeMaxDynamicSharedMemorySize, attn_smem);

    // weight transpose + split
    dim3 ct(32, 32);
    convT_kernel<<<ct, 256>>>(Wq, wqh, wql, D_MODEL, D_MODEL);
    convT_kernel<<<ct, 256>>>(Wk, wkh, wkl, D_MODEL, D_MODEL);
    convT_kernel<<<ct, 256>>>(Wv, wvh, wvl, D_MODEL, D_MODEL);
    convT_kernel<<<ct, 256>>>(Wo, woh, wol, D_MODEL, D_MODEL);
    convT_kernel<<<dim3(D_FF / 32, D_MODEL / 32), 256>>>(W1, w1h, w1l, D_MODEL, D_FF);
    convT_kernel<<<dim3(D_MODEL / 32, D_FF / 32), 256>>>(W2, w2h, w2l, D_FF, D_MODEL);

    // src split + pos bias
    conv_kernel<<<(M_TOK * D_MODEL / 4 + 255) / 256, 256>>>(src, srch, srcl, M_TOK * D_MODEL / 4);
    posbias_kernel<<<M_TOK / 128, 128>>>(pos, pq_w1, pq_b1, pq_w2, pq_b2,
                                         pk_w1, pk_b1, pk_w2, pk_b2, qbb, kbb);

    // QKV projections (warp-MMA)
    dim3 gD(D_MODEL / BN, M_TOK / BM);   // (8, 32)
    tcgemm_kernel<0><<<gD, 256, GEMM_SMEM>>>(srch, srcl, wqh, wql, bq, (const float*)0,
                                             Qb, (__nv_bfloat16*)0, (__nv_bfloat16*)0,
                                             M_TOK, D_MODEL, D_MODEL);
    tcgemm_kernel<0><<<gD, 256, GEMM_SMEM>>>(srch, srcl, wkh, wkl, bk, (const float*)0,
                                             Kb, (__nv_bfloat16*)0, (__nv_bfloat16*)0,
                                             M_TOK, D_MODEL, D_MODEL);
    tcgemm_kernel<0><<<gD, 256, GEMM_SMEM>>>(srch, srcl, wvh, wvl, bv, (const float*)0,
                                             Vb, (__nv_bfloat16*)0, (__nv_bfloat16*)0,
                                             M_TOK, D_MODEL, D_MODEL);

    // attention
    attn_kernel<<<dim3(L_ / QT, NHEAD, B_), 256, attn_smem>>>(Qb, Kb, Vb, qbb, kbb, temp,
                                                              attnb, entp);

    // attn split -> Wo GEMM + residual -> LN1 (split out)
    conv_kernel<<<(M_TOK * D_MODEL / 4 + 255) / 256, 256>>>(attnb, ath, atl, M_TOK * D_MODEL / 4);
    tcgemm_kernel<2><<<gD, 256, GEMM_SMEM>>>(ath, atl, woh, wol, bo, src,
                                             yb, (__nv_bfloat16*)0, (__nv_bfloat16*)0,
                                             M_TOK, D_MODEL, D_MODEL);
    ln_kernel<1><<<M_TOK, 256>>>(yb, ln1g, ln1b, xb, xh, xl);

    // FFN
    dim3 gF(D_FF / BN, M_TOK / BM);      // (32, 32)
    tcgemm_kernel<1><<<gF, 256, GEMM_SMEM>>>(xh, xl, w1h, w1l, b1, (const float*)0,
                                             (float*)0, ffh, ffl,
                                             M_TOK, D_FF, D_MODEL);
    tcgemm_kernel<2><<<gD, 256, GEMM_SMEM>>>(ffh, ffl, w2h, w2l, b2, xb,
                                             yb, (__nv_bfloat16*)0, (__nv_bfloat16*)0,
                                             M_TOK, D_MODEL, D_FF);
    ln_kernel<0><<<M_TOK, 256>>>(yb, ln2g, ln2b, out, (__nv_bfloat16*)0, (__nv_bfloat16*)0);

    // entropy mean
    ent_final_kernel<<<1, 256>>>(entp, out, out_size);
}

// round 5
// speedup vs baseline: 2.8240x; 2.0050x over previous
#include <cuda_runtime.h>
#include <cuda_bf16.h>
#include <math.h>
#include <stdint.h>
#include <string.h>

#define D_MODEL 1024
#define NHEAD 16
#define HEAD_DIM 64
#define B_ 2
#define L_ 2048
#define M_TOK 4096
#define D_FF 4096
#define OUT_MAIN (M_TOK * D_MODEL)

// ---------------- scratch (device globals; no allocations allowed) ----------
__device__ float g_x[M_TOK * D_MODEL];
__device__ float g_y[M_TOK * D_MODEL];
__device__ float g_qbias[M_TOK * NHEAD];
__device__ float g_kbias[M_TOK * NHEAD];
__device__ float g_entpart[1024];
// bf16 split activations
__device__ __nv_bfloat16 g_src_h[M_TOK * D_MODEL];
__device__ __nv_bfloat16 g_src_l[M_TOK * D_MODEL];
__device__ __nv_bfloat16 g_q_h[M_TOK * D_MODEL];
__device__ __nv_bfloat16 g_q_l[M_TOK * D_MODEL];
__device__ __nv_bfloat16 g_k_h[M_TOK * D_MODEL];
__device__ __nv_bfloat16 g_k_l[M_TOK * D_MODEL];
__device__ __nv_bfloat16 g_v_h[M_TOK * D_MODEL];
__device__ __nv_bfloat16 g_v_l[M_TOK * D_MODEL];
__device__ __nv_bfloat16 g_at_h[M_TOK * D_MODEL];
__device__ __nv_bfloat16 g_at_l[M_TOK * D_MODEL];
__device__ __nv_bfloat16 g_x_h[M_TOK * D_MODEL];
__device__ __nv_bfloat16 g_x_l[M_TOK * D_MODEL];
__device__ __nv_bfloat16 g_ff_h[M_TOK * D_FF];
__device__ __nv_bfloat16 g_ff_l[M_TOK * D_FF];
// bf16 split transposed weights [N, K]
__device__ __nv_bfloat16 g_wq_h[D_MODEL * D_MODEL];
__device__ __nv_bfloat16 g_wq_l[D_MODEL * D_MODEL];
__device__ __nv_bfloat16 g_wk_h[D_MODEL * D_MODEL];
__device__ __nv_bfloat16 g_wk_l[D_MODEL * D_MODEL];
__device__ __nv_bfloat16 g_wv_h[D_MODEL * D_MODEL];
__device__ __nv_bfloat16 g_wv_l[D_MODEL * D_MODEL];
__device__ __nv_bfloat16 g_wo_h[D_MODEL * D_MODEL];
__device__ __nv_bfloat16 g_wo_l[D_MODEL * D_MODEL];
__device__ __nv_bfloat16 g_w1_h[D_FF * D_MODEL];
__device__ __nv_bfloat16 g_w1_l[D_FF * D_MODEL];
__device__ __nv_bfloat16 g_w2_h[D_MODEL * D_FF];
__device__ __nv_bfloat16 g_w2_l[D_MODEL * D_FF];

// ======================= PTX helpers (baseline sm_103-legal only) ===========
__device__ __forceinline__ uint32_t smem_u32(const void* p) {
    uint32_t a;
    asm("{ .reg .u64 t; cvta.to.shared.u64 t, %1; cvt.u32.u64 %0, t; }" : "=r"(a) : "l"(p));
    return a;
}
__device__ __forceinline__ void cp16(uint32_t s, const void* g) {
    asm volatile("cp.async.cg.shared.global [%0], [%1], 16;" :: "r"(s), "l"(g));
}
__device__ __forceinline__ void cp4(uint32_t s, const void* g) {
    asm volatile("cp.async.ca.shared.global [%0], [%1], 4;" :: "r"(s), "l"(g));
}
#define CP_COMMIT() asm volatile("cp.async.commit_group;" ::: "memory")

__device__ __forceinline__ void ldsm4(uint32_t* r, uint32_t addr) {
    asm volatile("ldmatrix.sync.aligned.m8n8.x4.shared.b16 {%0,%1,%2,%3}, [%4];"
                 : "=r"(r[0]), "=r"(r[1]), "=r"(r[2]), "=r"(r[3]) : "r"(addr));
}
__device__ __forceinline__ void ldsm4t(uint32_t* r, uint32_t addr) {
    asm volatile("ldmatrix.sync.aligned.m8n8.x4.trans.shared.b16 {%0,%1,%2,%3}, [%4];"
                 : "=r"(r[0]), "=r"(r[1]), "=r"(r[2]), "=r"(r[3]) : "r"(addr));
}
__device__ __forceinline__ void mma16816(float* d, const uint32_t* a, uint32_t b0, uint32_t b1) {
    asm volatile(
        "mma.sync.aligned.m16n8k16.row.col.f32.bf16.bf16.f32 "
        "{%0,%1,%2,%3}, {%4,%5,%6,%7}, {%8,%9}, {%0,%1,%2,%3};"
        : "+f"(d[0]), "+f"(d[1]), "+f"(d[2]), "+f"(d[3])
        : "r"(a[0]), "r"(a[1]), "r"(a[2]), "r"(a[3]), "r"(b0), "r"(b1));
}
__device__ __forceinline__ uint32_t packbf(float a, float b) {
    __nv_bfloat162 t = __floats2bfloat162_rn(a, b);
    uint32_t u; memcpy(&u, &t, 4); return u;
}

// ======================= warp-MMA split-bf16 GEMM ===========================
// MODE 0: fp32 +bias  MODE 1: gelu(+bias)->split  MODE 2: fp32 +bias+res
// MODE 3: +bias -> split
#define BM 128
#define BN 128
#define BKC 32
#define RSTR 80
#define TILE_B (128 * RSTR)
#define STAGE_B (4 * TILE_B)
#define NSTAGE 3
#define GEMM_SMEM (NSTAGE * STAGE_B)

__device__ __forceinline__ void g_load_chunk(
    uint32_t smem, int ci, int m0, int n0, int K, int tid,
    const __nv_bfloat16* __restrict__ Ah, const __nv_bfloat16* __restrict__ Al,
    const __nv_bfloat16* __restrict__ Bh, const __nv_bfloat16* __restrict__ Bl)
{
    uint32_t sb = smem + (uint32_t)(ci % NSTAGE) * STAGE_B;
    size_t kbase = (size_t)ci * BKC;
#pragma unroll
    for (int t = 0; t < 4; t++) {
        const __nv_bfloat16* P = (t == 0) ? Ah : (t == 1) ? Al : (t == 2) ? Bh : Bl;
        int r0 = (t < 2) ? m0 : n0;
        uint32_t tb = sb + (uint32_t)t * TILE_B;
#pragma unroll
        for (int rep = 0; rep < 2; rep++) {
            int seg = tid + (rep << 8);
            int row = seg >> 2;
            int s4  = seg & 3;
            cp16(tb + (uint32_t)row * RSTR + (uint32_t)s4 * 16,
                 P + (size_t)(r0 + row) * K + kbase + s4 * 8);
        }
    }
}

template <int MODE>
__global__ void __launch_bounds__(256, 1) tcgemm_kernel(
    const __nv_bfloat16* __restrict__ Ah, const __nv_bfloat16* __restrict__ Al,
    const __nv_bfloat16* __restrict__ Bh, const __nv_bfloat16* __restrict__ Bl,
    const float* __restrict__ bias, const float* __restrict__ res,
    float* __restrict__ C, __nv_bfloat16* __restrict__ Ch, __nv_bfloat16* __restrict__ Cl,
    int M, int N, int K)
{
    extern __shared__ char dsm[];
    uint32_t smem = smem_u32(dsm);

    int tid = threadIdx.x;
    int wid = tid >> 5;
    int lane = tid & 31;
    int m0 = blockIdx.y * BM;
    int n0 = blockIdx.x * BN;
    int nchunk = K / BKC;

    int wm = wid & 1;
    int wn = wid >> 1;
    int lr = lane & 15;
    uint32_t lk = (uint32_t)((lane >> 4) << 4);

    float acc[4][4][4];
#pragma unroll
    for (int i = 0; i < 4; i++)
#pragma unroll
        for (int j = 0; j < 4; j++)
#pragma unroll
            for (int c = 0; c < 4; c++) acc[i][j][c] = 0.0f;

    g_load_chunk(smem, 0, m0, n0, K, tid, Ah, Al, Bh, Bl);
    CP_COMMIT();
    g_load_chunk(smem, 1, m0, n0, K, tid, Ah, Al, Bh, Bl);
    CP_COMMIT();

    for (int i = 0; i < nchunk; i++) {
        if (i < nchunk - 1)
            asm volatile("cp.async.wait_group 1;" ::: "memory");
        else
            asm volatile("cp.async.wait_group 0;" ::: "memory");
        __syncthreads();

        if (i + 2 < nchunk) {
            g_load_chunk(smem, i + 2, m0, n0, K, tid, Ah, Al, Bh, Bl);
            CP_COMMIT();
        }

        uint32_t sb = smem + (uint32_t)(i % NSTAGE) * STAGE_B;
        uint32_t aBase = sb + (uint32_t)(wm * 64 + lr) * RSTR + lk;
        uint32_t bBase = sb + 2u * TILE_B + (uint32_t)(wn * 32 + lr) * RSTR + lk;

#pragma unroll
        for (int ks = 0; ks < 2; ks++) {
            uint32_t koff = (uint32_t)ks * 32;
            uint32_t ah[4][4], al[4][4], bh[2][4], bl[2][4];
#pragma unroll
            for (int mt = 0; mt < 4; mt++) {
                ldsm4(ah[mt], aBase + (uint32_t)(mt * 16) * RSTR + koff);
                ldsm4(al[mt], aBase + TILE_B + (uint32_t)(mt * 16) * RSTR + koff);
            }
#pragma unroll
            for (int nt = 0; nt < 2; nt++) {
                ldsm4(bh[nt], bBase + (uint32_t)(nt * 16) * RSTR + koff);
                ldsm4(bl[nt], bBase + TILE_B + (uint32_t)(nt * 16) * RSTR + koff);
            }
#pragma unroll
            for (int mt = 0; mt < 4; mt++)
#pragma unroll
                for (int nt = 0; nt < 2; nt++) {
                    mma16816(acc[mt][nt * 2],     ah[mt], bh[nt][0], bh[nt][2]);
                    mma16816(acc[mt][nt * 2 + 1], ah[mt], bh[nt][1], bh[nt][3]);
                    mma16816(acc[mt][nt * 2],     ah[mt], bl[nt][0], bl[nt][2]);
                    mma16816(acc[mt][nt * 2 + 1], ah[mt], bl[nt][1], bl[nt][3]);
                    mma16816(acc[mt][nt * 2],     al[mt], bh[nt][0], bh[nt][2]);
                    mma16816(acc[mt][nt * 2 + 1], al[mt], bh[nt][1], bh[nt][3]);
                }
        }
    }

    int rbase = m0 + wm * 64 + (lane >> 2);
    int cbase = n0 + wn * 32 + (lane & 3) * 2;
#pragma unroll
    for (int mt = 0; mt < 4; mt++) {
#pragma unroll
        for (int n8 = 0; n8 < 4; n8++) {
            int col = cbase + n8 * 8;
            float b0 = bias[col], b1 = bias[col + 1];
#pragma unroll
            for (int half = 0; half < 2; half++) {
                int row = rbase + mt * 16 + half * 8;
                float v0 = acc[mt][n8][half * 2] + b0;
                float v1 = acc[mt][n8][half * 2 + 1] + b1;
                if (MODE == 1) {
                    v0 = 0.5f * v0 * (1.0f + erff(v0 * 0.70710678118654752f));
                    v1 = 0.5f * v1 * (1.0f + erff(v1 * 0.70710678118654752f));
                }
                if (MODE == 2) {
                    const float2 rv = *(const float2*)(res + (size_t)row * N + col);
                    v0 += rv.x; v1 += rv.y;
                }
                if (MODE == 0 || MODE == 2) {
                    float2 o; o.x = v0; o.y = v1;
                    *(float2*)(C + (size_t)row * N + col) = o;
                } else {
                    __nv_bfloat16 h0 = __float2bfloat16(v0);
                    __nv_bfloat16 h1 = __float2bfloat16(v1);
                    __nv_bfloat16 l0 = __float2bfloat16(v0 - __bfloat162float(h0));
                    __nv_bfloat16 l1 = __float2bfloat16(v1 - __bfloat162float(h1));
                    *(__nv_bfloat162*)(Ch + (size_t)row * N + col) = __nv_bfloat162(h0, h1);
                    *(__nv_bfloat162*)(Cl + (size_t)row * N + col) = __nv_bfloat162(l0, l1);
                }
            }
        }
    }
}

// ======================= MMA flash attention ================================
// grid (L/128, NHEAD, B), 256 thr. Warp w owns q rows [w*16, w*16+16).
// Scores: 2 passes (qh*kh + qh*kl). PV: 1 pass bf16.
// Rows are 64 bf16 = 128 bytes; stride 144 = 128 + 16 pad (4-bank row offset
// => 8 ldmatrix rows hit 8 distinct 4-bank groups, conflict-free).
#define ASTR 144
#define ATILE (64 * ASTR)               // 9216 bytes per 64x64 bf16 tile
#define ASTAGE (3 * ATILE + 256)        // Kh, Kl, Vh, kb(64 fp32) = 27904
#define ASMEM (2 * ASTAGE + 64)         // 55872

__device__ __forceinline__ void a_load_chunk(
    uint32_t sm0, int ci, size_t tokb, int h, int tid,
    const __nv_bfloat16* __restrict__ Kh, const __nv_bfloat16* __restrict__ Kl,
    const __nv_bfloat16* __restrict__ Vh, const float* __restrict__ kb)
{
    uint32_t st = sm0 + (uint32_t)(ci & 1) * ASTAGE;
    size_t rowb = tokb + (size_t)ci * 64;
#pragma unroll
    for (int r = 0; r < 6; r++) {
        int idx = tid + (r << 8);          // 0..1535
        int t = idx >> 9;                  // 0..2
        int row = (idx >> 3) & 63;
        int seg = idx & 7;
        const __nv_bfloat16* P = (t == 0) ? Kh : (t == 1) ? Kl : Vh;
        cp16(st + (uint32_t)t * ATILE + (uint32_t)row * ASTR + (uint32_t)seg * 16,
             P + (rowb + row) * D_MODEL + h * HEAD_DIM + seg * 8);
    }
    if (tid < 64)
        cp4(st + 3u * ATILE + (uint32_t)tid * 4, kb + (rowb + tid) * NHEAD + h);
}

__global__ void __launch_bounds__(256, 1) attn_mma_kernel(
    const __nv_bfloat16* __restrict__ Qh, const __nv_bfloat16* __restrict__ Kh,
    const __nv_bfloat16* __restrict__ Kl, const __nv_bfloat16* __restrict__ Vh,
    const float* __restrict__ qb, const float* __restrict__ kb,
    const float* __restrict__ temp,
    __nv_bfloat16* __restrict__ Oh, __nv_bfloat16* __restrict__ Ol,
    float* __restrict__ ent_part)
{
    extern __shared__ char smemv[];
    uint32_t sm0 = smem_u32(smemv);
    float* red = (float*)(smemv + 2 * ASTAGE);

    int tid = threadIdx.x;
    int w = tid >> 5;
    int lane = tid & 31;
    int q0 = blockIdx.x * 128;
    int h = blockIdx.y;
    int b = blockIdx.z;
    size_t tokb = (size_t)b * L_;

    float tmph = fminf(fmaxf(temp[h], 0.1f), 5.0f);
    float inv_t = 1.0f / tmph;
    float sc = 0.125f * inv_t;

    // stage Q-hi tile (128 x 64) into smem, build A-frags
    for (int i = tid; i < 128 * 8; i += 256) {
        int row = i >> 3, seg = i & 7;
        cp16(sm0 + (uint32_t)row * ASTR + (uint32_t)seg * 16,
             Qh + (tokb + q0 + row) * D_MODEL + h * HEAD_DIM + seg * 8);
    }
    CP_COMMIT();
    asm volatile("cp.async.wait_group 0;" ::: "memory");
    __syncthreads();

    uint32_t qfr[4][4];
    {
        uint32_t qbase = sm0 + (uint32_t)(w * 16 + (lane & 15)) * ASTR + (uint32_t)((lane >> 4) << 4);
#pragma unroll
        for (int ks = 0; ks < 4; ks++) ldsm4(qfr[ks], qbase + ks * 32);
    }
    int gid = lane >> 2, tig = lane & 3;
    int r0 = q0 + w * 16 + gid, r1 = r0 + 8;
    float qb0 = qb[(tokb + r0) * NHEAD + h] * inv_t;
    float qb1 = qb[(tokb + r1) * NHEAD + h] * inv_t;
    __syncthreads();   // done reading Q smem

    a_load_chunk(sm0, 0, tokb, h, tid, Kh, Kl, Vh, kb);
    CP_COMMIT();
    a_load_chunk(sm0, 1, tokb, h, tid, Kh, Kl, Vh, kb);
    CP_COMMIT();

    float O[8][4];
#pragma unroll
    for (int f = 0; f < 8; f++)
#pragma unroll
        for (int c = 0; c < 4; c++) O[f][c] = 0.0f;
    float m0 = -1e30f, m1 = -1e30f, z0 = 0.0f, z1 = 0.0f, t0 = 0.0f, t1 = 0.0f;

    const int NCH = L_ / 64;   // 32
    for (int ci = 0; ci < NCH; ci++) {
        if (ci < NCH - 2)
            asm volatile("cp.async.wait_group 1;" ::: "memory");
        else
            asm volatile("cp.async.wait_group 0;" ::: "memory");
        __syncthreads();

        uint32_t st = sm0 + (uint32_t)(ci & 1) * ASTAGE;
        uint32_t kbh = st + (uint32_t)(lane & 15) * ASTR + (uint32_t)((lane >> 4) << 4);
        uint32_t kbl = kbh + ATILE;

        float S[8][4];
#pragma unroll
        for (int f = 0; f < 8; f++)
#pragma unroll
            for (int c = 0; c < 4; c++) S[f][c] = 0.0f;

#pragma unroll
        for (int ks = 0; ks < 4; ks++) {
            uint32_t koff = (uint32_t)ks * 32;
#pragma unroll
            for (int nt = 0; nt < 4; nt++) {
                uint32_t bh[4], bl[4];
                ldsm4(bh, kbh + (uint32_t)(nt * 16) * ASTR + koff);
                mma16816(S[nt * 2],     qfr[ks], bh[0], bh[2]);
                mma16816(S[nt * 2 + 1], qfr[ks], bh[1], bh[3]);
                ldsm4(bl, kbl + (uint32_t)(nt * 16) * ASTR + koff);
                mma16816(S[nt * 2],     qfr[ks], bl[0], bl[2]);
                mma16816(S[nt * 2 + 1], qfr[ks], bl[1], bl[3]);
            }
        }

        const float* kbs = (const float*)(smemv + (size_t)((ci & 1) * ASTAGE + 3 * ATILE));
        float mx0 = -1e30f, mx1 = -1e30f;
#pragma unroll
        for (int f = 0; f < 8; f++) {
            float kc0 = kbs[f * 8 + 2 * tig] * inv_t;
            float kc1 = kbs[f * 8 + 2 * tig + 1] * inv_t;
            S[f][0] = S[f][0] * sc + qb0 + kc0;
            S[f][1] = S[f][1] * sc + qb0 + kc1;
            S[f][2] = S[f][2] * sc + qb1 + kc0;
            S[f][3] = S[f][3] * sc + qb1 + kc1;
            mx0 = fmaxf(mx0, fmaxf(S[f][0], S[f][1]));
            mx1 = fmaxf(mx1, fmaxf(S[f][2], S[f][3]));
        }
        mx0 = fmaxf(mx0, __shfl_xor_sync(0xffffffffu, mx0, 1));
        mx0 = fmaxf(mx0, __shfl_xor_sync(0xffffffffu, mx0, 2));
        mx1 = fmaxf(mx1, __shfl_xor_sync(0xffffffffu, mx1, 1));
        mx1 = fmaxf(mx1, __shfl_xor_sync(0xffffffffu, mx1, 2));

        float nm0 = fmaxf(m0, mx0), nm1 = fmaxf(m1, mx1);
        float sc0 = __expf(m0 - nm0), sc1 = __expf(m1 - nm1);
        float zc0 = 0.0f, zc1 = 0.0f, tc0 = 0.0f, tc1 = 0.0f;
        uint32_t pa[4][4];
#pragma unroll
        for (int j = 0; j < 4; j++) {
#pragma unroll
            for (int g = 0; g < 2; g++) {
                int f = 2 * j + g;
                float p0 = __expf(S[f][0] - nm0);
                float p1 = __expf(S[f][1] - nm0);
                float p2 = __expf(S[f][2] - nm1);
                float p3 = __expf(S[f][3] - nm1);
                zc0 += p0 + p1; zc1 += p2 + p3;
                tc0 += p0 * S[f][0] + p1 * S[f][1];
                tc1 += p2 * S[f][2] + p3 * S[f][3];
                pa[j][g * 2]     = packbf(p0, p1);
                pa[j][g * 2 + 1] = packbf(p2, p3);
            }
        }
        zc0 += __shfl_xor_sync(0xffffffffu, zc0, 1); zc0 += __shfl_xor_sync(0xffffffffu, zc0, 2);
        zc1 += __shfl_xor_sync(0xffffffffu, zc1, 1); zc1 += __shfl_xor_sync(0xffffffffu, zc1, 2);
        tc0 += __shfl_xor_sync(0xffffffffu, tc0, 1); tc0 += __shfl_xor_sync(0xffffffffu, tc0, 2);
        tc1 += __shfl_xor_sync(0xffffffffu, tc1, 1); tc1 += __shfl_xor_sync(0xffffffffu, tc1, 2);
        z0 = z0 * sc0 + zc0; t0 = t0 * sc0 + tc0; m0 = nm0;
        z1 = z1 * sc1 + zc1; t1 = t1 * sc1 + tc1; m1 = nm1;
#pragma unroll
        for (int f = 0; f < 8; f++) {
            O[f][0] *= sc0; O[f][1] *= sc0; O[f][2] *= sc1; O[f][3] *= sc1;
        }

        uint32_t vb = st + 2u * ATILE + (uint32_t)(lane & 15) * ASTR + (uint32_t)((lane >> 4) << 4);
#pragma unroll
        for (int j = 0; j < 4; j++) {
            uint32_t vrow = vb + (uint32_t)(j * 16) * ASTR;
#pragma unroll
            for (int hg = 0; hg < 4; hg++) {
                uint32_t v[4];
                ldsm4t(v, vrow + (uint32_t)hg * 32);
                mma16816(O[hg * 2],     pa[j], v[0], v[1]);
                mma16816(O[hg * 2 + 1], pa[j], v[2], v[3]);
            }
        }
        __syncthreads();
        if (ci + 2 < NCH) {
            a_load_chunk(sm0, ci + 2, tokb, h, tid, Kh, Kl, Vh, kb);
            CP_COMMIT();
        }
    }

    // epilogue: write O as bf16 hi/lo
    float iz0 = 1.0f / z0, iz1 = 1.0f / z1;
    size_t row0b = (tokb + r0) * D_MODEL, row1b = (tokb + r1) * D_MODEL;
#pragma unroll
    for (int f = 0; f < 8; f++) {
        int col = h * HEAD_DIM + f * 8 + 2 * tig;
        float v0 = O[f][0] * iz0, v1 = O[f][1] * iz0;
        float v2 = O[f][2] * iz1, v3 = O[f][3] * iz1;
        __nv_bfloat16 h0 = __float2bfloat16(v0), h1 = __float2bfloat16(v1);
        __nv_bfloat16 h2 = __float2bfloat16(v2), h3 = __float2bfloat16(v3);
        *(__nv_bfloat162*)(Oh + row0b + col) = __nv_bfloat162(h0, h1);
        *(__nv_bfloat162*)(Oh + row1b + col) = __nv_bfloat162(h2, h3);
        __nv_bfloat16 l0 = __float2bfloat16(v0 - __bfloat162float(h0));
        __nv_bfloat16 l1 = __float2bfloat16(v1 - __bfloat162float(h1));
        __nv_bfloat16 l2 = __float2bfloat16(v2 - __bfloat162float(h2));
        __nv_bfloat16 l3 = __float2bfloat16(v3 - __bfloat162float(h3));
        *(__nv_bfloat162*)(Ol + row0b + col) = __nv_bfloat162(l0, l1);
        *(__nv_bfloat162*)(Ol + row1b + col) = __nv_bfloat162(l2, l3);
    }

    // entropy: H = m + log z - t/z per row; quad-duplicated -> *0.25
    float Hv = (m0 + logf(z0) - t0 / z0 + m1 + logf(z1) - t1 / z1) * 0.25f;
#pragma unroll
    for (int off = 16; off; off >>= 1) Hv += __shfl_xor_sync(0xffffffffu, Hv, off);
    if (lane == 0) red[w] = Hv;
    __syncthreads();
    if (tid == 0) {
        float s = 0.0f;
#pragma unroll
        for (int i = 0; i < 8; i++) s += red[i];
        ent_part[((b * NHEAD + h) << 4) + blockIdx.x] = s;
    }
}

// ======================= weight transpose + split ===========================
__global__ void __launch_bounds__(256) convT_kernel(
    const float* __restrict__ W, __nv_bfloat16* __restrict__ hi, __nv_bfloat16* __restrict__ lo,
    int K, int N)
{
    __shared__ float t[32][33];
    int n0 = blockIdx.x * 32, k0 = blockIdx.y * 32;
    int tx = threadIdx.x & 31, ty = threadIdx.x >> 5;
#pragma unroll
    for (int i = 0; i < 32; i += 8)
        t[ty + i][tx] = W[(size_t)(k0 + ty + i) * N + n0 + tx];
    __syncthreads();
#pragma unroll
    for (int i = 0; i < 32; i += 8) {
        float v = t[tx][ty + i];
        __nv_bfloat16 h = __float2bfloat16(v);
        __nv_bfloat16 l = __float2bfloat16(v - __bfloat162float(h));
        size_t o = (size_t)(n0 + ty + i) * K + k0 + tx;
        hi[o] = h; lo[o] = l;
    }
}

__global__ void __launch_bounds__(256) conv_kernel(
    const float* __restrict__ in, __nv_bfloat16* __restrict__ hi, __nv_bfloat16* __restrict__ lo, int n4)
{
    int i = blockIdx.x * 256 + threadIdx.x;
    if (i >= n4) return;
    float4 v = ((const float4*)in)[i];
    __nv_bfloat16 h0 = __float2bfloat16(v.x), h1 = __float2bfloat16(v.y);
    __nv_bfloat16 h2 = __float2bfloat16(v.z), h3 = __float2bfloat16(v.w);
    __nv_bfloat16 l0 = __float2bfloat16(v.x - __bfloat162float(h0));
    __nv_bfloat16 l1 = __float2bfloat16(v.y - __bfloat162float(h1));
    __nv_bfloat16 l2 = __float2bfloat16(v.z - __bfloat162float(h2));
    __nv_bfloat16 l3 = __float2bfloat16(v.w - __bfloat162float(h3));
    ((__nv_bfloat162*)hi)[i * 2]     = __nv_bfloat162(h0, h1);
    ((__nv_bfloat162*)hi)[i * 2 + 1] = __nv_bfloat162(h2, h3);
    ((__nv_bfloat162*)lo)[i * 2]     = __nv_bfloat162(l0, l1);
    ((__nv_bfloat162*)lo)[i * 2 + 1] = __nv_bfloat162(l2, l3);
}

// ---------------- POS bias MLPs ----------------------------------------------
__global__ void __launch_bounds__(128) posbias_kernel(
    const float* __restrict__ pos,
    const float* __restrict__ qw1, const float* __restrict__ qb1,
    const float* __restrict__ qw2, const float* __restrict__ qb2,
    const float* __restrict__ kw1, const float* __restrict__ kb1,
    const float* __restrict__ kw2, const float* __restrict__ kb2,
    float* __restrict__ qbias, float* __restrict__ kbias)
{
    __shared__ float sw1q[32 * 32], sw2q[32 * 16], sb1q[32], sb2q[16];
    __shared__ float sw1k[32 * 32], sw2k[32 * 16], sb1k[32], sb2k[16];
    int tid = threadIdx.x;
    for (int i = tid; i < 1024; i += 128) { sw1q[i] = qw1[i]; sw1k[i] = kw1[i]; }
    for (int i = tid; i < 512;  i += 128) { sw2q[i] = qw2[i]; sw2k[i] = kw2[i]; }
    if (tid < 32) { sb1q[tid] = qb1[tid]; sb1k[tid] = kb1[tid]; }
    if (tid < 16) { sb2q[tid] = qb2[tid]; sb2k[tid] = kb2[tid]; }
    __syncthreads();

    int token = blockIdx.x * 128 + tid;
    float pf[32];
#pragma unroll
    for (int i = 0; i < 32; i++) pf[i] = pos[(size_t)token * 32 + i];

    float hq[32], hk[32];
#pragma unroll
    for (int j = 0; j < 32; j++) { hq[j] = sb1q[j]; hk[j] = sb1k[j]; }
    for (int i = 0; i < 32; i++) {
        float p = pf[i];
#pragma unroll
        for (int j = 0; j < 32; j++) {
            hq[j] += p * sw1q[i * 32 + j];
            hk[j] += p * sw1k[i * 32 + j];
        }
    }
#pragma unroll
    for (int j = 0; j < 32; j++) {
        hq[j] = fmaxf(hq[j], 0.0f);
        hk[j] = fmaxf(hk[j], 0.0f);
    }
#pragma unroll
    for (int h = 0; h < 16; h++) {
        float oq = sb2q[h], ok = sb2k[h];
        for (int j = 0; j < 32; j++) {
            oq += hq[j] * sw2q[j * 16 + h];
            ok += hk[j] * sw2k[j * 16 + h];
        }
        qbias[(size_t)token * NHEAD + h] = oq;
        kbias[(size_t)token * NHEAD + h] = ok;
    }
}

// ---------------- layernorm (optionally emits bf16 hi/lo split) --------------
template <int SPLIT>
__global__ void __launch_bounds__(256) ln_kernel(
    const float* __restrict__ in, const float* __restrict__ gam,
    const float* __restrict__ bet, float* __restrict__ out,
    __nv_bfloat16* __restrict__ oh, __nv_bfloat16* __restrict__ ol)
{
    int row = blockIdx.x, tid = threadIdx.x;
    float4 v = ((const float4*)(in + (size_t)row * D_MODEL))[tid];
    float s = v.x + v.y + v.z + v.w;
    float q = v.x * v.x + v.y * v.y + v.z * v.z + v.w * v.w;
#pragma unroll
    for (int off = 16; off; off >>= 1) {
        s += __shfl_xor_sync(0xffffffffu, s, off);
        q += __shfl_xor_sync(0xffffffffu, q, off);
    }
    __shared__ float ws[8], wq[8], stats[2];
    int lane = tid & 31, w = tid >> 5;
    if (lane == 0) { ws[w] = s; wq[w] = q; }
    __syncthreads();
    if (tid == 0) {
        float S = 0.0f, Qq = 0.0f;
        for (int i = 0; i < 8; i++) { S += ws[i]; Qq += wq[i]; }
        float mu  = S * (1.0f / D_MODEL);
        float var = Qq * (1.0f / D_MODEL) - mu * mu;
        stats[0] = mu;
        stats[1] = rsqrtf(var + 1e-5f);
    }
    __syncthreads();
    float mu = stats[0], rs = stats[1];
    float4 gv = ((const float4*)gam)[tid];
    float4 bv = ((const float4*)bet)[tid];
    float4 ov;
    ov.x = (v.x - mu) * rs * gv.x + bv.x;
    ov.y = (v.y - mu) * rs * gv.y + bv.y;
    ov.z = (v.z - mu) * rs * gv.z + bv.z;
    ov.w = (v.w - mu) * rs * gv.w + bv.w;
    ((float4*)(out + (size_t)row * D_MODEL))[tid] = ov;
    if (SPLIT) {
        __nv_bfloat16 h0 = __float2bfloat16(ov.x), h1 = __float2bfloat16(ov.y);
        __nv_bfloat16 h2 = __float2bfloat16(ov.z), h3 = __float2bfloat16(ov.w);
        __nv_bfloat16 l0 = __float2bfloat16(ov.x - __bfloat162float(h0));
        __nv_bfloat16 l1 = __float2bfloat16(ov.y - __bfloat162float(h1));
        __nv_bfloat16 l2 = __float2bfloat16(ov.z - __bfloat162float(h2));
        __nv_bfloat16 l3 = __float2bfloat16(ov.w - __bfloat162float(h3));
        size_t base = (size_t)row * D_MODEL + tid * 4;
        *(__nv_bfloat162*)(oh + base)     = __nv_bfloat162(h0, h1);
        *(__nv_bfloat162*)(oh + base + 2) = __nv_bfloat162(h2, h3);
        *(__nv_bfloat162*)(ol + base)     = __nv_bfloat162(l0, l1);
        *(__nv_bfloat162*)(ol + base + 2) = __nv_bfloat162(l2, l3);
    }
}

// ---------------- deterministic entropy reduction (512 partials) -------------
__global__ void __launch_bounds__(256) ent_final_kernel(
    const float* __restrict__ part, float* __restrict__ out, int out_size)
{
    __shared__ float sm[256];
    int tid = threadIdx.x;
    sm[tid] = part[tid] + part[tid + 256];
    __syncthreads();
    for (int off = 128; off; off >>= 1) {
        if (tid < off) sm[tid] += sm[tid + off];
        __syncthreads();
    }
    if (tid == 0 && out_size > OUT_MAIN)
        out[OUT_MAIN] = sm[0] * (1.0f / (B_ * NHEAD * L_));
}

// ---------------- launch -----------------------------------------------------
extern "C" void kernel_launch(void* const* d_in, const int* in_sizes, int n_in,
                              void* d_out, int out_size)
{
    const float* src   = (const float*)d_in[0];
    const float* pos   = (const float*)d_in[1];
    const float* Wq    = (const float*)d_in[2];
    const float* bq    = (const float*)d_in[3];
    const float* Wk    = (const float*)d_in[4];
    const float* bk    = (const float*)d_in[5];
    const float* Wv    = (const float*)d_in[6];
    const float* bv    = (const float*)d_in[7];
    const float* Wo    = (const float*)d_in[8];
    const float* bo    = (const float*)d_in[9];
    const float* pq_w1 = (const float*)d_in[10];
    const float* pq_b1 = (const float*)d_in[11];
    const float* pq_w2 = (const float*)d_in[12];
    const float* pq_b2 = (const float*)d_in[13];
    const float* pk_w1 = (const float*)d_in[14];
    const float* pk_b1 = (const float*)d_in[15];
    const float* pk_w2 = (const float*)d_in[16];
    const float* pk_b2 = (const float*)d_in[17];
    const float* temp  = (const float*)d_in[18];
    const float* ln1g  = (const float*)d_in[19];
    const float* ln1b  = (const float*)d_in[20];
    const float* ln2g  = (const float*)d_in[21];
    const float* ln2b  = (const float*)d_in[22];
    const float* W1    = (const float*)d_in[23];
    const float* b1    = (const float*)d_in[24];
    const float* W2    = (const float*)d_in[25];
    const float* b2    = (const float*)d_in[26];
    float* out = (float*)d_out;

    float *xb, *yb, *qbb, *kbb, *entp;
    cudaGetSymbolAddress((void**)&xb, g_x);
    cudaGetSymbolAddress((void**)&yb, g_y);
    cudaGetSymbolAddress((void**)&qbb, g_qbias);
    cudaGetSymbolAddress((void**)&kbb, g_kbias);
    cudaGetSymbolAddress((void**)&entp, g_entpart);

    __nv_bfloat16 *srch, *srcl, *qh, *ql, *kh, *kl, *vh, *vl, *ath, *atl, *xh, *xl, *ffh, *ffl;
    __nv_bfloat16 *wqh, *wql, *wkh, *wkl, *wvh, *wvl, *woh, *wol, *w1h, *w1l, *w2h, *w2l;
    cudaGetSymbolAddress((void**)&srch, g_src_h); cudaGetSymbolAddress((void**)&srcl, g_src_l);
    cudaGetSymbolAddress((void**)&qh, g_q_h);     cudaGetSymbolAddress((void**)&ql, g_q_l);
    cudaGetSymbolAddress((void**)&kh, g_k_h);     cudaGetSymbolAddress((void**)&kl, g_k_l);
    cudaGetSymbolAddress((void**)&vh, g_v_h);     cudaGetSymbolAddress((void**)&vl, g_v_l);
    cudaGetSymbolAddress((void**)&ath, g_at_h);   cudaGetSymbolAddress((void**)&atl, g_at_l);
    cudaGetSymbolAddress((void**)&xh, g_x_h);     cudaGetSymbolAddress((void**)&xl, g_x_l);
    cudaGetSymbolAddress((void**)&ffh, g_ff_h);   cudaGetSymbolAddress((void**)&ffl, g_ff_l);
    cudaGetSymbolAddress((void**)&wqh, g_wq_h);   cudaGetSymbolAddress((void**)&wql, g_wq_l);
    cudaGetSymbolAddress((void**)&wkh, g_wk_h);   cudaGetSymbolAddress((void**)&wkl, g_wk_l);
    cudaGetSymbolAddress((void**)&wvh, g_wv_h);   cudaGetSymbolAddress((void**)&wvl, g_wv_l);
    cudaGetSymbolAddress((void**)&woh, g_wo_h);   cudaGetSymbolAddress((void**)&wol, g_wo_l);
    cudaGetSymbolAddress((void**)&w1h, g_w1_h);   cudaGetSymbolAddress((void**)&w1l, g_w1_l);
    cudaGetSymbolAddress((void**)&w2h, g_w2_h);   cudaGetSymbolAddress((void**)&w2l, g_w2_l);

    cudaFuncSetAttribute(tcgemm_kernel<1>, cudaFuncAttributeMaxDynamicSharedMemorySize, GEMM_SMEM);
    cudaFuncSetAttribute(tcgemm_kernel<2>, cudaFuncAttributeMaxDynamicSharedMemorySize, GEMM_SMEM);
    cudaFuncSetAttribute(tcgemm_kernel<3>, cudaFuncAttributeMaxDynamicSharedMemorySize, GEMM_SMEM);
    cudaFuncSetAttribute(attn_mma_kernel, cudaFuncAttributeMaxDynamicSharedMemorySize, ASMEM);

    // weight transpose + split
    dim3 ct(32, 32);
    convT_kernel<<<ct, 256>>>(Wq, wqh, wql, D_MODEL, D_MODEL);
    convT_kernel<<<ct, 256>>>(Wk, wkh, wkl, D_MODEL, D_MODEL);
    convT_kernel<<<ct, 256>>>(Wv, wvh, wvl, D_MODEL, D_MODEL);
    convT_kernel<<<ct, 256>>>(Wo, woh, wol, D_MODEL, D_MODEL);
    convT_kernel<<<dim3(D_FF / 32, D_MODEL / 32), 256>>>(W1, w1h, w1l, D_MODEL, D_FF);
    convT_kernel<<<dim3(D_MODEL / 32, D_FF / 32), 256>>>(W2, w2h, w2l, D_FF, D_MODEL);

    // src split + pos bias
    conv_kernel<<<(M_TOK * D_MODEL / 4 + 255) / 256, 256>>>(src, srch, srcl, M_TOK * D_MODEL / 4);
    posbias_kernel<<<M_TOK / 128, 128>>>(pos, pq_w1, pq_b1, pq_w2, pq_b2,
                                         pk_w1, pk_b1, pk_w2, pk_b2, qbb, kbb);

    // QKV projections -> bf16 hi/lo
    dim3 gD(D_MODEL / BN, M_TOK / BM);
    tcgemm_kernel<3><<<gD, 256, GEMM_SMEM>>>(srch, srcl, wqh, wql, bq, (const float*)0,
                                             (float*)0, qh, ql, M_TOK, D_MODEL, D_MODEL);
    tcgemm_kernel<3><<<gD, 256, GEMM_SMEM>>>(srch, srcl, wkh, wkl, bk, (const float*)0,
                                             (float*)0, kh, kl, M_TOK, D_MODEL, D_MODEL);
    tcgemm_kernel<3><<<gD, 256, GEMM_SMEM>>>(srch, srcl, wvh, wvl, bv, (const float*)0,
                                             (float*)0, vh, vl, M_TOK, D_MODEL, D_MODEL);

    // MMA flash attention -> at hi/lo + entropy partials
    attn_mma_kernel<<<dim3(L_ / 128, NHEAD, B_), 256, ASMEM>>>(
        qh, kh, kl, vh, qbb, kbb, temp, ath, atl, entp);

    // Wo GEMM + residual -> LN1 (split out)
    tcgemm_kernel<2><<<gD, 256, GEMM_SMEM>>>(ath, atl, woh, wol, bo, src,
                                             yb, (__nv_bfloat16*)0, (__nv_bfloat16*)0,
                                             M_TOK, D_MODEL, D_MODEL);
    ln_kernel<1><<<M_TOK, 256>>>(yb, ln1g, ln1b, xb, xh, xl);

    // FFN
    dim3 gF(D_FF / BN, M_TOK / BM);
    tcgemm_kernel<1><<<gF, 256, GEMM_SMEM>>>(xh, xl, w1h, w1l, b1, (const float*)0,
                                             (float*)0, ffh, ffl, M_TOK, D_FF, D_MODEL);
    tcgemm_kernel<2><<<gD, 256, GEMM_SMEM>>>(ffh, ffl, w2h, w2l, b2, xb,
                                             yb, (__nv_bfloat16*)0, (__nv_bfloat16*)0,
                                             M_TOK, D_MODEL, D_FF);
    ln_kernel<0><<<M_TOK, 256>>>(yb, ln2g, ln2b, out, (__nv_bfloat16*)0, (__nv_bfloat16*)0);

    // entropy mean
    ent_final_kernel<<<1, 256>>>(entp, out, out_size);
}

// round 6
// speedup vs baseline: 3.0139x; 1.0672x over previous
#include <cuda_runtime.h>
#include <cuda_bf16.h>
#include <math.h>
#include <stdint.h>
#include <string.h>

#define D_MODEL 1024
#define NHEAD 16
#define HEAD_DIM 64
#define B_ 2
#define L_ 2048
#define M_TOK 4096
#define D_FF 4096
#define OUT_MAIN (M_TOK * D_MODEL)

// ---------------- scratch (device globals; no allocations allowed) ----------
__device__ float g_x[M_TOK * D_MODEL];
__device__ float g_y[M_TOK * D_MODEL];
__device__ float g_qbias[M_TOK * NHEAD];
__device__ float g_kbias[M_TOK * NHEAD];
__device__ float g_entpart[1024];
__device__ __nv_bfloat16 g_src_h[M_TOK * D_MODEL];
__device__ __nv_bfloat16 g_src_l[M_TOK * D_MODEL];
__device__ __nv_bfloat16 g_q_h[M_TOK * D_MODEL];
__device__ __nv_bfloat16 g_q_l[M_TOK * D_MODEL];
__device__ __nv_bfloat16 g_k_h[M_TOK * D_MODEL];
__device__ __nv_bfloat16 g_k_l[M_TOK * D_MODEL];
__device__ __nv_bfloat16 g_v_h[M_TOK * D_MODEL];
__device__ __nv_bfloat16 g_v_l[M_TOK * D_MODEL];
__device__ __nv_bfloat16 g_at_h[M_TOK * D_MODEL];
__device__ __nv_bfloat16 g_at_l[M_TOK * D_MODEL];
__device__ __nv_bfloat16 g_x_h[M_TOK * D_MODEL];
__device__ __nv_bfloat16 g_x_l[M_TOK * D_MODEL];
__device__ __nv_bfloat16 g_ff_h[M_TOK * D_FF];
__device__ __nv_bfloat16 g_ff_l[M_TOK * D_FF];
__device__ __nv_bfloat16 g_wq_h[D_MODEL * D_MODEL];
__device__ __nv_bfloat16 g_wq_l[D_MODEL * D_MODEL];
__device__ __nv_bfloat16 g_wk_h[D_MODEL * D_MODEL];
__device__ __nv_bfloat16 g_wk_l[D_MODEL * D_MODEL];
__device__ __nv_bfloat16 g_wv_h[D_MODEL * D_MODEL];
__device__ __nv_bfloat16 g_wv_l[D_MODEL * D_MODEL];
__device__ __nv_bfloat16 g_wo_h[D_MODEL * D_MODEL];
__device__ __nv_bfloat16 g_wo_l[D_MODEL * D_MODEL];
__device__ __nv_bfloat16 g_w1_h[D_FF * D_MODEL];
__device__ __nv_bfloat16 g_w1_l[D_FF * D_MODEL];
__device__ __nv_bfloat16 g_w2_h[D_MODEL * D_FF];
__device__ __nv_bfloat16 g_w2_l[D_MODEL * D_FF];

// ======================= PTX helpers (baseline sm_103-legal only) ===========
__device__ __forceinline__ uint32_t smem_u32(const void* p) {
    uint32_t a;
    asm("{ .reg .u64 t; cvta.to.shared.u64 t, %1; cvt.u32.u64 %0, t; }" : "=r"(a) : "l"(p));
    return a;
}
__device__ __forceinline__ void cp16(uint32_t s, const void* g) {
    asm volatile("cp.async.cg.shared.global [%0], [%1], 16;" :: "r"(s), "l"(g));
}
__device__ __forceinline__ void cp4(uint32_t s, const void* g) {
    asm volatile("cp.async.ca.shared.global [%0], [%1], 4;" :: "r"(s), "l"(g));
}
#define CP_COMMIT() asm volatile("cp.async.commit_group;" ::: "memory")

__device__ __forceinline__ void ldsm4(uint32_t* r, uint32_t addr) {
    asm volatile("ldmatrix.sync.aligned.m8n8.x4.shared.b16 {%0,%1,%2,%3}, [%4];"
                 : "=r"(r[0]), "=r"(r[1]), "=r"(r[2]), "=r"(r[3]) : "r"(addr));
}
__device__ __forceinline__ void ldsm4t(uint32_t* r, uint32_t addr) {
    asm volatile("ldmatrix.sync.aligned.m8n8.x4.trans.shared.b16 {%0,%1,%2,%3}, [%4];"
                 : "=r"(r[0]), "=r"(r[1]), "=r"(r[2]), "=r"(r[3]) : "r"(addr));
}
__device__ __forceinline__ void mma16816(float* d, const uint32_t* a, uint32_t b0, uint32_t b1) {
    asm volatile(
        "mma.sync.aligned.m16n8k16.row.col.f32.bf16.bf16.f32 "
        "{%0,%1,%2,%3}, {%4,%5,%6,%7}, {%8,%9}, {%0,%1,%2,%3};"
        : "+f"(d[0]), "+f"(d[1]), "+f"(d[2]), "+f"(d[3])
        : "r"(a[0]), "r"(a[1]), "r"(a[2]), "r"(a[3]), "r"(b0), "r"(b1));
}
__device__ __forceinline__ uint32_t packbf(float a, float b) {
    __nv_bfloat162 t = __floats2bfloat162_rn(a, b);
    uint32_t u; memcpy(&u, &t, 4); return u;
}

// ======================= warp-MMA split-bf16 GEMM ===========================
// MODE 0: fp32 +bias  MODE 1: gelu(+bias)->split  MODE 2: fp32 +bias+res
// MODE 3: +bias -> split
// Double-buffered (NSTAGE=2) so 2 CTAs co-reside per SM (4 warps/SMSP).
#define BM 128
#define BN 128
#define BKC 32
#define RSTR 80
#define TILE_B (128 * RSTR)
#define STAGE_B (4 * TILE_B)            // 40960
#define NSTAGE 2
#define GEMM_SMEM (NSTAGE * STAGE_B)    // 81920 -> 2 CTAs/SM

__device__ __forceinline__ void g_load_chunk(
    uint32_t smem, int ci, int m0, int n0, int K, int tid,
    const __nv_bfloat16* __restrict__ Ah, const __nv_bfloat16* __restrict__ Al,
    const __nv_bfloat16* __restrict__ Bh, const __nv_bfloat16* __restrict__ Bl)
{
    uint32_t sb = smem + (uint32_t)(ci & 1) * STAGE_B;
    size_t kbase = (size_t)ci * BKC;
#pragma unroll
    for (int t = 0; t < 4; t++) {
        const __nv_bfloat16* P = (t == 0) ? Ah : (t == 1) ? Al : (t == 2) ? Bh : Bl;
        int r0 = (t < 2) ? m0 : n0;
        uint32_t tb = sb + (uint32_t)t * TILE_B;
#pragma unroll
        for (int rep = 0; rep < 2; rep++) {
            int seg = tid + (rep << 8);
            int row = seg >> 2;
            int s4  = seg & 3;
            cp16(tb + (uint32_t)row * RSTR + (uint32_t)s4 * 16,
                 P + (size_t)(r0 + row) * K + kbase + s4 * 8);
        }
    }
}

template <int MODE>
__global__ void __launch_bounds__(256, 2) tcgemm_kernel(
    const __nv_bfloat16* __restrict__ Ah, const __nv_bfloat16* __restrict__ Al,
    const __nv_bfloat16* __restrict__ Bh, const __nv_bfloat16* __restrict__ Bl,
    const float* __restrict__ bias, const float* __restrict__ res,
    float* __restrict__ C, __nv_bfloat16* __restrict__ Ch, __nv_bfloat16* __restrict__ Cl,
    int M, int N, int K)
{
    extern __shared__ char dsm[];
    uint32_t smem = smem_u32(dsm);

    int tid = threadIdx.x;
    int wid = tid >> 5;
    int lane = tid & 31;
    int m0 = blockIdx.y * BM;
    int n0 = blockIdx.x * BN;
    int nchunk = K / BKC;

    int wm = wid & 1;
    int wn = wid >> 1;
    int lr = lane & 15;
    uint32_t lk = (uint32_t)((lane >> 4) << 4);

    float acc[4][4][4];
#pragma unroll
    for (int i = 0; i < 4; i++)
#pragma unroll
        for (int j = 0; j < 4; j++)
#pragma unroll
            for (int c = 0; c < 4; c++) acc[i][j][c] = 0.0f;

    g_load_chunk(smem, 0, m0, n0, K, tid, Ah, Al, Bh, Bl);
    CP_COMMIT();

    for (int i = 0; i < nchunk; i++) {
        if (i + 1 < nchunk) {
            g_load_chunk(smem, i + 1, m0, n0, K, tid, Ah, Al, Bh, Bl);
            CP_COMMIT();
            asm volatile("cp.async.wait_group 1;" ::: "memory");
        } else {
            asm volatile("cp.async.wait_group 0;" ::: "memory");
        }
        __syncthreads();

        uint32_t sb = smem + (uint32_t)(i & 1) * STAGE_B;
        uint32_t aBase = sb + (uint32_t)(wm * 64 + lr) * RSTR + lk;
        uint32_t bBase = sb + 2u * TILE_B + (uint32_t)(wn * 32 + lr) * RSTR + lk;

#pragma unroll
        for (int ks = 0; ks < 2; ks++) {
            uint32_t koff = (uint32_t)ks * 32;
            uint32_t ah[4][4], al[4][4];
#pragma unroll
            for (int mt = 0; mt < 4; mt++) {
                ldsm4(ah[mt], aBase + (uint32_t)(mt * 16) * RSTR + koff);
                ldsm4(al[mt], aBase + TILE_B + (uint32_t)(mt * 16) * RSTR + koff);
            }
#pragma unroll
            for (int nt = 0; nt < 2; nt++) {
                uint32_t bb[4];
                ldsm4(bb, bBase + (uint32_t)(nt * 16) * RSTR + koff);   // B-hi
#pragma unroll
                for (int mt = 0; mt < 4; mt++) {
                    mma16816(acc[mt][nt * 2],     ah[mt], bb[0], bb[2]);
                    mma16816(acc[mt][nt * 2 + 1], ah[mt], bb[1], bb[3]);
                }
#pragma unroll
                for (int mt = 0; mt < 4; mt++) {
                    mma16816(acc[mt][nt * 2],     al[mt], bb[0], bb[2]);
                    mma16816(acc[mt][nt * 2 + 1], al[mt], bb[1], bb[3]);
                }
                ldsm4(bb, bBase + TILE_B + (uint32_t)(nt * 16) * RSTR + koff);  // B-lo
#pragma unroll
                for (int mt = 0; mt < 4; mt++) {
                    mma16816(acc[mt][nt * 2],     ah[mt], bb[0], bb[2]);
                    mma16816(acc[mt][nt * 2 + 1], ah[mt], bb[1], bb[3]);
                }
            }
        }
        __syncthreads();   // protect stage (i+1)&1 before next prefetch overwrites
    }

    int rbase = m0 + wm * 64 + (lane >> 2);
    int cbase = n0 + wn * 32 + (lane & 3) * 2;
#pragma unroll
    for (int mt = 0; mt < 4; mt++) {
#pragma unroll
        for (int n8 = 0; n8 < 4; n8++) {
            int col = cbase + n8 * 8;
            float b0 = bias[col], b1 = bias[col + 1];
#pragma unroll
            for (int half = 0; half < 2; half++) {
                int row = rbase + mt * 16 + half * 8;
                float v0 = acc[mt][n8][half * 2] + b0;
                float v1 = acc[mt][n8][half * 2 + 1] + b1;
                if (MODE == 1) {
                    v0 = 0.5f * v0 * (1.0f + erff(v0 * 0.70710678118654752f));
                    v1 = 0.5f * v1 * (1.0f + erff(v1 * 0.70710678118654752f));
                }
                if (MODE == 2) {
                    const float2 rv = *(const float2*)(res + (size_t)row * N + col);
                    v0 += rv.x; v1 += rv.y;
                }
                if (MODE == 0 || MODE == 2) {
                    float2 o; o.x = v0; o.y = v1;
                    *(float2*)(C + (size_t)row * N + col) = o;
                } else {
                    __nv_bfloat16 h0 = __float2bfloat16(v0);
                    __nv_bfloat16 h1 = __float2bfloat16(v1);
                    __nv_bfloat16 l0 = __float2bfloat16(v0 - __bfloat162float(h0));
                    __nv_bfloat16 l1 = __float2bfloat16(v1 - __bfloat162float(h1));
                    *(__nv_bfloat162*)(Ch + (size_t)row * N + col) = __nv_bfloat162(h0, h1);
                    *(__nv_bfloat162*)(Cl + (size_t)row * N + col) = __nv_bfloat162(l0, l1);
                }
            }
        }
    }
}

// ======================= MMA flash attention (unchanged) ====================
#define ASTR 144
#define ATILE (64 * ASTR)
#define ASTAGE (3 * ATILE + 256)
#define ASMEM (2 * ASTAGE + 64)

__device__ __forceinline__ void a_load_chunk(
    uint32_t sm0, int ci, size_t tokb, int h, int tid,
    const __nv_bfloat16* __restrict__ Kh, const __nv_bfloat16* __restrict__ Kl,
    const __nv_bfloat16* __restrict__ Vh, const float* __restrict__ kb)
{
    uint32_t st = sm0 + (uint32_t)(ci & 1) * ASTAGE;
    size_t rowb = tokb + (size_t)ci * 64;
#pragma unroll
    for (int r = 0; r < 6; r++) {
        int idx = tid + (r << 8);
        int t = idx >> 9;
        int row = (idx >> 3) & 63;
        int seg = idx & 7;
        const __nv_bfloat16* P = (t == 0) ? Kh : (t == 1) ? Kl : Vh;
        cp16(st + (uint32_t)t * ATILE + (uint32_t)row * ASTR + (uint32_t)seg * 16,
             P + (rowb + row) * D_MODEL + h * HEAD_DIM + seg * 8);
    }
    if (tid < 64)
        cp4(st + 3u * ATILE + (uint32_t)tid * 4, kb + (rowb + tid) * NHEAD + h);
}

__global__ void __launch_bounds__(256, 1) attn_mma_kernel(
    const __nv_bfloat16* __restrict__ Qh, const __nv_bfloat16* __restrict__ Kh,
    const __nv_bfloat16* __restrict__ Kl, const __nv_bfloat16* __restrict__ Vh,
    const float* __restrict__ qb, const float* __restrict__ kb,
    const float* __restrict__ temp,
    __nv_bfloat16* __restrict__ Oh, __nv_bfloat16* __restrict__ Ol,
    float* __restrict__ ent_part)
{
    extern __shared__ char smemv[];
    uint32_t sm0 = smem_u32(smemv);
    float* red = (float*)(smemv + 2 * ASTAGE);

    int tid = threadIdx.x;
    int w = tid >> 5;
    int lane = tid & 31;
    int q0 = blockIdx.x * 128;
    int h = blockIdx.y;
    int b = blockIdx.z;
    size_t tokb = (size_t)b * L_;

    float tmph = fminf(fmaxf(temp[h], 0.1f), 5.0f);
    float inv_t = 1.0f / tmph;
    float sc = 0.125f * inv_t;

    for (int i = tid; i < 128 * 8; i += 256) {
        int row = i >> 3, seg = i & 7;
        cp16(sm0 + (uint32_t)row * ASTR + (uint32_t)seg * 16,
             Qh + (tokb + q0 + row) * D_MODEL + h * HEAD_DIM + seg * 8);
    }
    CP_COMMIT();
    asm volatile("cp.async.wait_group 0;" ::: "memory");
    __syncthreads();

    uint32_t qfr[4][4];
    {
        uint32_t qbase = sm0 + (uint32_t)(w * 16 + (lane & 15)) * ASTR + (uint32_t)((lane >> 4) << 4);
#pragma unroll
        for (int ks = 0; ks < 4; ks++) ldsm4(qfr[ks], qbase + ks * 32);
    }
    int gid = lane >> 2, tig = lane & 3;
    int r0 = q0 + w * 16 + gid, r1 = r0 + 8;
    float qb0 = qb[(tokb + r0) * NHEAD + h] * inv_t;
    float qb1 = qb[(tokb + r1) * NHEAD + h] * inv_t;
    __syncthreads();

    a_load_chunk(sm0, 0, tokb, h, tid, Kh, Kl, Vh, kb);
    CP_COMMIT();
    a_load_chunk(sm0, 1, tokb, h, tid, Kh, Kl, Vh, kb);
    CP_COMMIT();

    float O[8][4];
#pragma unroll
    for (int f = 0; f < 8; f++)
#pragma unroll
        for (int c = 0; c < 4; c++) O[f][c] = 0.0f;
    float m0 = -1e30f, m1 = -1e30f, z0 = 0.0f, z1 = 0.0f, t0 = 0.0f, t1 = 0.0f;

    const int NCH = L_ / 64;
    for (int ci = 0; ci < NCH; ci++) {
        if (ci < NCH - 2)
            asm volatile("cp.async.wait_group 1;" ::: "memory");
        else
            asm volatile("cp.async.wait_group 0;" ::: "memory");
        __syncthreads();

        uint32_t st = sm0 + (uint32_t)(ci & 1) * ASTAGE;
        uint32_t kbh = st + (uint32_t)(lane & 15) * ASTR + (uint32_t)((lane >> 4) << 4);
        uint32_t kbl = kbh + ATILE;

        float S[8][4];
#pragma unroll
        for (int f = 0; f < 8; f++)
#pragma unroll
            for (int c = 0; c < 4; c++) S[f][c] = 0.0f;

#pragma unroll
        for (int ks = 0; ks < 4; ks++) {
            uint32_t koff = (uint32_t)ks * 32;
#pragma unroll
            for (int nt = 0; nt < 4; nt++) {
                uint32_t bh[4], bl[4];
                ldsm4(bh, kbh + (uint32_t)(nt * 16) * ASTR + koff);
                mma16816(S[nt * 2],     qfr[ks], bh[0], bh[2]);
                mma16816(S[nt * 2 + 1], qfr[ks], bh[1], bh[3]);
                ldsm4(bl, kbl + (uint32_t)(nt * 16) * ASTR + koff);
                mma16816(S[nt * 2],     qfr[ks], bl[0], bl[2]);
                mma16816(S[nt * 2 + 1], qfr[ks], bl[1], bl[3]);
            }
        }

        const float* kbs = (const float*)(smemv + (size_t)((ci & 1) * ASTAGE + 3 * ATILE));
        float mx0 = -1e30f, mx1 = -1e30f;
#pragma unroll
        for (int f = 0; f < 8; f++) {
            float kc0 = kbs[f * 8 + 2 * tig] * inv_t;
            float kc1 = kbs[f * 8 + 2 * tig + 1] * inv_t;
            S[f][0] = S[f][0] * sc + qb0 + kc0;
            S[f][1] = S[f][1] * sc + qb0 + kc1;
            S[f][2] = S[f][2] * sc + qb1 + kc0;
            S[f][3] = S[f][3] * sc + qb1 + kc1;
            mx0 = fmaxf(mx0, fmaxf(S[f][0], S[f][1]));
            mx1 = fmaxf(mx1, fmaxf(S[f][2], S[f][3]));
        }
        mx0 = fmaxf(mx0, __shfl_xor_sync(0xffffffffu, mx0, 1));
        mx0 = fmaxf(mx0, __shfl_xor_sync(0xffffffffu, mx0, 2));
        mx1 = fmaxf(mx1, __shfl_xor_sync(0xffffffffu, mx1, 1));
        mx1 = fmaxf(mx1, __shfl_xor_sync(0xffffffffu, mx1, 2));

        float nm0 = fmaxf(m0, mx0), nm1 = fmaxf(m1, mx1);
        float sc0 = __expf(m0 - nm0), sc1 = __expf(m1 - nm1);
        float zc0 = 0.0f, zc1 = 0.0f, tc0 = 0.0f, tc1 = 0.0f;
        uint32_t pa[4][4];
#pragma unroll
        for (int j = 0; j < 4; j++) {
#pragma unroll
            for (int g = 0; g < 2; g++) {
                int f = 2 * j + g;
                float p0 = __expf(S[f][0] - nm0);
                float p1 = __expf(S[f][1] - nm0);
                float p2 = __expf(S[f][2] - nm1);
                float p3 = __expf(S[f][3] - nm1);
                zc0 += p0 + p1; zc1 += p2 + p3;
                tc0 += p0 * S[f][0] + p1 * S[f][1];
                tc1 += p2 * S[f][2] + p3 * S[f][3];
                pa[j][g * 2]     = packbf(p0, p1);
                pa[j][g * 2 + 1] = packbf(p2, p3);
            }
        }
        zc0 += __shfl_xor_sync(0xffffffffu, zc0, 1); zc0 += __shfl_xor_sync(0xffffffffu, zc0, 2);
        zc1 += __shfl_xor_sync(0xffffffffu, zc1, 1); zc1 += __shfl_xor_sync(0xffffffffu, zc1, 2);
        tc0 += __shfl_xor_sync(0xffffffffu, tc0, 1); tc0 += __shfl_xor_sync(0xffffffffu, tc0, 2);
        tc1 += __shfl_xor_sync(0xffffffffu, tc1, 1); tc1 += __shfl_xor_sync(0xffffffffu, tc1, 2);
        z0 = z0 * sc0 + zc0; t0 = t0 * sc0 + tc0; m0 = nm0;
        z1 = z1 * sc1 + zc1; t1 = t1 * sc1 + tc1; m1 = nm1;
#pragma unroll
        for (int f = 0; f < 8; f++) {
            O[f][0] *= sc0; O[f][1] *= sc0; O[f][2] *= sc1; O[f][3] *= sc1;
        }

        uint32_t vb = st + 2u * ATILE + (uint32_t)(lane & 15) * ASTR + (uint32_t)((lane >> 4) << 4);
#pragma unroll
        for (int j = 0; j < 4; j++) {
            uint32_t vrow = vb + (uint32_t)(j * 16) * ASTR;
#pragma unroll
            for (int hg = 0; hg < 4; hg++) {
                uint32_t v[4];
                ldsm4t(v, vrow + (uint32_t)hg * 32);
                mma16816(O[hg * 2],     pa[j], v[0], v[1]);
                mma16816(O[hg * 2 + 1], pa[j], v[2], v[3]);
            }
        }
        __syncthreads();
        if (ci + 2 < NCH) {
            a_load_chunk(sm0, ci + 2, tokb, h, tid, Kh, Kl, Vh, kb);
            CP_COMMIT();
        }
    }

    float iz0 = 1.0f / z0, iz1 = 1.0f / z1;
    size_t row0b = (tokb + r0) * D_MODEL, row1b = (tokb + r1) * D_MODEL;
#pragma unroll
    for (int f = 0; f < 8; f++) {
        int col = h * HEAD_DIM + f * 8 + 2 * tig;
        float v0 = O[f][0] * iz0, v1 = O[f][1] * iz0;
        float v2 = O[f][2] * iz1, v3 = O[f][3] * iz1;
        __nv_bfloat16 h0 = __float2bfloat16(v0), h1 = __float2bfloat16(v1);
        __nv_bfloat16 h2 = __float2bfloat16(v2), h3 = __float2bfloat16(v3);
        *(__nv_bfloat162*)(Oh + row0b + col) = __nv_bfloat162(h0, h1);
        *(__nv_bfloat162*)(Oh + row1b + col) = __nv_bfloat162(h2, h3);
        __nv_bfloat16 l0 = __float2bfloat16(v0 - __bfloat162float(h0));
        __nv_bfloat16 l1 = __float2bfloat16(v1 - __bfloat162float(h1));
        __nv_bfloat16 l2 = __float2bfloat16(v2 - __bfloat162float(h2));
        __nv_bfloat16 l3 = __float2bfloat16(v3 - __bfloat162float(h3));
        *(__nv_bfloat162*)(Ol + row0b + col) = __nv_bfloat162(l0, l1);
        *(__nv_bfloat162*)(Ol + row1b + col) = __nv_bfloat162(l2, l3);
    }

    float Hv = (m0 + logf(z0) - t0 / z0 + m1 + logf(z1) - t1 / z1) * 0.25f;
#pragma unroll
    for (int off = 16; off; off >>= 1) Hv += __shfl_xor_sync(0xffffffffu, Hv, off);
    if (lane == 0) red[w] = Hv;
    __syncthreads();
    if (tid == 0) {
        float s = 0.0f;
#pragma unroll
        for (int i = 0; i < 8; i++) s += red[i];
        ent_part[((b * NHEAD + h) << 4) + blockIdx.x] = s;
    }
}

// ======================= weight transpose + split ===========================
__global__ void __launch_bounds__(256) convT_kernel(
    const float* __restrict__ W, __nv_bfloat16* __restrict__ hi, __nv_bfloat16* __restrict__ lo,
    int K, int N)
{
    __shared__ float t[32][33];
    int n0 = blockIdx.x * 32, k0 = blockIdx.y * 32;
    int tx = threadIdx.x & 31, ty = threadIdx.x >> 5;
#pragma unroll
    for (int i = 0; i < 32; i += 8)
        t[ty + i][tx] = W[(size_t)(k0 + ty + i) * N + n0 + tx];
    __syncthreads();
#pragma unroll
    for (int i = 0; i < 32; i += 8) {
        float v = t[tx][ty + i];
        __nv_bfloat16 h = __float2bfloat16(v);
        __nv_bfloat16 l = __float2bfloat16(v - __bfloat162float(h));
        size_t o = (size_t)(n0 + ty + i) * K + k0 + tx;
        hi[o] = h; lo[o] = l;
    }
}

__global__ void __launch_bounds__(256) conv_kernel(
    const float* __restrict__ in, __nv_bfloat16* __restrict__ hi, __nv_bfloat16* __restrict__ lo, int n4)
{
    int i = blockIdx.x * 256 + threadIdx.x;
    if (i >= n4) return;
    float4 v = ((const float4*)in)[i];
    __nv_bfloat16 h0 = __float2bfloat16(v.x), h1 = __float2bfloat16(v.y);
    __nv_bfloat16 h2 = __float2bfloat16(v.z), h3 = __float2bfloat16(v.w);
    __nv_bfloat16 l0 = __float2bfloat16(v.x - __bfloat162float(h0));
    __nv_bfloat16 l1 = __float2bfloat16(v.y - __bfloat162float(h1));
    __nv_bfloat16 l2 = __float2bfloat16(v.z - __bfloat162float(h2));
    __nv_bfloat16 l3 = __float2bfloat16(v.w - __bfloat162float(h3));
    ((__nv_bfloat162*)hi)[i * 2]     = __nv_bfloat162(h0, h1);
    ((__nv_bfloat162*)hi)[i * 2 + 1] = __nv_bfloat162(h2, h3);
    ((__nv_bfloat162*)lo)[i * 2]     = __nv_bfloat162(l0, l1);
    ((__nv_bfloat162*)lo)[i * 2 + 1] = __nv_bfloat162(l2, l3);
}

// ---------------- POS bias MLPs ----------------------------------------------
__global__ void __launch_bounds__(128) posbias_kernel(
    const float* __restrict__ pos,
    const float* __restrict__ qw1, const float* __restrict__ qb1,
    const float* __restrict__ qw2, const float* __restrict__ qb2,
    const float* __restrict__ kw1, const float* __restrict__ kb1,
    const float* __restrict__ kw2, const float* __restrict__ kb2,
    float* __restrict__ qbias, float* __restrict__ kbias)
{
    __shared__ float sw1q[32 * 32], sw2q[32 * 16], sb1q[32], sb2q[16];
    __shared__ float sw1k[32 * 32], sw2k[32 * 16], sb1k[32], sb2k[16];
    int tid = threadIdx.x;
    for (int i = tid; i < 1024; i += 128) { sw1q[i] = qw1[i]; sw1k[i] = kw1[i]; }
    for (int i = tid; i < 512;  i += 128) { sw2q[i] = qw2[i]; sw2k[i] = kw2[i]; }
    if (tid < 32) { sb1q[tid] = qb1[tid]; sb1k[tid] = kb1[tid]; }
    if (tid < 16) { sb2q[tid] = qb2[tid]; sb2k[tid] = kb2[tid]; }
    __syncthreads();

    int token = blockIdx.x * 128 + tid;
    float pf[32];
#pragma unroll
    for (int i = 0; i < 32; i++) pf[i] = pos[(size_t)token * 32 + i];

    float hq[32], hk[32];
#pragma unroll
    for (int j = 0; j < 32; j++) { hq[j] = sb1q[j]; hk[j] = sb1k[j]; }
    for (int i = 0; i < 32; i++) {
        float p = pf[i];
#pragma unroll
        for (int j = 0; j < 32; j++) {
            hq[j] += p * sw1q[i * 32 + j];
            hk[j] += p * sw1k[i * 32 + j];
        }
    }
#pragma unroll
    for (int j = 0; j < 32; j++) {
        hq[j] = fmaxf(hq[j], 0.0f);
        hk[j] = fmaxf(hk[j], 0.0f);
    }
#pragma unroll
    for (int h = 0; h < 16; h++) {
        float oq = sb2q[h], ok = sb2k[h];
        for (int j = 0; j < 32; j++) {
            oq += hq[j] * sw2q[j * 16 + h];
            ok += hk[j] * sw2k[j * 16 + h];
        }
        qbias[(size_t)token * NHEAD + h] = oq;
        kbias[(size_t)token * NHEAD + h] = ok;
    }
}

// ---------------- layernorm (optionally emits bf16 hi/lo split) --------------
template <int SPLIT>
__global__ void __launch_bounds__(256) ln_kernel(
    const float* __restrict__ in, const float* __restrict__ gam,
    const float* __restrict__ bet, float* __restrict__ out,
    __nv_bfloat16* __restrict__ oh, __nv_bfloat16* __restrict__ ol)
{
    int row = blockIdx.x, tid = threadIdx.x;
    float4 v = ((const float4*)(in + (size_t)row * D_MODEL))[tid];
    float s = v.x + v.y + v.z + v.w;
    float q = v.x * v.x + v.y * v.y + v.z * v.z + v.w * v.w;
#pragma unroll
    for (int off = 16; off; off >>= 1) {
        s += __shfl_xor_sync(0xffffffffu, s, off);
        q += __shfl_xor_sync(0xffffffffu, q, off);
    }
    __shared__ float ws[8], wq[8], stats[2];
    int lane = tid & 31, w = tid >> 5;
    if (lane == 0) { ws[w] = s; wq[w] = q; }
    __syncthreads();
    if (tid == 0) {
        float S = 0.0f, Qq = 0.0f;
        for (int i = 0; i < 8; i++) { S += ws[i]; Qq += wq[i]; }
        float mu  = S * (1.0f / D_MODEL);
        float var = Qq * (1.0f / D_MODEL) - mu * mu;
        stats[0] = mu;
        stats[1] = rsqrtf(var + 1e-5f);
    }
    __syncthreads();
    float mu = stats[0], rs = stats[1];
    float4 gv = ((const float4*)gam)[tid];
    float4 bv = ((const float4*)bet)[tid];
    float4 ov;
    ov.x = (v.x - mu) * rs * gv.x + bv.x;
    ov.y = (v.y - mu) * rs * gv.y + bv.y;
    ov.z = (v.z - mu) * rs * gv.z + bv.z;
    ov.w = (v.w - mu) * rs * gv.w + bv.w;
    ((float4*)(out + (size_t)row * D_MODEL))[tid] = ov;
    if (SPLIT) {
        __nv_bfloat16 h0 = __float2bfloat16(ov.x), h1 = __float2bfloat16(ov.y);
        __nv_bfloat16 h2 = __float2bfloat16(ov.z), h3 = __float2bfloat16(ov.w);
        __nv_bfloat16 l0 = __float2bfloat16(ov.x - __bfloat162float(h0));
        __nv_bfloat16 l1 = __float2bfloat16(ov.y - __bfloat162float(h1));
        __nv_bfloat16 l2 = __float2bfloat16(ov.z - __bfloat162float(h2));
        __nv_bfloat16 l3 = __float2bfloat16(ov.w - __bfloat162float(h3));
        size_t base = (size_t)row * D_MODEL + tid * 4;
        *(__nv_bfloat162*)(oh + base)     = __nv_bfloat162(h0, h1);
        *(__nv_bfloat162*)(oh + base + 2) = __nv_bfloat162(h2, h3);
        *(__nv_bfloat162*)(ol + base)     = __nv_bfloat162(l0, l1);
        *(__nv_bfloat162*)(ol + base + 2) = __nv_bfloat162(l2, l3);
    }
}

// ---------------- deterministic entropy reduction ----------------------------
__global__ void __launch_bounds__(256) ent_final_kernel(
    const float* __restrict__ part, float* __restrict__ out, int out_size)
{
    __shared__ float sm[256];
    int tid = threadIdx.x;
    sm[tid] = part[tid] + part[tid + 256];
    __syncthreads();
    for (int off = 128; off; off >>= 1) {
        if (tid < off) sm[tid] += sm[tid + off];
        __syncthreads();
    }
    if (tid == 0 && out_size > OUT_MAIN)
        out[OUT_MAIN] = sm[0] * (1.0f / (B_ * NHEAD * L_));
}

// ---------------- launch -----------------------------------------------------
extern "C" void kernel_launch(void* const* d_in, const int* in_sizes, int n_in,
                              void* d_out, int out_size)
{
    const float* src   = (const float*)d_in[0];
    const float* pos   = (const float*)d_in[1];
    const float* Wq    = (const float*)d_in[2];
    const float* bq    = (const float*)d_in[3];
    const float* Wk    = (const float*)d_in[4];
    const float* bk    = (const float*)d_in[5];
    const float* Wv    = (const float*)d_in[6];
    const float* bv    = (const float*)d_in[7];
    const float* Wo    = (const float*)d_in[8];
    const float* bo    = (const float*)d_in[9];
    const float* pq_w1 = (const float*)d_in[10];
    const float* pq_b1 = (const float*)d_in[11];
    const float* pq_w2 = (const float*)d_in[12];
    const float* pq_b2 = (const float*)d_in[13];
    const float* pk_w1 = (const float*)d_in[14];
    const float* pk_b1 = (const float*)d_in[15];
    const float* pk_w2 = (const float*)d_in[16];
    const float* pk_b2 = (const float*)d_in[17];
    const float* temp  = (const float*)d_in[18];
    const float* ln1g  = (const float*)d_in[19];
    const float* ln1b  = (const float*)d_in[20];
    const float* ln2g  = (const float*)d_in[21];
    const float* ln2b  = (const float*)d_in[22];
    const float* W1    = (const float*)d_in[23];
    const float* b1    = (const float*)d_in[24];
    const float* W2    = (const float*)d_in[25];
    const float* b2    = (const float*)d_in[26];
    float* out = (float*)d_out;

    float *xb, *yb, *qbb, *kbb, *entp;
    cudaGetSymbolAddress((void**)&xb, g_x);
    cudaGetSymbolAddress((void**)&yb, g_y);
    cudaGetSymbolAddress((void**)&qbb, g_qbias);
    cudaGetSymbolAddress((void**)&kbb, g_kbias);
    cudaGetSymbolAddress((void**)&entp, g_entpart);

    __nv_bfloat16 *srch, *srcl, *qh, *ql, *kh, *kl, *vh, *vl, *ath, *atl, *xh, *xl, *ffh, *ffl;
    __nv_bfloat16 *wqh, *wql, *wkh, *wkl, *wvh, *wvl, *woh, *wol, *w1h, *w1l, *w2h, *w2l;
    cudaGetSymbolAddress((void**)&srch, g_src_h); cudaGetSymbolAddress((void**)&srcl, g_src_l);
    cudaGetSymbolAddress((void**)&qh, g_q_h);     cudaGetSymbolAddress((void**)&ql, g_q_l);
    cudaGetSymbolAddress((void**)&kh, g_k_h);     cudaGetSymbolAddress((void**)&kl, g_k_l);
    cudaGetSymbolAddress((void**)&vh, g_v_h);     cudaGetSymbolAddress((void**)&vl, g_v_l);
    cudaGetSymbolAddress((void**)&ath, g_at_h);   cudaGetSymbolAddress((void**)&atl, g_at_l);
    cudaGetSymbolAddress((void**)&xh, g_x_h);     cudaGetSymbolAddress((void**)&xl, g_x_l);
    cudaGetSymbolAddress((void**)&ffh, g_ff_h);   cudaGetSymbolAddress((void**)&ffl, g_ff_l);
    cudaGetSymbolAddress((void**)&wqh, g_wq_h);   cudaGetSymbolAddress((void**)&wql, g_wq_l);
    cudaGetSymbolAddress((void**)&wkh, g_wk_h);   cudaGetSymbolAddress((void**)&wkl, g_wk_l);
    cudaGetSymbolAddress((void**)&wvh, g_wv_h);   cudaGetSymbolAddress((void**)&wvl, g_wv_l);
    cudaGetSymbolAddress((void**)&woh, g_wo_h);   cudaGetSymbolAddress((void**)&wol, g_wo_l);
    cudaGetSymbolAddress((void**)&w1h, g_w1_h);   cudaGetSymbolAddress((void**)&w1l, g_w1_l);
    cudaGetSymbolAddress((void**)&w2h, g_w2_h);   cudaGetSymbolAddress((void**)&w2l, g_w2_l);

    cudaFuncSetAttribute(tcgemm_kernel<1>, cudaFuncAttributeMaxDynamicSharedMemorySize, GEMM_SMEM);
    cudaFuncSetAttribute(tcgemm_kernel<2>, cudaFuncAttributeMaxDynamicSharedMemorySize, GEMM_SMEM);
    cudaFuncSetAttribute(tcgemm_kernel<3>, cudaFuncAttributeMaxDynamicSharedMemorySize, GEMM_SMEM);
    cudaFuncSetAttribute(attn_mma_kernel, cudaFuncAttributeMaxDynamicSharedMemorySize, ASMEM);

    dim3 ct(32, 32);
    convT_kernel<<<ct, 256>>>(Wq, wqh, wql, D_MODEL, D_MODEL);
    convT_kernel<<<ct, 256>>>(Wk, wkh, wkl, D_MODEL, D_MODEL);
    convT_kernel<<<ct, 256>>>(Wv, wvh, wvl, D_MODEL, D_MODEL);
    convT_kernel<<<ct, 256>>>(Wo, woh, wol, D_MODEL, D_MODEL);
    convT_kernel<<<dim3(D_FF / 32, D_MODEL / 32), 256>>>(W1, w1h, w1l, D_MODEL, D_FF);
    convT_kernel<<<dim3(D_MODEL / 32, D_FF / 32), 256>>>(W2, w2h, w2l, D_FF, D_MODEL);

    conv_kernel<<<(M_TOK * D_MODEL / 4 + 255) / 256, 256>>>(src, srch, srcl, M_TOK * D_MODEL / 4);
    posbias_kernel<<<M_TOK / 128, 128>>>(pos, pq_w1, pq_b1, pq_w2, pq_b2,
                                         pk_w1, pk_b1, pk_w2, pk_b2, qbb, kbb);

    dim3 gD(D_MODEL / BN, M_TOK / BM);
    tcgemm_kernel<3><<<gD, 256, GEMM_SMEM>>>(srch, srcl, wqh, wql, bq, (const float*)0,
                                             (float*)0, qh, ql, M_TOK, D_MODEL, D_MODEL);
    tcgemm_kernel<3><<<gD, 256, GEMM_SMEM>>>(srch, srcl, wkh, wkl, bk, (const float*)0,
                                             (float*)0, kh, kl, M_TOK, D_MODEL, D_MODEL);
    tcgemm_kernel<3><<<gD, 256, GEMM_SMEM>>>(srch, srcl, wvh, wvl, bv, (const float*)0,
                                             (float*)0, vh, vl, M_TOK, D_MODEL, D_MODEL);

    attn_mma_kernel<<<dim3(L_ / 128, NHEAD, B_), 256, ASMEM>>>(
        qh, kh, kl, vh, qbb, kbb, temp, ath, atl, entp);

    tcgemm_kernel<2><<<gD, 256, GEMM_SMEM>>>(ath, atl, woh, wol, bo, src,
                                             yb, (__nv_bfloat16*)0, (__nv_bfloat16*)0,
                                             M_TOK, D_MODEL, D_MODEL);
    ln_kernel<1><<<M_TOK, 256>>>(yb, ln1g, ln1b, xb, xh, xl);

    dim3 gF(D_FF / BN, M_TOK / BM);
    tcgemm_kernel<1><<<gF, 256, GEMM_SMEM>>>(xh, xl, w1h, w1l, b1, (const float*)0,
                                             (float*)0, ffh, ffl, M_TOK, D_FF, D_MODEL);
    tcgemm_kernel<2><<<gD, 256, GEMM_SMEM>>>(ffh, ffl, w2h, w2l, b2, xb,
                                             yb, (__nv_bfloat16*)0, (__nv_bfloat16*)0,
                                             M_TOK, D_MODEL, D_FF);
    ln_kernel<0><<<M_TOK, 256>>>(yb, ln2g, ln2b, out, (__nv_bfloat16*)0, (__nv_bfloat16*)0);

    ent_final_kernel<<<1, 256>>>(entp, out, out_size);
}

// round 7
// speedup vs baseline: 4.4153x; 1.4650x over previous
#include <cuda_runtime.h>
#include <cuda_fp16.h>
#include <math.h>
#include <stdint.h>
#include <string.h>

#define D_MODEL 1024
#define NHEAD 16
#define HEAD_DIM 64
#define B_ 2
#define L_ 2048
#define M_TOK 4096
#define D_FF 4096
#define OUT_MAIN (M_TOK * D_MODEL)

// ---------------- scratch (device globals; no allocations allowed) ----------
__device__ float g_x[M_TOK * D_MODEL];
__device__ float g_y[M_TOK * D_MODEL];
__device__ float g_qbias[M_TOK * NHEAD];
__device__ float g_kbias[M_TOK * NHEAD];
__device__ float g_entpart[1024];
// fp16 activations (single precision chunk)
__device__ __half g_src_f[M_TOK * D_MODEL];
__device__ __half g_q_f[M_TOK * D_MODEL];
__device__ __half g_k_f[M_TOK * D_MODEL];
__device__ __half g_v_f[M_TOK * D_MODEL];
__device__ __half g_at_f[M_TOK * D_MODEL];
__device__ __half g_x_f[M_TOK * D_MODEL];
__device__ __half g_ff_f[M_TOK * D_FF];
// fp16 hi/lo split transposed weights [N, K]
__device__ __half g_wq_h[D_MODEL * D_MODEL];
__device__ __half g_wq_l[D_MODEL * D_MODEL];
__device__ __half g_wk_h[D_MODEL * D_MODEL];
__device__ __half g_wk_l[D_MODEL * D_MODEL];
__device__ __half g_wv_h[D_MODEL * D_MODEL];
__device__ __half g_wv_l[D_MODEL * D_MODEL];
__device__ __half g_wo_h[D_MODEL * D_MODEL];
__device__ __half g_wo_l[D_MODEL * D_MODEL];
__device__ __half g_w1_h[D_FF * D_MODEL];
__device__ __half g_w1_l[D_FF * D_MODEL];
__device__ __half g_w2_h[D_MODEL * D_FF];
__device__ __half g_w2_l[D_MODEL * D_FF];

// ======================= PTX helpers (baseline sm_103-legal only) ===========
__device__ __forceinline__ uint32_t smem_u32(const void* p) {
    uint32_t a;
    asm("{ .reg .u64 t; cvta.to.shared.u64 t, %1; cvt.u32.u64 %0, t; }" : "=r"(a) : "l"(p));
    return a;
}
__device__ __forceinline__ void cp16(uint32_t s, const void* g) {
    asm volatile("cp.async.cg.shared.global [%0], [%1], 16;" :: "r"(s), "l"(g));
}
__device__ __forceinline__ void cp4(uint32_t s, const void* g) {
    asm volatile("cp.async.ca.shared.global [%0], [%1], 4;" :: "r"(s), "l"(g));
}
#define CP_COMMIT() asm volatile("cp.async.commit_group;" ::: "memory")

__device__ __forceinline__ void ldsm4(uint32_t* r, uint32_t addr) {
    asm volatile("ldmatrix.sync.aligned.m8n8.x4.shared.b16 {%0,%1,%2,%3}, [%4];"
                 : "=r"(r[0]), "=r"(r[1]), "=r"(r[2]), "=r"(r[3]) : "r"(addr));
}
__device__ __forceinline__ void ldsm4t(uint32_t* r, uint32_t addr) {
    asm volatile("ldmatrix.sync.aligned.m8n8.x4.trans.shared.b16 {%0,%1,%2,%3}, [%4];"
                 : "=r"(r[0]), "=r"(r[1]), "=r"(r[2]), "=r"(r[3]) : "r"(addr));
}
__device__ __forceinline__ void mma16816(float* d, const uint32_t* a, uint32_t b0, uint32_t b1) {
    asm volatile(
        "mma.sync.aligned.m16n8k16.row.col.f32.f16.f16.f32 "
        "{%0,%1,%2,%3}, {%4,%5,%6,%7}, {%8,%9}, {%0,%1,%2,%3};"
        : "+f"(d[0]), "+f"(d[1]), "+f"(d[2]), "+f"(d[3])
        : "r"(a[0]), "r"(a[1]), "r"(a[2]), "r"(a[3]), "r"(b0), "r"(b1));
}
__device__ __forceinline__ uint32_t packh(float a, float b) {
    __half2 t = __floats2half2_rn(a, b);
    uint32_t u; memcpy(&u, &t, 4); return u;
}

// ======================= warp-MMA fp16 GEMM (A single, W split) =============
// C[M,N] = A[M,K] @ (Wh+Wl)[N,K]^T  (2 MMA passes)
// MODE 0: fp32 +bias  MODE 1: gelu(+bias)->fp16  MODE 2: fp32 +bias+res
// MODE 3: +bias -> fp16
#define BM 128
#define BN 128
#define BKC 32
#define RSTR 80
#define TILE_B (128 * RSTR)             // 10240
#define STAGE_B (3 * TILE_B)            // 30720 : A, Wh, Wl
#define NSTAGE 3
#define GEMM_SMEM (NSTAGE * STAGE_B)    // 92160 -> 2 CTAs/SM

__device__ __forceinline__ void g_load_chunk(
    uint32_t smem, int ci, int m0, int n0, int K, int tid,
    const __half* __restrict__ A,
    const __half* __restrict__ Wh, const __half* __restrict__ Wl)
{
    uint32_t sb = smem + (uint32_t)(ci % NSTAGE) * STAGE_B;
    size_t kbase = (size_t)ci * BKC;
#pragma unroll
    for (int t = 0; t < 3; t++) {
        const __half* P = (t == 0) ? A : (t == 1) ? Wh : Wl;
        int r0 = (t == 0) ? m0 : n0;
        uint32_t tb = sb + (uint32_t)t * TILE_B;
#pragma unroll
        for (int rep = 0; rep < 2; rep++) {
            int seg = tid + (rep << 8);
            int row = seg >> 2;
            int s4  = seg & 3;
            cp16(tb + (uint32_t)row * RSTR + (uint32_t)s4 * 16,
                 P + (size_t)(r0 + row) * K + kbase + s4 * 8);
        }
    }
}

template <int MODE>
__global__ void __launch_bounds__(256, 2) tcgemm_kernel(
    const __half* __restrict__ A,
    const __half* __restrict__ Wh, const __half* __restrict__ Wl,
    const float* __restrict__ bias, const float* __restrict__ res,
    float* __restrict__ C, __half* __restrict__ Cf,
    int M, int N, int K)
{
    extern __shared__ char dsm[];
    uint32_t smem = smem_u32(dsm);

    int tid = threadIdx.x;
    int wid = tid >> 5;
    int lane = tid & 31;
    int m0 = blockIdx.y * BM;
    int n0 = blockIdx.x * BN;
    int nchunk = K / BKC;

    int wm = wid & 1;
    int wn = wid >> 1;
    int lr = lane & 15;
    uint32_t lk = (uint32_t)((lane >> 4) << 4);

    float acc[4][4][4];
#pragma unroll
    for (int i = 0; i < 4; i++)
#pragma unroll
        for (int j = 0; j < 4; j++)
#pragma unroll
            for (int c = 0; c < 4; c++) acc[i][j][c] = 0.0f;

    g_load_chunk(smem, 0, m0, n0, K, tid, A, Wh, Wl);
    CP_COMMIT();
    g_load_chunk(smem, 1, m0, n0, K, tid, A, Wh, Wl);
    CP_COMMIT();

    for (int i = 0; i < nchunk; i++) {
        if (i < nchunk - 1)
            asm volatile("cp.async.wait_group 1;" ::: "memory");
        else
            asm volatile("cp.async.wait_group 0;" ::: "memory");
        __syncthreads();

        if (i + 2 < nchunk) {
            g_load_chunk(smem, i + 2, m0, n0, K, tid, A, Wh, Wl);
            CP_COMMIT();
        }

        uint32_t sb = smem + (uint32_t)(i % NSTAGE) * STAGE_B;
        uint32_t aBase = sb + (uint32_t)(wm * 64 + lr) * RSTR + lk;
        uint32_t bBase = sb + TILE_B + (uint32_t)(wn * 32 + lr) * RSTR + lk;

#pragma unroll
        for (int ks = 0; ks < 2; ks++) {
            uint32_t koff = (uint32_t)ks * 32;
            uint32_t ah[4][4];
#pragma unroll
            for (int mt = 0; mt < 4; mt++)
                ldsm4(ah[mt], aBase + (uint32_t)(mt * 16) * RSTR + koff);
#pragma unroll
            for (int nt = 0; nt < 2; nt++) {
                uint32_t bb[4];
                ldsm4(bb, bBase + (uint32_t)(nt * 16) * RSTR + koff);            // W-hi
#pragma unroll
                for (int mt = 0; mt < 4; mt++) {
                    mma16816(acc[mt][nt * 2],     ah[mt], bb[0], bb[2]);
                    mma16816(acc[mt][nt * 2 + 1], ah[mt], bb[1], bb[3]);
                }
                ldsm4(bb, bBase + TILE_B + (uint32_t)(nt * 16) * RSTR + koff);   // W-lo
#pragma unroll
                for (int mt = 0; mt < 4; mt++) {
                    mma16816(acc[mt][nt * 2],     ah[mt], bb[0], bb[2]);
                    mma16816(acc[mt][nt * 2 + 1], ah[mt], bb[1], bb[3]);
                }
            }
        }
    }

    int rbase = m0 + wm * 64 + (lane >> 2);
    int cbase = n0 + wn * 32 + (lane & 3) * 2;
#pragma unroll
    for (int mt = 0; mt < 4; mt++) {
#pragma unroll
        for (int n8 = 0; n8 < 4; n8++) {
            int col = cbase + n8 * 8;
            float b0 = bias[col], b1 = bias[col + 1];
#pragma unroll
            for (int half = 0; half < 2; half++) {
                int row = rbase + mt * 16 + half * 8;
                float v0 = acc[mt][n8][half * 2] + b0;
                float v1 = acc[mt][n8][half * 2 + 1] + b1;
                if (MODE == 1) {
                    v0 = 0.5f * v0 * (1.0f + erff(v0 * 0.70710678118654752f));
                    v1 = 0.5f * v1 * (1.0f + erff(v1 * 0.70710678118654752f));
                }
                if (MODE == 2) {
                    const float2 rv = *(const float2*)(res + (size_t)row * N + col);
                    v0 += rv.x; v1 += rv.y;
                }
                if (MODE == 0 || MODE == 2) {
                    float2 o; o.x = v0; o.y = v1;
                    *(float2*)(C + (size_t)row * N + col) = o;
                } else {
                    *(__half2*)(Cf + (size_t)row * N + col) = __floats2half2_rn(v0, v1);
                }
            }
        }
    }
}

// ======================= MMA flash attention (fp16 single) ==================
// Scores: 1 pass fp16. PV: 1 pass fp16.
#define ASTR 144
#define ATILE (64 * ASTR)               // 9216
#define ASTAGE (2 * ATILE + 256)        // K, V, kb(64 fp32) = 18688
#define ASMEM (2 * ASTAGE + 64)         // 37440

__device__ __forceinline__ void a_load_chunk(
    uint32_t sm0, int ci, size_t tokb, int h, int tid,
    const __half* __restrict__ Kf, const __half* __restrict__ Vf,
    const float* __restrict__ kb)
{
    uint32_t st = sm0 + (uint32_t)(ci & 1) * ASTAGE;
    size_t rowb = tokb + (size_t)ci * 64;
#pragma unroll
    for (int r = 0; r < 4; r++) {
        int idx = tid + (r << 8);          // 0..1023
        int t = idx >> 9;                  // 0..1
        int row = (idx >> 3) & 63;
        int seg = idx & 7;
        const __half* P = (t == 0) ? Kf : Vf;
        cp16(st + (uint32_t)t * ATILE + (uint32_t)row * ASTR + (uint32_t)seg * 16,
             P + (rowb + row) * D_MODEL + h * HEAD_DIM + seg * 8);
    }
    if (tid < 64)
        cp4(st + 2u * ATILE + (uint32_t)tid * 4, kb + (rowb + tid) * NHEAD + h);
}

__global__ void __launch_bounds__(256, 1) attn_mma_kernel(
    const __half* __restrict__ Qf, const __half* __restrict__ Kf,
    const __half* __restrict__ Vf,
    const float* __restrict__ qb, const float* __restrict__ kb,
    const float* __restrict__ temp,
    __half* __restrict__ Of, float* __restrict__ ent_part)
{
    extern __shared__ char smemv[];
    uint32_t sm0 = smem_u32(smemv);
    float* red = (float*)(smemv + 2 * ASTAGE);

    int tid = threadIdx.x;
    int w = tid >> 5;
    int lane = tid & 31;
    int q0 = blockIdx.x * 128;
    int h = blockIdx.y;
    int b = blockIdx.z;
    size_t tokb = (size_t)b * L_;

    float tmph = fminf(fmaxf(temp[h], 0.1f), 5.0f);
    float inv_t = 1.0f / tmph;
    float sc = 0.125f * inv_t;

    for (int i = tid; i < 128 * 8; i += 256) {
        int row = i >> 3, seg = i & 7;
        cp16(sm0 + (uint32_t)row * ASTR + (uint32_t)seg * 16,
             Qf + (tokb + q0 + row) * D_MODEL + h * HEAD_DIM + seg * 8);
    }
    CP_COMMIT();
    asm volatile("cp.async.wait_group 0;" ::: "memory");
    __syncthreads();

    uint32_t qfr[4][4];
    {
        uint32_t qbase = sm0 + (uint32_t)(w * 16 + (lane & 15)) * ASTR + (uint32_t)((lane >> 4) << 4);
#pragma unroll
        for (int ks = 0; ks < 4; ks++) ldsm4(qfr[ks], qbase + ks * 32);
    }
    int gid = lane >> 2, tig = lane & 3;
    int r0 = q0 + w * 16 + gid, r1 = r0 + 8;
    float qb0 = qb[(tokb + r0) * NHEAD + h] * inv_t;
    float qb1 = qb[(tokb + r1) * NHEAD + h] * inv_t;
    __syncthreads();

    a_load_chunk(sm0, 0, tokb, h, tid, Kf, Vf, kb);
    CP_COMMIT();
    a_load_chunk(sm0, 1, tokb, h, tid, Kf, Vf, kb);
    CP_COMMIT();

    float O[8][4];
#pragma unroll
    for (int f = 0; f < 8; f++)
#pragma unroll
        for (int c = 0; c < 4; c++) O[f][c] = 0.0f;
    float m0 = -1e30f, m1 = -1e30f, z0 = 0.0f, z1 = 0.0f, t0 = 0.0f, t1 = 0.0f;

    const int NCH = L_ / 64;
    for (int ci = 0; ci < NCH; ci++) {
        if (ci < NCH - 2)
            asm volatile("cp.async.wait_group 1;" ::: "memory");
        else
            asm volatile("cp.async.wait_group 0;" ::: "memory");
        __syncthreads();

        uint32_t st = sm0 + (uint32_t)(ci & 1) * ASTAGE;
        uint32_t kbh = st + (uint32_t)(lane & 15) * ASTR + (uint32_t)((lane >> 4) << 4);

        float S[8][4];
#pragma unroll
        for (int f = 0; f < 8; f++)
#pragma unroll
            for (int c = 0; c < 4; c++) S[f][c] = 0.0f;

#pragma unroll
        for (int ks = 0; ks < 4; ks++) {
            uint32_t koff = (uint32_t)ks * 32;
#pragma unroll
            for (int nt = 0; nt < 4; nt++) {
                uint32_t bb[4];
                ldsm4(bb, kbh + (uint32_t)(nt * 16) * ASTR + koff);
                mma16816(S[nt * 2],     qfr[ks], bb[0], bb[2]);
                mma16816(S[nt * 2 + 1], qfr[ks], bb[1], bb[3]);
            }
        }

        const float* kbs = (const float*)(smemv + (size_t)((ci & 1) * ASTAGE + 2 * ATILE));
        float mx0 = -1e30f, mx1 = -1e30f;
#pragma unroll
        for (int f = 0; f < 8; f++) {
            float kc0 = kbs[f * 8 + 2 * tig] * inv_t;
            float kc1 = kbs[f * 8 + 2 * tig + 1] * inv_t;
            S[f][0] = S[f][0] * sc + qb0 + kc0;
            S[f][1] = S[f][1] * sc + qb0 + kc1;
            S[f][2] = S[f][2] * sc + qb1 + kc0;
            S[f][3] = S[f][3] * sc + qb1 + kc1;
            mx0 = fmaxf(mx0, fmaxf(S[f][0], S[f][1]));
            mx1 = fmaxf(mx1, fmaxf(S[f][2], S[f][3]));
        }
        mx0 = fmaxf(mx0, __shfl_xor_sync(0xffffffffu, mx0, 1));
        mx0 = fmaxf(mx0, __shfl_xor_sync(0xffffffffu, mx0, 2));
        mx1 = fmaxf(mx1, __shfl_xor_sync(0xffffffffu, mx1, 1));
        mx1 = fmaxf(mx1, __shfl_xor_sync(0xffffffffu, mx1, 2));

        float nm0 = fmaxf(m0, mx0), nm1 = fmaxf(m1, mx1);
        float sc0 = __expf(m0 - nm0), sc1 = __expf(m1 - nm1);
        float zc0 = 0.0f, zc1 = 0.0f, tc0 = 0.0f, tc1 = 0.0f;
        uint32_t pa[4][4];
#pragma unroll
        for (int j = 0; j < 4; j++) {
#pragma unroll
            for (int g = 0; g < 2; g++) {
                int f = 2 * j + g;
                float p0 = __expf(S[f][0] - nm0);
                float p1 = __expf(S[f][1] - nm0);
                float p2 = __expf(S[f][2] - nm1);
                float p3 = __expf(S[f][3] - nm1);
                zc0 += p0 + p1; zc1 += p2 + p3;
                tc0 += p0 * S[f][0] + p1 * S[f][1];
                tc1 += p2 * S[f][2] + p3 * S[f][3];
                pa[j][g * 2]     = packh(p0, p1);
                pa[j][g * 2 + 1] = packh(p2, p3);
            }
        }
        zc0 += __shfl_xor_sync(0xffffffffu, zc0, 1); zc0 += __shfl_xor_sync(0xffffffffu, zc0, 2);
        zc1 += __shfl_xor_sync(0xffffffffu, zc1, 1); zc1 += __shfl_xor_sync(0xffffffffu, zc1, 2);
        tc0 += __shfl_xor_sync(0xffffffffu, tc0, 1); tc0 += __shfl_xor_sync(0xffffffffu, tc0, 2);
        tc1 += __shfl_xor_sync(0xffffffffu, tc1, 1); tc1 += __shfl_xor_sync(0xffffffffu, tc1, 2);
        z0 = z0 * sc0 + zc0; t0 = t0 * sc0 + tc0; m0 = nm0;
        z1 = z1 * sc1 + zc1; t1 = t1 * sc1 + tc1; m1 = nm1;
#pragma unroll
        for (int f = 0; f < 8; f++) {
            O[f][0] *= sc0; O[f][1] *= sc0; O[f][2] *= sc1; O[f][3] *= sc1;
        }

        uint32_t vb = st + ATILE + (uint32_t)(lane & 15) * ASTR + (uint32_t)((lane >> 4) << 4);
#pragma unroll
        for (int j = 0; j < 4; j++) {
            uint32_t vrow = vb + (uint32_t)(j * 16) * ASTR;
#pragma unroll
            for (int hg = 0; hg < 4; hg++) {
                uint32_t v[4];
                ldsm4t(v, vrow + (uint32_t)hg * 32);
                mma16816(O[hg * 2],     pa[j], v[0], v[1]);
                mma16816(O[hg * 2 + 1], pa[j], v[2], v[3]);
            }
        }
        __syncthreads();
        if (ci + 2 < NCH) {
            a_load_chunk(sm0, ci + 2, tokb, h, tid, Kf, Vf, kb);
            CP_COMMIT();
        }
    }

    float iz0 = 1.0f / z0, iz1 = 1.0f / z1;
    size_t row0b = (tokb + r0) * D_MODEL, row1b = (tokb + r1) * D_MODEL;
#pragma unroll
    for (int f = 0; f < 8; f++) {
        int col = h * HEAD_DIM + f * 8 + 2 * tig;
        *(__half2*)(Of + row0b + col) = __floats2half2_rn(O[f][0] * iz0, O[f][1] * iz0);
        *(__half2*)(Of + row1b + col) = __floats2half2_rn(O[f][2] * iz1, O[f][3] * iz1);
    }

    float Hv = (m0 + logf(z0) - t0 / z0 + m1 + logf(z1) - t1 / z1) * 0.25f;
#pragma unroll
    for (int off = 16; off; off >>= 1) Hv += __shfl_xor_sync(0xffffffffu, Hv, off);
    if (lane == 0) red[w] = Hv;
    __syncthreads();
    if (tid == 0) {
        float s = 0.0f;
#pragma unroll
        for (int i = 0; i < 8; i++) s += red[i];
        ent_part[((b * NHEAD + h) << 4) + blockIdx.x] = s;
    }
}

// ======================= weight transpose + split ===========================
__global__ void __launch_bounds__(256) convT_kernel(
    const float* __restrict__ W, __half* __restrict__ hi, __half* __restrict__ lo,
    int K, int N)
{
    __shared__ float t[32][33];
    int n0 = blockIdx.x * 32, k0 = blockIdx.y * 32;
    int tx = threadIdx.x & 31, ty = threadIdx.x >> 5;
#pragma unroll
    for (int i = 0; i < 32; i += 8)
        t[ty + i][tx] = W[(size_t)(k0 + ty + i) * N + n0 + tx];
    __syncthreads();
#pragma unroll
    for (int i = 0; i < 32; i += 8) {
        float v = t[tx][ty + i];
        __half hh = __float2half_rn(v);
        __half ll = __float2half_rn(v - __half2float(hh));
        size_t o = (size_t)(n0 + ty + i) * K + k0 + tx;
        hi[o] = hh; lo[o] = ll;
    }
}

__global__ void __launch_bounds__(256) conv_kernel(
    const float* __restrict__ in, __half* __restrict__ outp, int n4)
{
    int i = blockIdx.x * 256 + threadIdx.x;
    if (i >= n4) return;
    float4 v = ((const float4*)in)[i];
    ((__half2*)outp)[i * 2]     = __floats2half2_rn(v.x, v.y);
    ((__half2*)outp)[i * 2 + 1] = __floats2half2_rn(v.z, v.w);
}

// ---------------- POS bias MLPs ----------------------------------------------
__global__ void __launch_bounds__(128) posbias_kernel(
    const float* __restrict__ pos,
    const float* __restrict__ qw1, const float* __restrict__ qb1,
    const float* __restrict__ qw2, const float* __restrict__ qb2,
    const float* __restrict__ kw1, const float* __restrict__ kb1,
    const float* __restrict__ kw2, const float* __restrict__ kb2,
    float* __restrict__ qbias, float* __restrict__ kbias)
{
    __shared__ float sw1q[32 * 32], sw2q[32 * 16], sb1q[32], sb2q[16];
    __shared__ float sw1k[32 * 32], sw2k[32 * 16], sb1k[32], sb2k[16];
    int tid = threadIdx.x;
    for (int i = tid; i < 1024; i += 128) { sw1q[i] = qw1[i]; sw1k[i] = kw1[i]; }
    for (int i = tid; i < 512;  i += 128) { sw2q[i] = qw2[i]; sw2k[i] = kw2[i]; }
    if (tid < 32) { sb1q[tid] = qb1[tid]; sb1k[tid] = kb1[tid]; }
    if (tid < 16) { sb2q[tid] = qb2[tid]; sb2k[tid] = kb2[tid]; }
    __syncthreads();

    int token = blockIdx.x * 128 + tid;
    float pf[32];
#pragma unroll
    for (int i = 0; i < 32; i++) pf[i] = pos[(size_t)token * 32 + i];

    float hq[32], hk[32];
#pragma unroll
    for (int j = 0; j < 32; j++) { hq[j] = sb1q[j]; hk[j] = sb1k[j]; }
    for (int i = 0; i < 32; i++) {
        float p = pf[i];
#pragma unroll
        for (int j = 0; j < 32; j++) {
            hq[j] += p * sw1q[i * 32 + j];
            hk[j] += p * sw1k[i * 32 + j];
        }
    }
#pragma unroll
    for (int j = 0; j < 32; j++) {
        hq[j] = fmaxf(hq[j], 0.0f);
        hk[j] = fmaxf(hk[j], 0.0f);
    }
#pragma unroll
    for (int h = 0; h < 16; h++) {
        float oq = sb2q[h], ok = sb2k[h];
        for (int j = 0; j < 32; j++) {
            oq += hq[j] * sw2q[j * 16 + h];
            ok += hk[j] * sw2k[j * 16 + h];
        }
        qbias[(size_t)token * NHEAD + h] = oq;
        kbias[(size_t)token * NHEAD + h] = ok;
    }
}

// ---------------- layernorm (optionally emits fp16) --------------------------
template <int SPLIT>
__global__ void __launch_bounds__(256) ln_kernel(
    const float* __restrict__ in, const float* __restrict__ gam,
    const float* __restrict__ bet, float* __restrict__ out,
    __half* __restrict__ of)
{
    int row = blockIdx.x, tid = threadIdx.x;
    float4 v = ((const float4*)(in + (size_t)row * D_MODEL))[tid];
    float s = v.x + v.y + v.z + v.w;
    float q = v.x * v.x + v.y * v.y + v.z * v.z + v.w * v.w;
#pragma unroll
    for (int off = 16; off; off >>= 1) {
        s += __shfl_xor_sync(0xffffffffu, s, off);
        q += __shfl_xor_sync(0xffffffffu, q, off);
    }
    __shared__ float ws[8], wq[8], stats[2];
    int lane = tid & 31, w = tid >> 5;
    if (lane == 0) { ws[w] = s; wq[w] = q; }
    __syncthreads();
    if (tid == 0) {
        float S = 0.0f, Qq = 0.0f;
        for (int i = 0; i < 8; i++) { S += ws[i]; Qq += wq[i]; }
        float mu  = S * (1.0f / D_MODEL);
        float var = Qq * (1.0f / D_MODEL) - mu * mu;
        stats[0] = mu;
        stats[1] = rsqrtf(var + 1e-5f);
    }
    __syncthreads();
    float mu = stats[0], rs = stats[1];
    float4 gv = ((const float4*)gam)[tid];
    float4 bv = ((const float4*)bet)[tid];
    float4 ov;
    ov.x = (v.x - mu) * rs * gv.x + bv.x;
    ov.y = (v.y - mu) * rs * gv.y + bv.y;
    ov.z = (v.z - mu) * rs * gv.z + bv.z;
    ov.w = (v.w - mu) * rs * gv.w + bv.w;
    ((float4*)(out + (size_t)row * D_MODEL))[tid] = ov;
    if (SPLIT) {
        size_t base = (size_t)row * D_MODEL + tid * 4;
        *(__half2*)(of + base)     = __floats2half2_rn(ov.x, ov.y);
        *(__half2*)(of + base + 2) = __floats2half2_rn(ov.z, ov.w);
    }
}

// ---------------- deterministic entropy reduction ----------------------------
__global__ void __launch_bounds__(256) ent_final_kernel(
    const float* __restrict__ part, float* __restrict__ out, int out_size)
{
    __shared__ float sm[256];
    int tid = threadIdx.x;
    sm[tid] = part[tid] + part[tid + 256];
    __syncthreads();
    for (int off = 128; off; off >>= 1) {
        if (tid < off) sm[tid] += sm[tid + off];
        __syncthreads();
    }
    if (tid == 0 && out_size > OUT_MAIN)
        out[OUT_MAIN] = sm[0] * (1.0f / (B_ * NHEAD * L_));
}

// ---------------- launch -----------------------------------------------------
extern "C" void kernel_launch(void* const* d_in, const int* in_sizes, int n_in,
                              void* d_out, int out_size)
{
    const float* src   = (const float*)d_in[0];
    const float* pos   = (const float*)d_in[1];
    const float* Wq    = (const float*)d_in[2];
    const float* bq    = (const float*)d_in[3];
    const float* Wk    = (const float*)d_in[4];
    const float* bk    = (const float*)d_in[5];
    const float* Wv    = (const float*)d_in[6];
    const float* bv    = (const float*)d_in[7];
    const float* Wo    = (const float*)d_in[8];
    const float* bo    = (const float*)d_in[9];
    const float* pq_w1 = (const float*)d_in[10];
    const float* pq_b1 = (const float*)d_in[11];
    const float* pq_w2 = (const float*)d_in[12];
    const float* pq_b2 = (const float*)d_in[13];
    const float* pk_w1 = (const float*)d_in[14];
    const float* pk_b1 = (const float*)d_in[15];
    const float* pk_w2 = (const float*)d_in[16];
    const float* pk_b2 = (const float*)d_in[17];
    const float* temp  = (const float*)d_in[18];
    const float* ln1g  = (const float*)d_in[19];
    const float* ln1b  = (const float*)d_in[20];
    const float* ln2g  = (const float*)d_in[21];
    const float* ln2b  = (const float*)d_in[22];
    const float* W1    = (const float*)d_in[23];
    const float* b1    = (const float*)d_in[24];
    const float* W2    = (const float*)d_in[25];
    const float* b2    = (const float*)d_in[26];
    float* out = (float*)d_out;

    float *xb, *yb, *qbb, *kbb, *entp;
    cudaGetSymbolAddress((void**)&xb, g_x);
    cudaGetSymbolAddress((void**)&yb, g_y);
    cudaGetSymbolAddress((void**)&qbb, g_qbias);
    cudaGetSymbolAddress((void**)&kbb, g_kbias);
    cudaGetSymbolAddress((void**)&entp, g_entpart);

    __half *srcf, *qf, *kf, *vf, *atf, *xf, *fff;
    __half *wqh, *wql, *wkh, *wkl, *wvh, *wvl, *woh, *wol, *w1h, *w1l, *w2h, *w2l;
    cudaGetSymbolAddress((void**)&srcf, g_src_f);
    cudaGetSymbolAddress((void**)&qf, g_q_f);
    cudaGetSymbolAddress((void**)&kf, g_k_f);
    cudaGetSymbolAddress((void**)&vf, g_v_f);
    cudaGetSymbolAddress((void**)&atf, g_at_f);
    cudaGetSymbolAddress((void**)&xf, g_x_f);
    cudaGetSymbolAddress((void**)&fff, g_ff_f);
    cudaGetSymbolAddress((void**)&wqh, g_wq_h);   cudaGetSymbolAddress((void**)&wql, g_wq_l);
    cudaGetSymbolAddress((void**)&wkh, g_wk_h);   cudaGetSymbolAddress((void**)&wkl, g_wk_l);
    cudaGetSymbolAddress((void**)&wvh, g_wv_h);   cudaGetSymbolAddress((void**)&wvl, g_wv_l);
    cudaGetSymbolAddress((void**)&woh, g_wo_h);   cudaGetSymbolAddress((void**)&wol, g_wo_l);
    cudaGetSymbolAddress((void**)&w1h, g_w1_h);   cudaGetSymbolAddress((void**)&w1l, g_w1_l);
    cudaGetSymbolAddress((void**)&w2h, g_w2_h);   cudaGetSymbolAddress((void**)&w2l, g_w2_l);

    cudaFuncSetAttribute(tcgemm_kernel<1>, cudaFuncAttributeMaxDynamicSharedMemorySize, GEMM_SMEM);
    cudaFuncSetAttribute(tcgemm_kernel<2>, cudaFuncAttributeMaxDynamicSharedMemorySize, GEMM_SMEM);
    cudaFuncSetAttribute(tcgemm_kernel<3>, cudaFuncAttributeMaxDynamicSharedMemorySize, GEMM_SMEM);
    cudaFuncSetAttribute(attn_mma_kernel, cudaFuncAttributeMaxDynamicSharedMemorySize, ASMEM);

    dim3 ct(32, 32);
    convT_kernel<<<ct, 256>>>(Wq, wqh, wql, D_MODEL, D_MODEL);
    convT_kernel<<<ct, 256>>>(Wk, wkh, wkl, D_MODEL, D_MODEL);
    convT_kernel<<<ct, 256>>>(Wv, wvh, wvl, D_MODEL, D_MODEL);
    convT_kernel<<<ct, 256>>>(Wo, woh, wol, D_MODEL, D_MODEL);
    convT_kernel<<<dim3(D_FF / 32, D_MODEL / 32), 256>>>(W1, w1h, w1l, D_MODEL, D_FF);
    convT_kernel<<<dim3(D_MODEL / 32, D_FF / 32), 256>>>(W2, w2h, w2l, D_FF, D_MODEL);

    conv_kernel<<<(M_TOK * D_MODEL / 4 + 255) / 256, 256>>>(src, srcf, M_TOK * D_MODEL / 4);
    posbias_kernel<<<M_TOK / 128, 128>>>(pos, pq_w1, pq_b1, pq_w2, pq_b2,
                                         pk_w1, pk_b1, pk_w2, pk_b2, qbb, kbb);

    // QKV projections -> fp16
    dim3 gD(D_MODEL / BN, M_TOK / BM);
    tcgemm_kernel<3><<<gD, 256, GEMM_SMEM>>>(srcf, wqh, wql, bq, (const float*)0,
                                             (float*)0, qf, M_TOK, D_MODEL, D_MODEL);
    tcgemm_kernel<3><<<gD, 256, GEMM_SMEM>>>(srcf, wkh, wkl, bk, (const float*)0,
                                             (float*)0, kf, M_TOK, D_MODEL, D_MODEL);
    tcgemm_kernel<3><<<gD, 256, GEMM_SMEM>>>(srcf, wvh, wvl, bv, (const float*)0,
                                             (float*)0, vf, M_TOK, D_MODEL, D_MODEL);

    attn_mma_kernel<<<dim3(L_ / 128, NHEAD, B_), 256, ASMEM>>>(
        qf, kf, vf, qbb, kbb, temp, atf, entp);

    tcgemm_kernel<2><<<gD, 256, GEMM_SMEM>>>(atf, woh, wol, bo, src,
                                             yb, (__half*)0, M_TOK, D_MODEL, D_MODEL);
    ln_kernel<1><<<M_TOK, 256>>>(yb, ln1g, ln1b, xb, xf);

    dim3 gF(D_FF / BN, M_TOK / BM);
    tcgemm_kernel<1><<<gF, 256, GEMM_SMEM>>>(xf, w1h, w1l, b1, (const float*)0,
                                             (float*)0, fff, M_TOK, D_FF, D_MODEL);
    tcgemm_kernel<2><<<gD, 256, GEMM_SMEM>>>(fff, w2h, w2l, b2, xb,
                                             yb, (__half*)0, M_TOK, D_MODEL, D_FF);
    ln_kernel<0><<<M_TOK, 256>>>(yb, ln2g, ln2b, out, (__half*)0);

    ent_final_kernel<<<1, 256>>>(entp, out, out_size);
}

// round 8
// speedup vs baseline: 6.2665x; 1.4193x over previous
#include <cuda_runtime.h>
#include <cuda_fp16.h>
#include <math.h>
#include <stdint.h>
#include <string.h>

#define D_MODEL 1024
#define NHEAD 16
#define HEAD_DIM 64
#define B_ 2
#define L_ 2048
#define M_TOK 4096
#define D_FF 4096
#define OUT_MAIN (M_TOK * D_MODEL)

// ---------------- scratch (device globals; no allocations allowed) ----------
__device__ float g_x[M_TOK * D_MODEL];
__device__ float g_y[M_TOK * D_MODEL];
__device__ float g_qbias[M_TOK * NHEAD];
__device__ float g_kbias[M_TOK * NHEAD];
__device__ float g_entpart[1024];
// fp16 activations
__device__ __half g_src_f[M_TOK * D_MODEL];
__device__ __half g_q_f[M_TOK * D_MODEL];
__device__ __half g_k_f[M_TOK * D_MODEL];
__device__ __half g_v_f[M_TOK * D_MODEL];
__device__ __half g_at_f[M_TOK * D_MODEL];
__device__ __half g_x_f[M_TOK * D_MODEL];
__device__ __half g_ff_f[M_TOK * D_FF];
// fp16 transposed weights [N, K]
__device__ __half g_wq[D_MODEL * D_MODEL];
__device__ __half g_wk[D_MODEL * D_MODEL];
__device__ __half g_wv[D_MODEL * D_MODEL];
__device__ __half g_wo[D_MODEL * D_MODEL];
__device__ __half g_w1[D_FF * D_MODEL];
__device__ __half g_w2[D_MODEL * D_FF];

// ======================= PTX helpers (baseline sm_103-legal only) ===========
__device__ __forceinline__ uint32_t smem_u32(const void* p) {
    uint32_t a;
    asm("{ .reg .u64 t; cvta.to.shared.u64 t, %1; cvt.u32.u64 %0, t; }" : "=r"(a) : "l"(p));
    return a;
}
__device__ __forceinline__ void cp16(uint32_t s, const void* g) {
    asm volatile("cp.async.cg.shared.global [%0], [%1], 16;" :: "r"(s), "l"(g));
}
__device__ __forceinline__ void cp4(uint32_t s, const void* g) {
    asm volatile("cp.async.ca.shared.global [%0], [%1], 4;" :: "r"(s), "l"(g));
}
#define CP_COMMIT() asm volatile("cp.async.commit_group;" ::: "memory")

__device__ __forceinline__ void ldsm4(uint32_t* r, uint32_t addr) {
    asm volatile("ldmatrix.sync.aligned.m8n8.x4.shared.b16 {%0,%1,%2,%3}, [%4];"
                 : "=r"(r[0]), "=r"(r[1]), "=r"(r[2]), "=r"(r[3]) : "r"(addr));
}
__device__ __forceinline__ void ldsm4t(uint32_t* r, uint32_t addr) {
    asm volatile("ldmatrix.sync.aligned.m8n8.x4.trans.shared.b16 {%0,%1,%2,%3}, [%4];"
                 : "=r"(r[0]), "=r"(r[1]), "=r"(r[2]), "=r"(r[3]) : "r"(addr));
}
__device__ __forceinline__ void mma16816(float* d, const uint32_t* a, uint32_t b0, uint32_t b1) {
    asm volatile(
        "mma.sync.aligned.m16n8k16.row.col.f32.f16.f16.f32 "
        "{%0,%1,%2,%3}, {%4,%5,%6,%7}, {%8,%9}, {%0,%1,%2,%3};"
        : "+f"(d[0]), "+f"(d[1]), "+f"(d[2]), "+f"(d[3])
        : "r"(a[0]), "r"(a[1]), "r"(a[2]), "r"(a[3]), "r"(b0), "r"(b1));
}
__device__ __forceinline__ uint32_t packh(float a, float b) {
    __half2 t = __floats2half2_rn(a, b);
    uint32_t u; memcpy(&u, &t, 4); return u;
}

// ======================= warp-MMA fp16 GEMM (single precision pass) =========
// C[M,N] = A[M,K] @ W[N,K]^T
// MODE 0: fp32 +bias  MODE 1: gelu(+bias)->fp16  MODE 2: fp32 +bias+res
// MODE 3: +bias -> fp16
#define BM 128
#define BN 128
#define BKC 32
#define RSTR 80
#define TILE_B (128 * RSTR)             // 10240
#define STAGE_B (2 * TILE_B)            // 20480 : A, W
#define NSTAGE 3
#define GEMM_SMEM (NSTAGE * STAGE_B)    // 61440

__device__ __forceinline__ void g_load_chunk(
    uint32_t smem, int ci, int m0, int n0, int K, int tid,
    const __half* __restrict__ A, const __half* __restrict__ W)
{
    uint32_t sb = smem + (uint32_t)(ci % NSTAGE) * STAGE_B;
    size_t kbase = (size_t)ci * BKC;
#pragma unroll
    for (int t = 0; t < 2; t++) {
        const __half* P = (t == 0) ? A : W;
        int r0 = (t == 0) ? m0 : n0;
        uint32_t tb = sb + (uint32_t)t * TILE_B;
#pragma unroll
        for (int rep = 0; rep < 2; rep++) {
            int seg = tid + (rep << 8);
            int row = seg >> 2;
            int s4  = seg & 3;
            cp16(tb + (uint32_t)row * RSTR + (uint32_t)s4 * 16,
                 P + (size_t)(r0 + row) * K + kbase + s4 * 8);
        }
    }
}

template <int MODE>
__global__ void __launch_bounds__(256, 2) tcgemm_kernel(
    const __half* __restrict__ A, const __half* __restrict__ W,
    const float* __restrict__ bias, const float* __restrict__ res,
    float* __restrict__ C, __half* __restrict__ Cf,
    int M, int N, int K)
{
    extern __shared__ char dsm[];
    uint32_t smem = smem_u32(dsm);

    int tid = threadIdx.x;
    int wid = tid >> 5;
    int lane = tid & 31;
    int m0 = blockIdx.y * BM;
    int n0 = blockIdx.x * BN;
    int nchunk = K / BKC;

    int wm = wid & 1;
    int wn = wid >> 1;
    int lr = lane & 15;
    uint32_t lk = (uint32_t)((lane >> 4) << 4);

    float acc[4][4][4];
#pragma unroll
    for (int i = 0; i < 4; i++)
#pragma unroll
        for (int j = 0; j < 4; j++)
#pragma unroll
            for (int c = 0; c < 4; c++) acc[i][j][c] = 0.0f;

    g_load_chunk(smem, 0, m0, n0, K, tid, A, W);
    CP_COMMIT();
    g_load_chunk(smem, 1, m0, n0, K, tid, A, W);
    CP_COMMIT();

    for (int i = 0; i < nchunk; i++) {
        if (i < nchunk - 1)
            asm volatile("cp.async.wait_group 1;" ::: "memory");
        else
            asm volatile("cp.async.wait_group 0;" ::: "memory");
        __syncthreads();

        if (i + 2 < nchunk) {
            g_load_chunk(smem, i + 2, m0, n0, K, tid, A, W);
            CP_COMMIT();
        }

        uint32_t sb = smem + (uint32_t)(i % NSTAGE) * STAGE_B;
        uint32_t aBase = sb + (uint32_t)(wm * 64 + lr) * RSTR + lk;
        uint32_t bBase = sb + TILE_B + (uint32_t)(wn * 32 + lr) * RSTR + lk;

#pragma unroll
        for (int ks = 0; ks < 2; ks++) {
            uint32_t koff = (uint32_t)ks * 32;
            uint32_t ah[4][4];
#pragma unroll
            for (int mt = 0; mt < 4; mt++)
                ldsm4(ah[mt], aBase + (uint32_t)(mt * 16) * RSTR + koff);
#pragma unroll
            for (int nt = 0; nt < 2; nt++) {
                uint32_t bb[4];
                ldsm4(bb, bBase + (uint32_t)(nt * 16) * RSTR + koff);
#pragma unroll
                for (int mt = 0; mt < 4; mt++) {
                    mma16816(acc[mt][nt * 2],     ah[mt], bb[0], bb[2]);
                    mma16816(acc[mt][nt * 2 + 1], ah[mt], bb[1], bb[3]);
                }
            }
        }
    }

    int rbase = m0 + wm * 64 + (lane >> 2);
    int cbase = n0 + wn * 32 + (lane & 3) * 2;
#pragma unroll
    for (int mt = 0; mt < 4; mt++) {
#pragma unroll
        for (int n8 = 0; n8 < 4; n8++) {
            int col = cbase + n8 * 8;
            float b0 = bias[col], b1 = bias[col + 1];
#pragma unroll
            for (int half = 0; half < 2; half++) {
                int row = rbase + mt * 16 + half * 8;
                float v0 = acc[mt][n8][half * 2] + b0;
                float v1 = acc[mt][n8][half * 2 + 1] + b1;
                if (MODE == 1) {
                    v0 = 0.5f * v0 * (1.0f + erff(v0 * 0.70710678118654752f));
                    v1 = 0.5f * v1 * (1.0f + erff(v1 * 0.70710678118654752f));
                }
                if (MODE == 2) {
                    const float2 rv = *(const float2*)(res + (size_t)row * N + col);
                    v0 += rv.x; v1 += rv.y;
                }
                if (MODE == 0 || MODE == 2) {
                    float2 o; o.x = v0; o.y = v1;
                    *(float2*)(C + (size_t)row * N + col) = o;
                } else {
                    *(__half2*)(Cf + (size_t)row * N + col) = __floats2half2_rn(v0, v1);
                }
            }
        }
    }
}

// ======================= MMA flash attention (fp16, unchanged) ==============
#define ASTR 144
#define ATILE (64 * ASTR)
#define ASTAGE (2 * ATILE + 256)
#define ASMEM (2 * ASTAGE + 64)

__device__ __forceinline__ void a_load_chunk(
    uint32_t sm0, int ci, size_t tokb, int h, int tid,
    const __half* __restrict__ Kf, const __half* __restrict__ Vf,
    const float* __restrict__ kb)
{
    uint32_t st = sm0 + (uint32_t)(ci & 1) * ASTAGE;
    size_t rowb = tokb + (size_t)ci * 64;
#pragma unroll
    for (int r = 0; r < 4; r++) {
        int idx = tid + (r << 8);
        int t = idx >> 9;
        int row = (idx >> 3) & 63;
        int seg = idx & 7;
        const __half* P = (t == 0) ? Kf : Vf;
        cp16(st + (uint32_t)t * ATILE + (uint32_t)row * ASTR + (uint32_t)seg * 16,
             P + (rowb + row) * D_MODEL + h * HEAD_DIM + seg * 8);
    }
    if (tid < 64)
        cp4(st + 2u * ATILE + (uint32_t)tid * 4, kb + (rowb + tid) * NHEAD + h);
}

__global__ void __launch_bounds__(256, 1) attn_mma_kernel(
    const __half* __restrict__ Qf, const __half* __restrict__ Kf,
    const __half* __restrict__ Vf,
    const float* __restrict__ qb, const float* __restrict__ kb,
    const float* __restrict__ temp,
    __half* __restrict__ Of, float* __restrict__ ent_part)
{
    extern __shared__ char smemv[];
    uint32_t sm0 = smem_u32(smemv);
    float* red = (float*)(smemv + 2 * ASTAGE);

    int tid = threadIdx.x;
    int w = tid >> 5;
    int lane = tid & 31;
    int q0 = blockIdx.x * 128;
    int h = blockIdx.y;
    int b = blockIdx.z;
    size_t tokb = (size_t)b * L_;

    float tmph = fminf(fmaxf(temp[h], 0.1f), 5.0f);
    float inv_t = 1.0f / tmph;
    float sc = 0.125f * inv_t;

    for (int i = tid; i < 128 * 8; i += 256) {
        int row = i >> 3, seg = i & 7;
        cp16(sm0 + (uint32_t)row * ASTR + (uint32_t)seg * 16,
             Qf + (tokb + q0 + row) * D_MODEL + h * HEAD_DIM + seg * 8);
    }
    CP_COMMIT();
    asm volatile("cp.async.wait_group 0;" ::: "memory");
    __syncthreads();

    uint32_t qfr[4][4];
    {
        uint32_t qbase = sm0 + (uint32_t)(w * 16 + (lane & 15)) * ASTR + (uint32_t)((lane >> 4) << 4);
#pragma unroll
        for (int ks = 0; ks < 4; ks++) ldsm4(qfr[ks], qbase + ks * 32);
    }
    int gid = lane >> 2, tig = lane & 3;
    int r0 = q0 + w * 16 + gid, r1 = r0 + 8;
    float qb0 = qb[(tokb + r0) * NHEAD + h] * inv_t;
    float qb1 = qb[(tokb + r1) * NHEAD + h] * inv_t;
    __syncthreads();

    a_load_chunk(sm0, 0, tokb, h, tid, Kf, Vf, kb);
    CP_COMMIT();
    a_load_chunk(sm0, 1, tokb, h, tid, Kf, Vf, kb);
    CP_COMMIT();

    float O[8][4];
#pragma unroll
    for (int f = 0; f < 8; f++)
#pragma unroll
        for (int c = 0; c < 4; c++) O[f][c] = 0.0f;
    float m0 = -1e30f, m1 = -1e30f, z0 = 0.0f, z1 = 0.0f, t0 = 0.0f, t1 = 0.0f;

    const int NCH = L_ / 64;
    for (int ci = 0; ci < NCH; ci++) {
        if (ci < NCH - 2)
            asm volatile("cp.async.wait_group 1;" ::: "memory");
        else
            asm volatile("cp.async.wait_group 0;" ::: "memory");
        __syncthreads();

        uint32_t st = sm0 + (uint32_t)(ci & 1) * ASTAGE;
        uint32_t kbh = st + (uint32_t)(lane & 15) * ASTR + (uint32_t)((lane >> 4) << 4);

        float S[8][4];
#pragma unroll
        for (int f = 0; f < 8; f++)
#pragma unroll
            for (int c = 0; c < 4; c++) S[f][c] = 0.0f;

#pragma unroll
        for (int ks = 0; ks < 4; ks++) {
            uint32_t koff = (uint32_t)ks * 32;
#pragma unroll
            for (int nt = 0; nt < 4; nt++) {
                uint32_t bb[4];
                ldsm4(bb, kbh + (uint32_t)(nt * 16) * ASTR + koff);
                mma16816(S[nt * 2],     qfr[ks], bb[0], bb[2]);
                mma16816(S[nt * 2 + 1], qfr[ks], bb[1], bb[3]);
            }
        }

        const float* kbs = (const float*)(smemv + (size_t)((ci & 1) * ASTAGE + 2 * ATILE));
        float mx0 = -1e30f, mx1 = -1e30f;
#pragma unroll
        for (int f = 0; f < 8; f++) {
            float kc0 = kbs[f * 8 + 2 * tig] * inv_t;
            float kc1 = kbs[f * 8 + 2 * tig + 1] * inv_t;
            S[f][0] = S[f][0] * sc + qb0 + kc0;
            S[f][1] = S[f][1] * sc + qb0 + kc1;
            S[f][2] = S[f][2] * sc + qb1 + kc0;
            S[f][3] = S[f][3] * sc + qb1 + kc1;
            mx0 = fmaxf(mx0, fmaxf(S[f][0], S[f][1]));
            mx1 = fmaxf(mx1, fmaxf(S[f][2], S[f][3]));
        }
        mx0 = fmaxf(mx0, __shfl_xor_sync(0xffffffffu, mx0, 1));
        mx0 = fmaxf(mx0, __shfl_xor_sync(0xffffffffu, mx0, 2));
        mx1 = fmaxf(mx1, __shfl_xor_sync(0xffffffffu, mx1, 1));
        mx1 = fmaxf(mx1, __shfl_xor_sync(0xffffffffu, mx1, 2));

        float nm0 = fmaxf(m0, mx0), nm1 = fmaxf(m1, mx1);
        float sc0 = __expf(m0 - nm0), sc1 = __expf(m1 - nm1);
        float zc0 = 0.0f, zc1 = 0.0f, tc0 = 0.0f, tc1 = 0.0f;
        uint32_t pa[4][4];
#pragma unroll
        for (int j = 0; j < 4; j++) {
#pragma unroll
            for (int g = 0; g < 2; g++) {
                int f = 2 * j + g;
                float p0 = __expf(S[f][0] - nm0);
                float p1 = __expf(S[f][1] - nm0);
                float p2 = __expf(S[f][2] - nm1);
                float p3 = __expf(S[f][3] - nm1);
                zc0 += p0 + p1; zc1 += p2 + p3;
                tc0 += p0 * S[f][0] + p1 * S[f][1];
                tc1 += p2 * S[f][2] + p3 * S[f][3];
                pa[j][g * 2]     = packh(p0, p1);
                pa[j][g * 2 + 1] = packh(p2, p3);
            }
        }
        zc0 += __shfl_xor_sync(0xffffffffu, zc0, 1); zc0 += __shfl_xor_sync(0xffffffffu, zc0, 2);
        zc1 += __shfl_xor_sync(0xffffffffu, zc1, 1); zc1 += __shfl_xor_sync(0xffffffffu, zc1, 2);
        tc0 += __shfl_xor_sync(0xffffffffu, tc0, 1); tc0 += __shfl_xor_sync(0xffffffffu, tc0, 2);
        tc1 += __shfl_xor_sync(0xffffffffu, tc1, 1); tc1 += __shfl_xor_sync(0xffffffffu, tc1, 2);
        z0 = z0 * sc0 + zc0; t0 = t0 * sc0 + tc0; m0 = nm0;
        z1 = z1 * sc1 + zc1; t1 = t1 * sc1 + tc1; m1 = nm1;
#pragma unroll
        for (int f = 0; f < 8; f++) {
            O[f][0] *= sc0; O[f][1] *= sc0; O[f][2] *= sc1; O[f][3] *= sc1;
        }

        uint32_t vb = st + ATILE + (uint32_t)(lane & 15) * ASTR + (uint32_t)((lane >> 4) << 4);
#pragma unroll
        for (int j = 0; j < 4; j++) {
            uint32_t vrow = vb + (uint32_t)(j * 16) * ASTR;
#pragma unroll
            for (int hg = 0; hg < 4; hg++) {
                uint32_t v[4];
                ldsm4t(v, vrow + (uint32_t)hg * 32);
                mma16816(O[hg * 2],     pa[j], v[0], v[1]);
                mma16816(O[hg * 2 + 1], pa[j], v[2], v[3]);
            }
        }
        __syncthreads();
        if (ci + 2 < NCH) {
            a_load_chunk(sm0, ci + 2, tokb, h, tid, Kf, Vf, kb);
            CP_COMMIT();
        }
    }

    float iz0 = 1.0f / z0, iz1 = 1.0f / z1;
    size_t row0b = (tokb + r0) * D_MODEL, row1b = (tokb + r1) * D_MODEL;
#pragma unroll
    for (int f = 0; f < 8; f++) {
        int col = h * HEAD_DIM + f * 8 + 2 * tig;
        *(__half2*)(Of + row0b + col) = __floats2half2_rn(O[f][0] * iz0, O[f][1] * iz0);
        *(__half2*)(Of + row1b + col) = __floats2half2_rn(O[f][2] * iz1, O[f][3] * iz1);
    }

    float Hv = (m0 + logf(z0) - t0 / z0 + m1 + logf(z1) - t1 / z1) * 0.25f;
#pragma unroll
    for (int off = 16; off; off >>= 1) Hv += __shfl_xor_sync(0xffffffffu, Hv, off);
    if (lane == 0) red[w] = Hv;
    __syncthreads();
    if (tid == 0) {
        float s = 0.0f;
#pragma unroll
        for (int i = 0; i < 8; i++) s += red[i];
        ent_part[((b * NHEAD + h) << 4) + blockIdx.x] = s;
    }
}

// ======================= weight transpose (fp16) ============================
__global__ void __launch_bounds__(256) convT_kernel(
    const float* __restrict__ W, __half* __restrict__ o16, int K, int N)
{
    __shared__ float t[32][33];
    int n0 = blockIdx.x * 32, k0 = blockIdx.y * 32;
    int tx = threadIdx.x & 31, ty = threadIdx.x >> 5;
#pragma unroll
    for (int i = 0; i < 32; i += 8)
        t[ty + i][tx] = W[(size_t)(k0 + ty + i) * N + n0 + tx];
    __syncthreads();
#pragma unroll
    for (int i = 0; i < 32; i += 8)
        o16[(size_t)(n0 + ty + i) * K + k0 + tx] = __float2half_rn(t[tx][ty + i]);
}

__global__ void __launch_bounds__(256) conv_kernel(
    const float* __restrict__ in, __half* __restrict__ outp, int n4)
{
    int i = blockIdx.x * 256 + threadIdx.x;
    if (i >= n4) return;
    float4 v = ((const float4*)in)[i];
    ((__half2*)outp)[i * 2]     = __floats2half2_rn(v.x, v.y);
    ((__half2*)outp)[i * 2 + 1] = __floats2half2_rn(v.z, v.w);
}

// ---------------- POS bias MLPs ----------------------------------------------
__global__ void __launch_bounds__(128) posbias_kernel(
    const float* __restrict__ pos,
    const float* __restrict__ qw1, const float* __restrict__ qb1,
    const float* __restrict__ qw2, const float* __restrict__ qb2,
    const float* __restrict__ kw1, const float* __restrict__ kb1,
    const float* __restrict__ kw2, const float* __restrict__ kb2,
    float* __restrict__ qbias, float* __restrict__ kbias)
{
    __shared__ float sw1q[32 * 32], sw2q[32 * 16], sb1q[32], sb2q[16];
    __shared__ float sw1k[32 * 32], sw2k[32 * 16], sb1k[32], sb2k[16];
    int tid = threadIdx.x;
    for (int i = tid; i < 1024; i += 128) { sw1q[i] = qw1[i]; sw1k[i] = kw1[i]; }
    for (int i = tid; i < 512;  i += 128) { sw2q[i] = qw2[i]; sw2k[i] = kw2[i]; }
    if (tid < 32) { sb1q[tid] = qb1[tid]; sb1k[tid] = kb1[tid]; }
    if (tid < 16) { sb2q[tid] = qb2[tid]; sb2k[tid] = kb2[tid]; }
    __syncthreads();

    int token = blockIdx.x * 128 + tid;
    float pf[32];
#pragma unroll
    for (int i = 0; i < 32; i++) pf[i] = pos[(size_t)token * 32 + i];

    float hq[32], hk[32];
#pragma unroll
    for (int j = 0; j < 32; j++) { hq[j] = sb1q[j]; hk[j] = sb1k[j]; }
    for (int i = 0; i < 32; i++) {
        float p = pf[i];
#pragma unroll
        for (int j = 0; j < 32; j++) {
            hq[j] += p * sw1q[i * 32 + j];
            hk[j] += p * sw1k[i * 32 + j];
        }
    }
#pragma unroll
    for (int j = 0; j < 32; j++) {
        hq[j] = fmaxf(hq[j], 0.0f);
        hk[j] = fmaxf(hk[j], 0.0f);
    }
#pragma unroll
    for (int h = 0; h < 16; h++) {
        float oq = sb2q[h], ok = sb2k[h];
        for (int j = 0; j < 32; j++) {
            oq += hq[j] * sw2q[j * 16 + h];
            ok += hk[j] * sw2k[j * 16 + h];
        }
        qbias[(size_t)token * NHEAD + h] = oq;
        kbias[(size_t)token * NHEAD + h] = ok;
    }
}

// ---------------- layernorm (optionally emits fp16) --------------------------
template <int SPLIT>
__global__ void __launch_bounds__(256) ln_kernel(
    const float* __restrict__ in, const float* __restrict__ gam,
    const float* __restrict__ bet, float* __restrict__ out,
    __half* __restrict__ of)
{
    int row = blockIdx.x, tid = threadIdx.x;
    float4 v = ((const float4*)(in + (size_t)row * D_MODEL))[tid];
    float s = v.x + v.y + v.z + v.w;
    float q = v.x * v.x + v.y * v.y + v.z * v.z + v.w * v.w;
#pragma unroll
    for (int off = 16; off; off >>= 1) {
        s += __shfl_xor_sync(0xffffffffu, s, off);
        q += __shfl_xor_sync(0xffffffffu, q, off);
    }
    __shared__ float ws[8], wq[8], stats[2];
    int lane = tid & 31, w = tid >> 5;
    if (lane == 0) { ws[w] = s; wq[w] = q; }
    __syncthreads();
    if (tid == 0) {
        float S = 0.0f, Qq = 0.0f;
        for (int i = 0; i < 8; i++) { S += ws[i]; Qq += wq[i]; }
        float mu  = S * (1.0f / D_MODEL);
        float var = Qq * (1.0f / D_MODEL) - mu * mu;
        stats[0] = mu;
        stats[1] = rsqrtf(var + 1e-5f);
    }
    __syncthreads();
    float mu = stats[0], rs = stats[1];
    float4 gv = ((const float4*)gam)[tid];
    float4 bv = ((const float4*)bet)[tid];
    float4 ov;
    ov.x = (v.x - mu) * rs * gv.x + bv.x;
    ov.y = (v.y - mu) * rs * gv.y + bv.y;
    ov.z = (v.z - mu) * rs * gv.z + bv.z;
    ov.w = (v.w - mu) * rs * gv.w + bv.w;
    ((float4*)(out + (size_t)row * D_MODEL))[tid] = ov;
    if (SPLIT) {
        size_t base = (size_t)row * D_MODEL + tid * 4;
        *(__half2*)(of + base)     = __floats2half2_rn(ov.x, ov.y);
        *(__half2*)(of + base + 2) = __floats2half2_rn(ov.z, ov.w);
    }
}

// ---------------- deterministic entropy reduction ----------------------------
__global__ void __launch_bounds__(256) ent_final_kernel(
    const float* __restrict__ part, float* __restrict__ out, int out_size)
{
    __shared__ float sm[256];
    int tid = threadIdx.x;
    sm[tid] = part[tid] + part[tid + 256];
    __syncthreads();
    for (int off = 128; off; off >>= 1) {
        if (tid < off) sm[tid] += sm[tid + off];
        __syncthreads();
    }
    if (tid == 0 && out_size > OUT_MAIN)
        out[OUT_MAIN] = sm[0] * (1.0f / (B_ * NHEAD * L_));
}

// ---------------- launch -----------------------------------------------------
extern "C" void kernel_launch(void* const* d_in, const int* in_sizes, int n_in,
                              void* d_out, int out_size)
{
    const float* src   = (const float*)d_in[0];
    const float* pos   = (const float*)d_in[1];
    const float* Wq    = (const float*)d_in[2];
    const float* bq    = (const float*)d_in[3];
    const float* Wk    = (const float*)d_in[4];
    const float* bk    = (const float*)d_in[5];
    const float* Wv    = (const float*)d_in[6];
    const float* bv    = (const float*)d_in[7];
    const float* Wo    = (const float*)d_in[8];
    const float* bo    = (const float*)d_in[9];
    const float* pq_w1 = (const float*)d_in[10];
    const float* pq_b1 = (const float*)d_in[11];
    const float* pq_w2 = (const float*)d_in[12];
    const float* pq_b2 = (const float*)d_in[13];
    const float* pk_w1 = (const float*)d_in[14];
    const float* pk_b1 = (const float*)d_in[15];
    const float* pk_w2 = (const float*)d_in[16];
    const float* pk_b2 = (const float*)d_in[17];
    const float* temp  = (const float*)d_in[18];
    const float* ln1g  = (const float*)d_in[19];
    const float* ln1b  = (const float*)d_in[20];
    const float* ln2g  = (const float*)d_in[21];
    const float* ln2b  = (const float*)d_in[22];
    const float* W1    = (const float*)d_in[23];
    const float* b1    = (const float*)d_in[24];
    const float* W2    = (const float*)d_in[25];
    const float* b2    = (const float*)d_in[26];
    float* out = (float*)d_out;

    float *xb, *yb, *qbb, *kbb, *entp;
    cudaGetSymbolAddress((void**)&xb, g_x);
    cudaGetSymbolAddress((void**)&yb, g_y);
    cudaGetSymbolAddress((void**)&qbb, g_qbias);
    cudaGetSymbolAddress((void**)&kbb, g_kbias);
    cudaGetSymbolAddress((void**)&entp, g_entpart);

    __half *srcf, *qf, *kf, *vf, *atf, *xf, *fff;
    __half *wq16, *wk16, *wv16, *wo16, *w116, *w216;
    cudaGetSymbolAddress((void**)&srcf, g_src_f);
    cudaGetSymbolAddress((void**)&qf, g_q_f);
    cudaGetSymbolAddress((void**)&kf, g_k_f);
    cudaGetSymbolAddress((void**)&vf, g_v_f);
    cudaGetSymbolAddress((void**)&atf, g_at_f);
    cudaGetSymbolAddress((void**)&xf, g_x_f);
    cudaGetSymbolAddress((void**)&fff, g_ff_f);
    cudaGetSymbolAddress((void**)&wq16, g_wq);
    cudaGetSymbolAddress((void**)&wk16, g_wk);
    cudaGetSymbolAddress((void**)&wv16, g_wv);
    cudaGetSymbolAddress((void**)&wo16, g_wo);
    cudaGetSymbolAddress((void**)&w116, g_w1);
    cudaGetSymbolAddress((void**)&w216, g_w2);

    cudaFuncSetAttribute(tcgemm_kernel<1>, cudaFuncAttributeMaxDynamicSharedMemorySize, GEMM_SMEM);
    cudaFuncSetAttribute(tcgemm_kernel<2>, cudaFuncAttributeMaxDynamicSharedMemorySize, GEMM_SMEM);
    cudaFuncSetAttribute(tcgemm_kernel<3>, cudaFuncAttributeMaxDynamicSharedMemorySize, GEMM_SMEM);
    cudaFuncSetAttribute(attn_mma_kernel, cudaFuncAttributeMaxDynamicSharedMemorySize, ASMEM);

    dim3 ct(32, 32);
    convT_kernel<<<ct, 256>>>(Wq, wq16, D_MODEL, D_MODEL);
    convT_kernel<<<ct, 256>>>(Wk, wk16, D_MODEL, D_MODEL);
    convT_kernel<<<ct, 256>>>(Wv, wv16, D_MODEL, D_MODEL);
    convT_kernel<<<ct, 256>>>(Wo, wo16, D_MODEL, D_MODEL);
    convT_kernel<<<dim3(D_FF / 32, D_MODEL / 32), 256>>>(W1, w116, D_MODEL, D_FF);
    convT_kernel<<<dim3(D_MODEL / 32, D_FF / 32), 256>>>(W2, w216, D_FF, D_MODEL);

    conv_kernel<<<(M_TOK * D_MODEL / 4 + 255) / 256, 256>>>(src, srcf, M_TOK * D_MODEL / 4);
    posbias_kernel<<<M_TOK / 128, 128>>>(pos, pq_w1, pq_b1, pq_w2, pq_b2,
                                         pk_w1, pk_b1, pk_w2, pk_b2, qbb, kbb);

    // QKV projections -> fp16
    dim3 gD(D_MODEL / BN, M_TOK / BM);
    tcgemm_kernel<3><<<gD, 256, GEMM_SMEM>>>(srcf, wq16, bq, (const float*)0,
                                             (float*)0, qf, M_TOK, D_MODEL, D_MODEL);
    tcgemm_kernel<3><<<gD, 256, GEMM_SMEM>>>(srcf, wk16, bk, (const float*)0,
                                             (float*)0, kf, M_TOK, D_MODEL, D_MODEL);
    tcgemm_kernel<3><<<gD, 256, GEMM_SMEM>>>(srcf, wv16, bv, (const float*)0,
                                             (float*)0, vf, M_TOK, D_MODEL, D_MODEL);

    attn_mma_kernel<<<dim3(L_ / 128, NHEAD, B_), 256, ASMEM>>>(
        qf, kf, vf, qbb, kbb, temp, atf, entp);

    tcgemm_kernel<2><<<gD, 256, GEMM_SMEM>>>(atf, wo16, bo, src,
                                             yb, (__half*)0, M_TOK, D_MODEL, D_MODEL);
    ln_kernel<1><<<M_TOK, 256>>>(yb, ln1g, ln1b, xb, xf);

    dim3 gF(D_FF / BN, M_TOK / BM);
    tcgemm_kernel<1><<<gF, 256, GEMM_SMEM>>>(xf, w116, b1, (const float*)0,
                                             (float*)0, fff, M_TOK, D_FF, D_MODEL);
    tcgemm_kernel<2><<<gD, 256, GEMM_SMEM>>>(fff, w216, b2, xb,
                                             yb, (__half*)0, M_TOK, D_MODEL, D_FF);
    ln_kernel<0><<<M_TOK, 256>>>(yb, ln2g, ln2b, out, (__half*)0);

    ent_final_kernel<<<1, 256>>>(entp, out, out_size);
}

// round 9
// speedup vs baseline: 6.3778x; 1.0178x over previous
#include <cuda_runtime.h>
#include <cuda_fp16.h>
#include <math.h>
#include <stdint.h>
#include <string.h>

#define D_MODEL 1024
#define NHEAD 16
#define HEAD_DIM 64
#define B_ 2
#define L_ 2048
#define M_TOK 4096
#define D_FF 4096
#define OUT_MAIN (M_TOK * D_MODEL)

// ---------------- scratch (device globals; no allocations allowed) ----------
__device__ float g_x[M_TOK * D_MODEL];
__device__ float g_y[M_TOK * D_MODEL];
__device__ float g_qbias[M_TOK * NHEAD];
__device__ float g_kbias[M_TOK * NHEAD];
__device__ float g_entpart[1024];
// fp16 activations
__device__ __half g_src_f[M_TOK * D_MODEL];
__device__ __half g_q_f[M_TOK * D_MODEL];
__device__ __half g_k_f[M_TOK * D_MODEL];
__device__ __half g_v_f[M_TOK * D_MODEL];
__device__ __half g_at_f[M_TOK * D_MODEL];
__device__ __half g_x_f[M_TOK * D_MODEL];
__device__ __half g_ff_f[M_TOK * D_FF];
// fp16 transposed weights [N, K]  (wq,wk,wv,wo packed contiguously)
__device__ __half g_w4[4 * D_MODEL * D_MODEL];
__device__ __half g_w1[D_FF * D_MODEL];
__device__ __half g_w2[D_MODEL * D_FF];

// ======================= PTX helpers (baseline sm_103-legal only) ===========
__device__ __forceinline__ uint32_t smem_u32(const void* p) {
    uint32_t a;
    asm("{ .reg .u64 t; cvta.to.shared.u64 t, %1; cvt.u32.u64 %0, t; }" : "=r"(a) : "l"(p));
    return a;
}
__device__ __forceinline__ void cp16(uint32_t s, const void* g) {
    asm volatile("cp.async.cg.shared.global [%0], [%1], 16;" :: "r"(s), "l"(g));
}
__device__ __forceinline__ void cp4(uint32_t s, const void* g) {
    asm volatile("cp.async.ca.shared.global [%0], [%1], 4;" :: "r"(s), "l"(g));
}
#define CP_COMMIT() asm volatile("cp.async.commit_group;" ::: "memory")

__device__ __forceinline__ void ldsm4(uint32_t* r, uint32_t addr) {
    asm volatile("ldmatrix.sync.aligned.m8n8.x4.shared.b16 {%0,%1,%2,%3}, [%4];"
                 : "=r"(r[0]), "=r"(r[1]), "=r"(r[2]), "=r"(r[3]) : "r"(addr));
}
__device__ __forceinline__ void ldsm4t(uint32_t* r, uint32_t addr) {
    asm volatile("ldmatrix.sync.aligned.m8n8.x4.trans.shared.b16 {%0,%1,%2,%3}, [%4];"
                 : "=r"(r[0]), "=r"(r[1]), "=r"(r[2]), "=r"(r[3]) : "r"(addr));
}
__device__ __forceinline__ void mma16816(float* d, const uint32_t* a, uint32_t b0, uint32_t b1) {
    asm volatile(
        "mma.sync.aligned.m16n8k16.row.col.f32.f16.f16.f32 "
        "{%0,%1,%2,%3}, {%4,%5,%6,%7}, {%8,%9}, {%0,%1,%2,%3};"
        : "+f"(d[0]), "+f"(d[1]), "+f"(d[2]), "+f"(d[3])
        : "r"(a[0]), "r"(a[1]), "r"(a[2]), "r"(a[3]), "r"(b0), "r"(b1));
}
__device__ __forceinline__ uint32_t packh(float a, float b) {
    __half2 t = __floats2half2_rn(a, b);
    uint32_t u; memcpy(&u, &t, 4); return u;
}

// ======================= warp-MMA fp16 GEMM (single precision pass) =========
// MODE 0: fp32 +bias  MODE 1: gelu(+bias)->fp16  MODE 2: fp32 +bias+res
// MODE 3: +bias -> fp16
#define BM 128
#define BN 128
#define BKC 32
#define RSTR 80
#define TILE_B (128 * RSTR)
#define STAGE_B (2 * TILE_B)
#define NSTAGE 3
#define GEMM_SMEM (NSTAGE * STAGE_B)

__device__ __forceinline__ void g_load_chunk(
    uint32_t smem, int ci, int m0, int n0, int K, int tid,
    const __half* __restrict__ A, const __half* __restrict__ W)
{
    uint32_t sb = smem + (uint32_t)(ci % NSTAGE) * STAGE_B;
    size_t kbase = (size_t)ci * BKC;
#pragma unroll
    for (int t = 0; t < 2; t++) {
        const __half* P = (t == 0) ? A : W;
        int r0 = (t == 0) ? m0 : n0;
        uint32_t tb = sb + (uint32_t)t * TILE_B;
#pragma unroll
        for (int rep = 0; rep < 2; rep++) {
            int seg = tid + (rep << 8);
            int row = seg >> 2;
            int s4  = seg & 3;
            cp16(tb + (uint32_t)row * RSTR + (uint32_t)s4 * 16,
                 P + (size_t)(r0 + row) * K + kbase + s4 * 8);
        }
    }
}

template <int MODE>
__global__ void __launch_bounds__(256, 2) tcgemm_kernel(
    const __half* __restrict__ A, const __half* __restrict__ W,
    const float* __restrict__ bias, const float* __restrict__ res,
    float* __restrict__ C, __half* __restrict__ Cf,
    int M, int N, int K)
{
    extern __shared__ char dsm[];
    uint32_t smem = smem_u32(dsm);

    int tid = threadIdx.x;
    int wid = tid >> 5;
    int lane = tid & 31;
    int m0 = blockIdx.y * BM;
    int n0 = blockIdx.x * BN;
    int nchunk = K / BKC;

    int wm = wid & 1;
    int wn = wid >> 1;
    int lr = lane & 15;
    uint32_t lk = (uint32_t)((lane >> 4) << 4);

    float acc[4][4][4];
#pragma unroll
    for (int i = 0; i < 4; i++)
#pragma unroll
        for (int j = 0; j < 4; j++)
#pragma unroll
            for (int c = 0; c < 4; c++) acc[i][j][c] = 0.0f;

    g_load_chunk(smem, 0, m0, n0, K, tid, A, W);
    CP_COMMIT();
    g_load_chunk(smem, 1, m0, n0, K, tid, A, W);
    CP_COMMIT();

    for (int i = 0; i < nchunk; i++) {
        if (i < nchunk - 1)
            asm volatile("cp.async.wait_group 1;" ::: "memory");
        else
            asm volatile("cp.async.wait_group 0;" ::: "memory");
        __syncthreads();

        if (i + 2 < nchunk) {
            g_load_chunk(smem, i + 2, m0, n0, K, tid, A, W);
            CP_COMMIT();
        }

        uint32_t sb = smem + (uint32_t)(i % NSTAGE) * STAGE_B;
        uint32_t aBase = sb + (uint32_t)(wm * 64 + lr) * RSTR + lk;
        uint32_t bBase = sb + TILE_B + (uint32_t)(wn * 32 + lr) * RSTR + lk;

#pragma unroll
        for (int ks = 0; ks < 2; ks++) {
            uint32_t koff = (uint32_t)ks * 32;
            uint32_t ah[4][4];
#pragma unroll
            for (int mt = 0; mt < 4; mt++)
                ldsm4(ah[mt], aBase + (uint32_t)(mt * 16) * RSTR + koff);
#pragma unroll
            for (int nt = 0; nt < 2; nt++) {
                uint32_t bb[4];
                ldsm4(bb, bBase + (uint32_t)(nt * 16) * RSTR + koff);
#pragma unroll
                for (int mt = 0; mt < 4; mt++) {
                    mma16816(acc[mt][nt * 2],     ah[mt], bb[0], bb[2]);
                    mma16816(acc[mt][nt * 2 + 1], ah[mt], bb[1], bb[3]);
                }
            }
        }
    }

    int rbase = m0 + wm * 64 + (lane >> 2);
    int cbase = n0 + wn * 32 + (lane & 3) * 2;
#pragma unroll
    for (int mt = 0; mt < 4; mt++) {
#pragma unroll
        for (int n8 = 0; n8 < 4; n8++) {
            int col = cbase + n8 * 8;
            float b0 = bias[col], b1 = bias[col + 1];
#pragma unroll
            for (int half = 0; half < 2; half++) {
                int row = rbase + mt * 16 + half * 8;
                float v0 = acc[mt][n8][half * 2] + b0;
                float v1 = acc[mt][n8][half * 2 + 1] + b1;
                if (MODE == 1) {
                    v0 = 0.5f * v0 * (1.0f + erff(v0 * 0.70710678118654752f));
                    v1 = 0.5f * v1 * (1.0f + erff(v1 * 0.70710678118654752f));
                }
                if (MODE == 2) {
                    const float2 rv = *(const float2*)(res + (size_t)row * N + col);
                    v0 += rv.x; v1 += rv.y;
                }
                if (MODE == 0 || MODE == 2) {
                    float2 o; o.x = v0; o.y = v1;
                    *(float2*)(C + (size_t)row * N + col) = o;
                } else {
                    *(__half2*)(Cf + (size_t)row * N + col) = __floats2half2_rn(v0, v1);
                }
            }
        }
    }
}

// ======================= MMA flash attention (fp16, occ 2) ==================
#define ASTR 144
#define ATILE (64 * ASTR)
#define ASTAGE (2 * ATILE + 256)
#define ASMEM (2 * ASTAGE + 64)

__device__ __forceinline__ void a_load_chunk(
    uint32_t sm0, int ci, size_t tokb, int h, int tid,
    const __half* __restrict__ Kf, const __half* __restrict__ Vf,
    const float* __restrict__ kb)
{
    uint32_t st = sm0 + (uint32_t)(ci & 1) * ASTAGE;
    size_t rowb = tokb + (size_t)ci * 64;
#pragma unroll
    for (int r = 0; r < 4; r++) {
        int idx = tid + (r << 8);
        int t = idx >> 9;
        int row = (idx >> 3) & 63;
        int seg = idx & 7;
        const __half* P = (t == 0) ? Kf : Vf;
        cp16(st + (uint32_t)t * ATILE + (uint32_t)row * ASTR + (uint32_t)seg * 16,
             P + (rowb + row) * D_MODEL + h * HEAD_DIM + seg * 8);
    }
    if (tid < 64)
        cp4(st + 2u * ATILE + (uint32_t)tid * 4, kb + (rowb + tid) * NHEAD + h);
}

__global__ void __launch_bounds__(256, 2) attn_mma_kernel(
    const __half* __restrict__ Qf, const __half* __restrict__ Kf,
    const __half* __restrict__ Vf,
    const float* __restrict__ qb, const float* __restrict__ kb,
    const float* __restrict__ temp,
    __half* __restrict__ Of, float* __restrict__ ent_part)
{
    extern __shared__ char smemv[];
    uint32_t sm0 = smem_u32(smemv);
    float* red = (float*)(smemv + 2 * ASTAGE);

    int tid = threadIdx.x;
    int w = tid >> 5;
    int lane = tid & 31;
    int q0 = blockIdx.x * 128;
    int h = blockIdx.y;
    int b = blockIdx.z;
    size_t tokb = (size_t)b * L_;

    float tmph = fminf(fmaxf(temp[h], 0.1f), 5.0f);
    float inv_t = 1.0f / tmph;
    float sc = 0.125f * inv_t;

    for (int i = tid; i < 128 * 8; i += 256) {
        int row = i >> 3, seg = i & 7;
        cp16(sm0 + (uint32_t)row * ASTR + (uint32_t)seg * 16,
             Qf + (tokb + q0 + row) * D_MODEL + h * HEAD_DIM + seg * 8);
    }
    CP_COMMIT();
    asm volatile("cp.async.wait_group 0;" ::: "memory");
    __syncthreads();

    uint32_t qfr[4][4];
    {
        uint32_t qbase = sm0 + (uint32_t)(w * 16 + (lane & 15)) * ASTR + (uint32_t)((lane >> 4) << 4);
#pragma unroll
        for (int ks = 0; ks < 4; ks++) ldsm4(qfr[ks], qbase + ks * 32);
    }
    int gid = lane >> 2, tig = lane & 3;
    int r0 = q0 + w * 16 + gid, r1 = r0 + 8;
    float qb0 = qb[(tokb + r0) * NHEAD + h] * inv_t;
    float qb1 = qb[(tokb + r1) * NHEAD + h] * inv_t;
    __syncthreads();

    a_load_chunk(sm0, 0, tokb, h, tid, Kf, Vf, kb);
    CP_COMMIT();
    a_load_chunk(sm0, 1, tokb, h, tid, Kf, Vf, kb);
    CP_COMMIT();

    float O[8][4];
#pragma unroll
    for (int f = 0; f < 8; f++)
#pragma unroll
        for (int c = 0; c < 4; c++) O[f][c] = 0.0f;
    float m0 = -1e30f, m1 = -1e30f, z0 = 0.0f, z1 = 0.0f, t0 = 0.0f, t1 = 0.0f;

    const int NCH = L_ / 64;
    for (int ci = 0; ci < NCH; ci++) {
        if (ci < NCH - 2)
            asm volatile("cp.async.wait_group 1;" ::: "memory");
        else
            asm volatile("cp.async.wait_group 0;" ::: "memory");
        __syncthreads();

        uint32_t st = sm0 + (uint32_t)(ci & 1) * ASTAGE;
        uint32_t kbh = st + (uint32_t)(lane & 15) * ASTR + (uint32_t)((lane >> 4) << 4);

        float S[8][4];
#pragma unroll
        for (int f = 0; f < 8; f++)
#pragma unroll
            for (int c = 0; c < 4; c++) S[f][c] = 0.0f;

#pragma unroll
        for (int ks = 0; ks < 4; ks++) {
            uint32_t koff = (uint32_t)ks * 32;
#pragma unroll
            for (int nt = 0; nt < 4; nt++) {
                uint32_t bb[4];
                ldsm4(bb, kbh + (uint32_t)(nt * 16) * ASTR + koff);
                mma16816(S[nt * 2],     qfr[ks], bb[0], bb[2]);
                mma16816(S[nt * 2 + 1], qfr[ks], bb[1], bb[3]);
            }
        }

        const float* kbs = (const float*)(smemv + (size_t)((ci & 1) * ASTAGE + 2 * ATILE));
        float mx0 = -1e30f, mx1 = -1e30f;
#pragma unroll
        for (int f = 0; f < 8; f++) {
            float kc0 = kbs[f * 8 + 2 * tig] * inv_t;
            float kc1 = kbs[f * 8 + 2 * tig + 1] * inv_t;
            S[f][0] = S[f][0] * sc + qb0 + kc0;
            S[f][1] = S[f][1] * sc + qb0 + kc1;
            S[f][2] = S[f][2] * sc + qb1 + kc0;
            S[f][3] = S[f][3] * sc + qb1 + kc1;
            mx0 = fmaxf(mx0, fmaxf(S[f][0], S[f][1]));
            mx1 = fmaxf(mx1, fmaxf(S[f][2], S[f][3]));
        }
        mx0 = fmaxf(mx0, __shfl_xor_sync(0xffffffffu, mx0, 1));
        mx0 = fmaxf(mx0, __shfl_xor_sync(0xffffffffu, mx0, 2));
        mx1 = fmaxf(mx1, __shfl_xor_sync(0xffffffffu, mx1, 1));
        mx1 = fmaxf(mx1, __shfl_xor_sync(0xffffffffu, mx1, 2));

        float nm0 = fmaxf(m0, mx0), nm1 = fmaxf(m1, mx1);
        float sc0 = __expf(m0 - nm0), sc1 = __expf(m1 - nm1);
        float zc0 = 0.0f, zc1 = 0.0f, tc0 = 0.0f, tc1 = 0.0f;
        uint32_t pa[4][4];
#pragma unroll
        for (int j = 0; j < 4; j++) {
#pragma unroll
            for (int g = 0; g < 2; g++) {
                int f = 2 * j + g;
                float p0 = __expf(S[f][0] - nm0);
                float p1 = __expf(S[f][1] - nm0);
                float p2 = __expf(S[f][2] - nm1);
                float p3 = __expf(S[f][3] - nm1);
                zc0 += p0 + p1; zc1 += p2 + p3;
                tc0 += p0 * S[f][0] + p1 * S[f][1];
                tc1 += p2 * S[f][2] + p3 * S[f][3];
                pa[j][g * 2]     = packh(p0, p1);
                pa[j][g * 2 + 1] = packh(p2, p3);
            }
        }
        zc0 += __shfl_xor_sync(0xffffffffu, zc0, 1); zc0 += __shfl_xor_sync(0xffffffffu, zc0, 2);
        zc1 += __shfl_xor_sync(0xffffffffu, zc1, 1); zc1 += __shfl_xor_sync(0xffffffffu, zc1, 2);
        tc0 += __shfl_xor_sync(0xffffffffu, tc0, 1); tc0 += __shfl_xor_sync(0xffffffffu, tc0, 2);
        tc1 += __shfl_xor_sync(0xffffffffu, tc1, 1); tc1 += __shfl_xor_sync(0xffffffffu, tc1, 2);
        z0 = z0 * sc0 + zc0; t0 = t0 * sc0 + tc0; m0 = nm0;
        z1 = z1 * sc1 + zc1; t1 = t1 * sc1 + tc1; m1 = nm1;
#pragma unroll
        for (int f = 0; f < 8; f++) {
            O[f][0] *= sc0; O[f][1] *= sc0; O[f][2] *= sc1; O[f][3] *= sc1;
        }

        uint32_t vb = st + ATILE + (uint32_t)(lane & 15) * ASTR + (uint32_t)((lane >> 4) << 4);
#pragma unroll
        for (int j = 0; j < 4; j++) {
            uint32_t vrow = vb + (uint32_t)(j * 16) * ASTR;
#pragma unroll
            for (int hg = 0; hg < 4; hg++) {
                uint32_t v[4];
                ldsm4t(v, vrow + (uint32_t)hg * 32);
                mma16816(O[hg * 2],     pa[j], v[0], v[1]);
                mma16816(O[hg * 2 + 1], pa[j], v[2], v[3]);
            }
        }
        __syncthreads();
        if (ci + 2 < NCH) {
            a_load_chunk(sm0, ci + 2, tokb, h, tid, Kf, Vf, kb);
            CP_COMMIT();
        }
    }

    float iz0 = 1.0f / z0, iz1 = 1.0f / z1;
    size_t row0b = (tokb + r0) * D_MODEL, row1b = (tokb + r1) * D_MODEL;
#pragma unroll
    for (int f = 0; f < 8; f++) {
        int col = h * HEAD_DIM + f * 8 + 2 * tig;
        *(__half2*)(Of + row0b + col) = __floats2half2_rn(O[f][0] * iz0, O[f][1] * iz0);
        *(__half2*)(Of + row1b + col) = __floats2half2_rn(O[f][2] * iz1, O[f][3] * iz1);
    }

    float Hv = (m0 + logf(z0) - t0 / z0 + m1 + logf(z1) - t1 / z1) * 0.25f;
#pragma unroll
    for (int off = 16; off; off >>= 1) Hv += __shfl_xor_sync(0xffffffffu, Hv, off);
    if (lane == 0) red[w] = Hv;
    __syncthreads();
    if (tid == 0) {
        float s = 0.0f;
#pragma unroll
        for (int i = 0; i < 8; i++) s += red[i];
        ent_part[((b * NHEAD + h) << 4) + blockIdx.x] = s;
    }
}

// ======================= weight transpose (fp16) ============================
// batched over blockIdx.z: 4 D_MODELxD_MODEL weights -> packed g_w4
__global__ void __launch_bounds__(256) convT4_kernel(
    const float* __restrict__ W0, const float* __restrict__ W1p,
    const float* __restrict__ W2p, const float* __restrict__ W3,
    __half* __restrict__ o16)
{
    __shared__ float t[32][33];
    const float* W = (blockIdx.z == 0) ? W0 : (blockIdx.z == 1) ? W1p
                   : (blockIdx.z == 2) ? W2p : W3;
    __half* dst = o16 + (size_t)blockIdx.z * D_MODEL * D_MODEL;
    int n0 = blockIdx.x * 32, k0 = blockIdx.y * 32;
    int tx = threadIdx.x & 31, ty = threadIdx.x >> 5;
#pragma unroll
    for (int i = 0; i < 32; i += 8)
        t[ty + i][tx] = W[(size_t)(k0 + ty + i) * D_MODEL + n0 + tx];
    __syncthreads();
#pragma unroll
    for (int i = 0; i < 32; i += 8)
        dst[(size_t)(n0 + ty + i) * D_MODEL + k0 + tx] = __float2half_rn(t[tx][ty + i]);
}

__global__ void __launch_bounds__(256) convT_kernel(
    const float* __restrict__ W, __half* __restrict__ o16, int K, int N)
{
    __shared__ float t[32][33];
    int n0 = blockIdx.x * 32, k0 = blockIdx.y * 32;
    int tx = threadIdx.x & 31, ty = threadIdx.x >> 5;
#pragma unroll
    for (int i = 0; i < 32; i += 8)
        t[ty + i][tx] = W[(size_t)(k0 + ty + i) * N + n0 + tx];
    __syncthreads();
#pragma unroll
    for (int i = 0; i < 32; i += 8)
        o16[(size_t)(n0 + ty + i) * K + k0 + tx] = __float2half_rn(t[tx][ty + i]);
}

__global__ void __launch_bounds__(256) conv_kernel(
    const float* __restrict__ in, __half* __restrict__ outp, int n4)
{
    int i = blockIdx.x * 256 + threadIdx.x;
    if (i >= n4) return;
    float4 v = ((const float4*)in)[i];
    ((__half2*)outp)[i * 2]     = __floats2half2_rn(v.x, v.y);
    ((__half2*)outp)[i * 2 + 1] = __floats2half2_rn(v.z, v.w);
}

// ---------------- POS bias MLPs ----------------------------------------------
__global__ void __launch_bounds__(128) posbias_kernel(
    const float* __restrict__ pos,
    const float* __restrict__ qw1, const float* __restrict__ qb1,
    const float* __restrict__ qw2, const float* __restrict__ qb2,
    const float* __restrict__ kw1, const float* __restrict__ kb1,
    const float* __restrict__ kw2, const float* __restrict__ kb2,
    float* __restrict__ qbias, float* __restrict__ kbias)
{
    __shared__ float sw1q[32 * 32], sw2q[32 * 16], sb1q[32], sb2q[16];
    __shared__ float sw1k[32 * 32], sw2k[32 * 16], sb1k[32], sb2k[16];
    int tid = threadIdx.x;
    for (int i = tid; i < 1024; i += 128) { sw1q[i] = qw1[i]; sw1k[i] = kw1[i]; }
    for (int i = tid; i < 512;  i += 128) { sw2q[i] = qw2[i]; sw2k[i] = kw2[i]; }
    if (tid < 32) { sb1q[tid] = qb1[tid]; sb1k[tid] = kb1[tid]; }
    if (tid < 16) { sb2q[tid] = qb2[tid]; sb2k[tid] = kb2[tid]; }
    __syncthreads();

    int token = blockIdx.x * 128 + tid;
    float pf[32];
#pragma unroll
    for (int i = 0; i < 32; i++) pf[i] = pos[(size_t)token * 32 + i];

    float hq[32], hk[32];
#pragma unroll
    for (int j = 0; j < 32; j++) { hq[j] = sb1q[j]; hk[j] = sb1k[j]; }
    for (int i = 0; i < 32; i++) {
        float p = pf[i];
#pragma unroll
        for (int j = 0; j < 32; j++) {
            hq[j] += p * sw1q[i * 32 + j];
            hk[j] += p * sw1k[i * 32 + j];
        }
    }
#pragma unroll
    for (int j = 0; j < 32; j++) {
        hq[j] = fmaxf(hq[j], 0.0f);
        hk[j] = fmaxf(hk[j], 0.0f);
    }
#pragma unroll
    for (int h = 0; h < 16; h++) {
        float oq = sb2q[h], ok = sb2k[h];
        for (int j = 0; j < 32; j++) {
            oq += hq[j] * sw2q[j * 16 + h];
            ok += hk[j] * sw2k[j * 16 + h];
        }
        qbias[(size_t)token * NHEAD + h] = oq;
        kbias[(size_t)token * NHEAD + h] = ok;
    }
}

// ---------------- layernorm (optionally emits fp16) --------------------------
template <int SPLIT>
__global__ void __launch_bounds__(256) ln_kernel(
    const float* __restrict__ in, const float* __restrict__ gam,
    const float* __restrict__ bet, float* __restrict__ out,
    __half* __restrict__ of)
{
    int row = blockIdx.x, tid = threadIdx.x;
    float4 v = ((const float4*)(in + (size_t)row * D_MODEL))[tid];
    float s = v.x + v.y + v.z + v.w;
    float q = v.x * v.x + v.y * v.y + v.z * v.z + v.w * v.w;
#pragma unroll
    for (int off = 16; off; off >>= 1) {
        s += __shfl_xor_sync(0xffffffffu, s, off);
        q += __shfl_xor_sync(0xffffffffu, q, off);
    }
    __shared__ float ws[8], wq[8], stats[2];
    int lane = tid & 31, w = tid >> 5;
    if (lane == 0) { ws[w] = s; wq[w] = q; }
    __syncthreads();
    if (tid == 0) {
        float S = 0.0f, Qq = 0.0f;
        for (int i = 0; i < 8; i++) { S += ws[i]; Qq += wq[i]; }
        float mu  = S * (1.0f / D_MODEL);
        float var = Qq * (1.0f / D_MODEL) - mu * mu;
        stats[0] = mu;
        stats[1] = rsqrtf(var + 1e-5f);
    }
    __syncthreads();
    float mu = stats[0], rs = stats[1];
    float4 gv = ((const float4*)gam)[tid];
    float4 bv = ((const float4*)bet)[tid];
    float4 ov;
    ov.x = (v.x - mu) * rs * gv.x + bv.x;
    ov.y = (v.y - mu) * rs * gv.y + bv.y;
    ov.z = (v.z - mu) * rs * gv.z + bv.z;
    ov.w = (v.w - mu) * rs * gv.w + bv.w;
    ((float4*)(out + (size_t)row * D_MODEL))[tid] = ov;
    if (SPLIT) {
        size_t base = (size_t)row * D_MODEL + tid * 4;
        *(__half2*)(of + base)     = __floats2half2_rn(ov.x, ov.y);
        *(__half2*)(of + base + 2) = __floats2half2_rn(ov.z, ov.w);
    }
}

// ---------------- deterministic entropy reduction ----------------------------
__global__ void __launch_bounds__(256) ent_final_kernel(
    const float* __restrict__ part, float* __restrict__ out, int out_size)
{
    __shared__ float sm[256];
    int tid = threadIdx.x;
    sm[tid] = part[tid] + part[tid + 256];
    __syncthreads();
    for (int off = 128; off; off >>= 1) {
        if (tid < off) sm[tid] += sm[tid + off];
        __syncthreads();
    }
    if (tid == 0 && out_size > OUT_MAIN)
        out[OUT_MAIN] = sm[0] * (1.0f / (B_ * NHEAD * L_));
}

// ---------------- launch -----------------------------------------------------
extern "C" void kernel_launch(void* const* d_in, const int* in_sizes, int n_in,
                              void* d_out, int out_size)
{
    const float* src   = (const float*)d_in[0];
    const float* pos   = (const float*)d_in[1];
    const float* Wq    = (const float*)d_in[2];
    const float* bq    = (const float*)d_in[3];
    const float* Wk    = (const float*)d_in[4];
    const float* bk    = (const float*)d_in[5];
    const float* Wv    = (const float*)d_in[6];
    const float* bv    = (const float*)d_in[7];
    const float* Wo    = (const float*)d_in[8];
    const float* bo    = (const float*)d_in[9];
    const float* pq_w1 = (const float*)d_in[10];
    const float* pq_b1 = (const float*)d_in[11];
    const float* pq_w2 = (const float*)d_in[12];
    const float* pq_b2 = (const float*)d_in[13];
    const float* pk_w1 = (const float*)d_in[14];
    const float* pk_b1 = (const float*)d_in[15];
    const float* pk_w2 = (const float*)d_in[16];
    const float* pk_b2 = (const float*)d_in[17];
    const float* temp  = (const float*)d_in[18];
    const float* ln1g  = (const float*)d_in[19];
    const float* ln1b  = (const float*)d_in[20];
    const float* ln2g  = (const float*)d_in[21];
    const float* ln2b  = (const float*)d_in[22];
    const float* W1    = (const float*)d_in[23];
    const float* b1    = (const float*)d_in[24];
    const float* W2    = (const float*)d_in[25];
    const float* b2    = (const float*)d_in[26];
    float* out = (float*)d_out;

    float *xb, *yb, *qbb, *kbb, *entp;
    cudaGetSymbolAddress((void**)&xb, g_x);
    cudaGetSymbolAddress((void**)&yb, g_y);
    cudaGetSymbolAddress((void**)&qbb, g_qbias);
    cudaGetSymbolAddress((void**)&kbb, g_kbias);
    cudaGetSymbolAddress((void**)&entp, g_entpart);

    __half *srcf, *qf, *kf, *vf, *atf, *xf, *fff;
    __half *w4, *w116, *w216;
    cudaGetSymbolAddress((void**)&srcf, g_src_f);
    cudaGetSymbolAddress((void**)&qf, g_q_f);
    cudaGetSymbolAddress((void**)&kf, g_k_f);
    cudaGetSymbolAddress((void**)&vf, g_v_f);
    cudaGetSymbolAddress((void**)&atf, g_at_f);
    cudaGetSymbolAddress((void**)&xf, g_x_f);
    cudaGetSymbolAddress((void**)&fff, g_ff_f);
    cudaGetSymbolAddress((void**)&w4, g_w4);
    cudaGetSymbolAddress((void**)&w116, g_w1);
    cudaGetSymbolAddress((void**)&w216, g_w2);

    __half* wq16 = w4;
    __half* wk16 = w4 + (size_t)D_MODEL * D_MODEL;
    __half* wv16 = w4 + 2 * (size_t)D_MODEL * D_MODEL;
    __half* wo16 = w4 + 3 * (size_t)D_MODEL * D_MODEL;

    cudaFuncSetAttribute(tcgemm_kernel<1>, cudaFuncAttributeMaxDynamicSharedMemorySize, GEMM_SMEM);
    cudaFuncSetAttribute(tcgemm_kernel<2>, cudaFuncAttributeMaxDynamicSharedMemorySize, GEMM_SMEM);
    cudaFuncSetAttribute(tcgemm_kernel<3>, cudaFuncAttributeMaxDynamicSharedMemorySize, GEMM_SMEM);
    cudaFuncSetAttribute(attn_mma_kernel, cudaFuncAttributeMaxDynamicSharedMemorySize, ASMEM);

    convT4_kernel<<<dim3(32, 32, 4), 256>>>(Wq, Wk, Wv, Wo, w4);
    convT_kernel<<<dim3(D_FF / 32, D_MODEL / 32), 256>>>(W1, w116, D_MODEL, D_FF);
    convT_kernel<<<dim3(D_MODEL / 32, D_FF / 32), 256>>>(W2, w216, D_FF, D_MODEL);

    conv_kernel<<<(M_TOK * D_MODEL / 4 + 255) / 256, 256>>>(src, srcf, M_TOK * D_MODEL / 4);
    posbias_kernel<<<M_TOK / 128, 128>>>(pos, pq_w1, pq_b1, pq_w2, pq_b2,
                                         pk_w1, pk_b1, pk_w2, pk_b2, qbb, kbb);

    // QKV projections -> fp16
    dim3 gD(D_MODEL / BN, M_TOK / BM);
    tcgemm_kernel<3><<<gD, 256, GEMM_SMEM>>>(srcf, wq16, bq, (const float*)0,
                                             (float*)0, qf, M_TOK, D_MODEL, D_MODEL);
    tcgemm_kernel<3><<<gD, 256, GEMM_SMEM>>>(srcf, wk16, bk, (const float*)0,
                                             (float*)0, kf, M_TOK, D_MODEL, D_MODEL);
    tcgemm_kernel<3><<<gD, 256, GEMM_SMEM>>>(srcf, wv16, bv, (const float*)0,
                                             (float*)0, vf, M_TOK, D_MODEL, D_MODEL);

    attn_mma_kernel<<<dim3(L_ / 128, NHEAD, B_), 256, ASMEM>>>(
        qf, kf, vf, qbb, kbb, temp, atf, entp);

    tcgemm_kernel<2><<<gD, 256, GEMM_SMEM>>>(atf, wo16, bo, src,
                                             yb, (__half*)0, M_TOK, D_MODEL, D_MODEL);
    ln_kernel<1><<<M_TOK, 256>>>(yb, ln1g, ln1b, xb, xf);

    dim3 gF(D_FF / BN, M_TOK / BM);
    tcgemm_kernel<1><<<gF, 256, GEMM_SMEM>>>(xf, w116, b1, (const float*)0,
                                             (float*)0, fff, M_TOK, D_FF, D_MODEL);
    tcgemm_kernel<2><<<gD, 256, GEMM_SMEM>>>(fff, w216, b2, xb,
                                             yb, (__half*)0, M_TOK, D_MODEL, D_FF);
    ln_kernel<0><<<M_TOK, 256>>>(yb, ln2g, ln2b, out, (__half*)0);

    ent_final_kernel<<<1, 256>>>(entp, out, out_size);
}

// round 10
// speedup vs baseline: 6.4919x; 1.0179x over previous
#include <cuda_runtime.h>
#include <cuda_fp16.h>
#include <math.h>
#include <stdint.h>
#include <string.h>

#define D_MODEL 1024
#define NHEAD 16
#define HEAD_DIM 64
#define B_ 2
#define L_ 2048
#define M_TOK 4096
#define D_FF 4096
#define QKVS 3072
#define OUT_MAIN (M_TOK * D_MODEL)

// ---------------- scratch (device globals; no allocations allowed) ----------
__device__ float g_x[M_TOK * D_MODEL];
__device__ float g_y[M_TOK * D_MODEL];
__device__ float g_qbias[M_TOK * NHEAD];
__device__ float g_kbias[M_TOK * NHEAD];
__device__ float g_bqkv[QKVS];
__device__ float g_entpart[1024];
// fp16 activations
__device__ __half g_src_f[M_TOK * D_MODEL];
__device__ __half g_qkv[M_TOK * QKVS];          // Q | K | V packed per row
__device__ __half g_at_f[M_TOK * D_MODEL];
__device__ __half g_x_f[M_TOK * D_MODEL];
__device__ __half g_ff_f[M_TOK * D_FF];
// fp16 transposed weights [N, K]  (wq,wk,wv,wo packed contiguously)
__device__ __half g_w4[4 * D_MODEL * D_MODEL];
__device__ __half g_w1[D_FF * D_MODEL];
__device__ __half g_w2[D_MODEL * D_FF];

// ======================= PTX helpers (baseline sm_103-legal only) ===========
__device__ __forceinline__ uint32_t smem_u32(const void* p) {
    uint32_t a;
    asm("{ .reg .u64 t; cvta.to.shared.u64 t, %1; cvt.u32.u64 %0, t; }" : "=r"(a) : "l"(p));
    return a;
}
__device__ __forceinline__ void cp16(uint32_t s, const void* g) {
    asm volatile("cp.async.cg.shared.global [%0], [%1], 16;" :: "r"(s), "l"(g));
}
__device__ __forceinline__ void cp4(uint32_t s, const void* g) {
    asm volatile("cp.async.ca.shared.global [%0], [%1], 4;" :: "r"(s), "l"(g));
}
#define CP_COMMIT() asm volatile("cp.async.commit_group;" ::: "memory")

__device__ __forceinline__ void ldsm4(uint32_t* r, uint32_t addr) {
    asm volatile("ldmatrix.sync.aligned.m8n8.x4.shared.b16 {%0,%1,%2,%3}, [%4];"
                 : "=r"(r[0]), "=r"(r[1]), "=r"(r[2]), "=r"(r[3]) : "r"(addr));
}
__device__ __forceinline__ void ldsm4t(uint32_t* r, uint32_t addr) {
    asm volatile("ldmatrix.sync.aligned.m8n8.x4.trans.shared.b16 {%0,%1,%2,%3}, [%4];"
                 : "=r"(r[0]), "=r"(r[1]), "=r"(r[2]), "=r"(r[3]) : "r"(addr));
}
__device__ __forceinline__ void mma16816(float* d, const uint32_t* a, uint32_t b0, uint32_t b1) {
    asm volatile(
        "mma.sync.aligned.m16n8k16.row.col.f32.f16.f16.f32 "
        "{%0,%1,%2,%3}, {%4,%5,%6,%7}, {%8,%9}, {%0,%1,%2,%3};"
        : "+f"(d[0]), "+f"(d[1]), "+f"(d[2]), "+f"(d[3])
        : "r"(a[0]), "r"(a[1]), "r"(a[2]), "r"(a[3]), "r"(b0), "r"(b1));
}
__device__ __forceinline__ uint32_t packh(float a, float b) {
    __half2 t = __floats2half2_rn(a, b);
    uint32_t u; memcpy(&u, &t, 4); return u;
}

// ======================= warp-MMA fp16 GEMM (single precision pass) =========
// MODE 0: fp32 +bias  MODE 1: gelu(+bias)->fp16  MODE 2: fp32 +bias+res
// MODE 3: +bias -> fp16
#define BM 128
#define BN 128
#define BKC 32
#define RSTR 80
#define TILE_B (128 * RSTR)
#define STAGE_B (2 * TILE_B)
#define NSTAGE 3
#define GEMM_SMEM (NSTAGE * STAGE_B)

__device__ __forceinline__ void g_load_chunk(
    uint32_t smem, int ci, int m0, int n0, int K, int tid,
    const __half* __restrict__ A, const __half* __restrict__ W)
{
    uint32_t sb = smem + (uint32_t)(ci % NSTAGE) * STAGE_B;
    size_t kbase = (size_t)ci * BKC;
#pragma unroll
    for (int t = 0; t < 2; t++) {
        const __half* P = (t == 0) ? A : W;
        int r0 = (t == 0) ? m0 : n0;
        uint32_t tb = sb + (uint32_t)t * TILE_B;
#pragma unroll
        for (int rep = 0; rep < 2; rep++) {
            int seg = tid + (rep << 8);
            int row = seg >> 2;
            int s4  = seg & 3;
            cp16(tb + (uint32_t)row * RSTR + (uint32_t)s4 * 16,
                 P + (size_t)(r0 + row) * K + kbase + s4 * 8);
        }
    }
}

template <int MODE>
__global__ void __launch_bounds__(256, 2) tcgemm_kernel(
    const __half* __restrict__ A, const __half* __restrict__ W,
    const float* __restrict__ bias, const float* __restrict__ res,
    float* __restrict__ C, __half* __restrict__ Cf,
    int M, int N, int K)
{
    extern __shared__ char dsm[];
    uint32_t smem = smem_u32(dsm);

    int tid = threadIdx.x;
    int wid = tid >> 5;
    int lane = tid & 31;
    int m0 = blockIdx.y * BM;
    int n0 = blockIdx.x * BN;
    int nchunk = K / BKC;

    int wm = wid & 1;
    int wn = wid >> 1;
    int lr = lane & 15;
    uint32_t lk = (uint32_t)((lane >> 4) << 4);

    float acc[4][4][4];
#pragma unroll
    for (int i = 0; i < 4; i++)
#pragma unroll
        for (int j = 0; j < 4; j++)
#pragma unroll
            for (int c = 0; c < 4; c++) acc[i][j][c] = 0.0f;

    g_load_chunk(smem, 0, m0, n0, K, tid, A, W);
    CP_COMMIT();
    g_load_chunk(smem, 1, m0, n0, K, tid, A, W);
    CP_COMMIT();

    for (int i = 0; i < nchunk; i++) {
        if (i < nchunk - 1)
            asm volatile("cp.async.wait_group 1;" ::: "memory");
        else
            asm volatile("cp.async.wait_group 0;" ::: "memory");
        __syncthreads();

        if (i + 2 < nchunk) {
            g_load_chunk(smem, i + 2, m0, n0, K, tid, A, W);
            CP_COMMIT();
        }

        uint32_t sb = smem + (uint32_t)(i % NSTAGE) * STAGE_B;
        uint32_t aBase = sb + (uint32_t)(wm * 64 + lr) * RSTR + lk;
        uint32_t bBase = sb + TILE_B + (uint32_t)(wn * 32 + lr) * RSTR + lk;

#pragma unroll
        for (int ks = 0; ks < 2; ks++) {
            uint32_t koff = (uint32_t)ks * 32;
            uint32_t ah[4][4];
#pragma unroll
            for (int mt = 0; mt < 4; mt++)
                ldsm4(ah[mt], aBase + (uint32_t)(mt * 16) * RSTR + koff);
#pragma unroll
            for (int nt = 0; nt < 2; nt++) {
                uint32_t bb[4];
                ldsm4(bb, bBase + (uint32_t)(nt * 16) * RSTR + koff);
#pragma unroll
                for (int mt = 0; mt < 4; mt++) {
                    mma16816(acc[mt][nt * 2],     ah[mt], bb[0], bb[2]);
                    mma16816(acc[mt][nt * 2 + 1], ah[mt], bb[1], bb[3]);
                }
            }
        }
    }

    int rbase = m0 + wm * 64 + (lane >> 2);
    int cbase = n0 + wn * 32 + (lane & 3) * 2;
#pragma unroll
    for (int mt = 0; mt < 4; mt++) {
#pragma unroll
        for (int n8 = 0; n8 < 4; n8++) {
            int col = cbase + n8 * 8;
            float b0 = bias[col], b1 = bias[col + 1];
#pragma unroll
            for (int half = 0; half < 2; half++) {
                int row = rbase + mt * 16 + half * 8;
                float v0 = acc[mt][n8][half * 2] + b0;
                float v1 = acc[mt][n8][half * 2 + 1] + b1;
                if (MODE == 1) {
                    v0 = 0.5f * v0 * (1.0f + erff(v0 * 0.70710678118654752f));
                    v1 = 0.5f * v1 * (1.0f + erff(v1 * 0.70710678118654752f));
                }
                if (MODE == 2) {
                    const float2 rv = *(const float2*)(res + (size_t)row * N + col);
                    v0 += rv.x; v1 += rv.y;
                }
                if (MODE == 0 || MODE == 2) {
                    float2 o; o.x = v0; o.y = v1;
                    *(float2*)(C + (size_t)row * N + col) = o;
                } else {
                    *(__half2*)(Cf + (size_t)row * N + col) = __floats2half2_rn(v0, v1);
                }
            }
        }
    }
}

// ======================= MMA flash attention (fp16, packed QKV) =============
#define ASTR 144
#define ATILE (64 * ASTR)
#define ASTAGE (2 * ATILE + 256)
#define ASMEM (2 * ASTAGE + 64)

__device__ __forceinline__ void a_load_chunk(
    uint32_t sm0, int ci, size_t tokb, int h, int tid,
    const __half* __restrict__ QKV, const float* __restrict__ kb)
{
    uint32_t st = sm0 + (uint32_t)(ci & 1) * ASTAGE;
    size_t rowb = tokb + (size_t)ci * 64;
#pragma unroll
    for (int r = 0; r < 4; r++) {
        int idx = tid + (r << 8);
        int t = idx >> 9;                  // 0 = K, 1 = V
        int row = (idx >> 3) & 63;
        int seg = idx & 7;
        cp16(st + (uint32_t)t * ATILE + (uint32_t)row * ASTR + (uint32_t)seg * 16,
             QKV + (rowb + row) * QKVS + (t + 1) * D_MODEL + h * HEAD_DIM + seg * 8);
    }
    if (tid < 64)
        cp4(st + 2u * ATILE + (uint32_t)tid * 4, kb + (rowb + tid) * NHEAD + h);
}

__global__ void __launch_bounds__(256, 2) attn_mma_kernel(
    const __half* __restrict__ QKV,
    const float* __restrict__ qb, const float* __restrict__ kb,
    const float* __restrict__ temp,
    __half* __restrict__ Of, float* __restrict__ ent_part)
{
    extern __shared__ char smemv[];
    uint32_t sm0 = smem_u32(smemv);
    float* red = (float*)(smemv + 2 * ASTAGE);

    int tid = threadIdx.x;
    int w = tid >> 5;
    int lane = tid & 31;
    int q0 = blockIdx.x * 128;
    int h = blockIdx.y;
    int b = blockIdx.z;
    size_t tokb = (size_t)b * L_;

    float tmph = fminf(fmaxf(temp[h], 0.1f), 5.0f);
    float inv_t = 1.0f / tmph;
    float sc = 0.125f * inv_t;

    for (int i = tid; i < 128 * 8; i += 256) {
        int row = i >> 3, seg = i & 7;
        cp16(sm0 + (uint32_t)row * ASTR + (uint32_t)seg * 16,
             QKV + (tokb + q0 + row) * QKVS + h * HEAD_DIM + seg * 8);
    }
    CP_COMMIT();
    asm volatile("cp.async.wait_group 0;" ::: "memory");
    __syncthreads();

    uint32_t qfr[4][4];
    {
        uint32_t qbase = sm0 + (uint32_t)(w * 16 + (lane & 15)) * ASTR + (uint32_t)((lane >> 4) << 4);
#pragma unroll
        for (int ks = 0; ks < 4; ks++) ldsm4(qfr[ks], qbase + ks * 32);
    }
    int gid = lane >> 2, tig = lane & 3;
    int r0 = q0 + w * 16 + gid, r1 = r0 + 8;
    float qb0 = qb[(tokb + r0) * NHEAD + h] * inv_t;
    float qb1 = qb[(tokb + r1) * NHEAD + h] * inv_t;
    __syncthreads();

    a_load_chunk(sm0, 0, tokb, h, tid, QKV, kb);
    CP_COMMIT();
    a_load_chunk(sm0, 1, tokb, h, tid, QKV, kb);
    CP_COMMIT();

    float O[8][4];
#pragma unroll
    for (int f = 0; f < 8; f++)
#pragma unroll
        for (int c = 0; c < 4; c++) O[f][c] = 0.0f;
    float m0 = -1e30f, m1 = -1e30f, z0 = 0.0f, z1 = 0.0f, t0 = 0.0f, t1 = 0.0f;

    const int NCH = L_ / 64;
    for (int ci = 0; ci < NCH; ci++) {
        if (ci < NCH - 2)
            asm volatile("cp.async.wait_group 1;" ::: "memory");
        else
            asm volatile("cp.async.wait_group 0;" ::: "memory");
        __syncthreads();

        uint32_t st = sm0 + (uint32_t)(ci & 1) * ASTAGE;
        uint32_t kbh = st + (uint32_t)(lane & 15) * ASTR + (uint32_t)((lane >> 4) << 4);

        float S[8][4];
#pragma unroll
        for (int f = 0; f < 8; f++)
#pragma unroll
            for (int c = 0; c < 4; c++) S[f][c] = 0.0f;

#pragma unroll
        for (int ks = 0; ks < 4; ks++) {
            uint32_t koff = (uint32_t)ks * 32;
#pragma unroll
            for (int nt = 0; nt < 4; nt++) {
                uint32_t bb[4];
                ldsm4(bb, kbh + (uint32_t)(nt * 16) * ASTR + koff);
                mma16816(S[nt * 2],     qfr[ks], bb[0], bb[2]);
                mma16816(S[nt * 2 + 1], qfr[ks], bb[1], bb[3]);
            }
        }

        const float* kbs = (const float*)(smemv + (size_t)((ci & 1) * ASTAGE + 2 * ATILE));
        float mx0 = -1e30f, mx1 = -1e30f;
#pragma unroll
        for (int f = 0; f < 8; f++) {
            float kc0 = kbs[f * 8 + 2 * tig] * inv_t;
            float kc1 = kbs[f * 8 + 2 * tig + 1] * inv_t;
            S[f][0] = S[f][0] * sc + qb0 + kc0;
            S[f][1] = S[f][1] * sc + qb0 + kc1;
            S[f][2] = S[f][2] * sc + qb1 + kc0;
            S[f][3] = S[f][3] * sc + qb1 + kc1;
            mx0 = fmaxf(mx0, fmaxf(S[f][0], S[f][1]));
            mx1 = fmaxf(mx1, fmaxf(S[f][2], S[f][3]));
        }
        mx0 = fmaxf(mx0, __shfl_xor_sync(0xffffffffu, mx0, 1));
        mx0 = fmaxf(mx0, __shfl_xor_sync(0xffffffffu, mx0, 2));
        mx1 = fmaxf(mx1, __shfl_xor_sync(0xffffffffu, mx1, 1));
        mx1 = fmaxf(mx1, __shfl_xor_sync(0xffffffffu, mx1, 2));

        float nm0 = fmaxf(m0, mx0), nm1 = fmaxf(m1, mx1);
        float sc0 = __expf(m0 - nm0), sc1 = __expf(m1 - nm1);
        float zc0 = 0.0f, zc1 = 0.0f, tc0 = 0.0f, tc1 = 0.0f;
        uint32_t pa[4][4];
#pragma unroll
        for (int j = 0; j < 4; j++) {
#pragma unroll
            for (int g = 0; g < 2; g++) {
                int f = 2 * j + g;
                float p0 = __expf(S[f][0] - nm0);
                float p1 = __expf(S[f][1] - nm0);
                float p2 = __expf(S[f][2] - nm1);
                float p3 = __expf(S[f][3] - nm1);
                zc0 += p0 + p1; zc1 += p2 + p3;
                tc0 += p0 * S[f][0] + p1 * S[f][1];
                tc1 += p2 * S[f][2] + p3 * S[f][3];
                pa[j][g * 2]     = packh(p0, p1);
                pa[j][g * 2 + 1] = packh(p2, p3);
            }
        }
        zc0 += __shfl_xor_sync(0xffffffffu, zc0, 1); zc0 += __shfl_xor_sync(0xffffffffu, zc0, 2);
        zc1 += __shfl_xor_sync(0xffffffffu, zc1, 1); zc1 += __shfl_xor_sync(0xffffffffu, zc1, 2);
        tc0 += __shfl_xor_sync(0xffffffffu, tc0, 1); tc0 += __shfl_xor_sync(0xffffffffu, tc0, 2);
        tc1 += __shfl_xor_sync(0xffffffffu, tc1, 1); tc1 += __shfl_xor_sync(0xffffffffu, tc1, 2);
        z0 = z0 * sc0 + zc0; t0 = t0 * sc0 + tc0; m0 = nm0;
        z1 = z1 * sc1 + zc1; t1 = t1 * sc1 + tc1; m1 = nm1;
#pragma unroll
        for (int f = 0; f < 8; f++) {
            O[f][0] *= sc0; O[f][1] *= sc0; O[f][2] *= sc1; O[f][3] *= sc1;
        }

        uint32_t vb = st + ATILE + (uint32_t)(lane & 15) * ASTR + (uint32_t)((lane >> 4) << 4);
#pragma unroll
        for (int j = 0; j < 4; j++) {
            uint32_t vrow = vb + (uint32_t)(j * 16) * ASTR;
#pragma unroll
            for (int hg = 0; hg < 4; hg++) {
                uint32_t v[4];
                ldsm4t(v, vrow + (uint32_t)hg * 32);
                mma16816(O[hg * 2],     pa[j], v[0], v[1]);
                mma16816(O[hg * 2 + 1], pa[j], v[2], v[3]);
            }
        }
        __syncthreads();
        if (ci + 2 < NCH) {
            a_load_chunk(sm0, ci + 2, tokb, h, tid, QKV, kb);
            CP_COMMIT();
        }
    }

    float iz0 = 1.0f / z0, iz1 = 1.0f / z1;
    size_t row0b = (tokb + r0) * D_MODEL, row1b = (tokb + r1) * D_MODEL;
#pragma unroll
    for (int f = 0; f < 8; f++) {
        int col = h * HEAD_DIM + f * 8 + 2 * tig;
        *(__half2*)(Of + row0b + col) = __floats2half2_rn(O[f][0] * iz0, O[f][1] * iz0);
        *(__half2*)(Of + row1b + col) = __floats2half2_rn(O[f][2] * iz1, O[f][3] * iz1);
    }

    float Hv = (m0 + logf(z0) - t0 / z0 + m1 + logf(z1) - t1 / z1) * 0.25f;
#pragma unroll
    for (int off = 16; off; off >>= 1) Hv += __shfl_xor_sync(0xffffffffu, Hv, off);
    if (lane == 0) red[w] = Hv;
    __syncthreads();
    if (tid == 0) {
        float s = 0.0f;
#pragma unroll
        for (int i = 0; i < 8; i++) s += red[i];
        ent_part[((b * NHEAD + h) << 4) + blockIdx.x] = s;
    }
}

// ======================= weight transpose (fp16) ============================
__global__ void __launch_bounds__(256) convT4_kernel(
    const float* __restrict__ W0, const float* __restrict__ W1p,
    const float* __restrict__ W2p, const float* __restrict__ W3,
    __half* __restrict__ o16)
{
    __shared__ float t[32][33];
    const float* W = (blockIdx.z == 0) ? W0 : (blockIdx.z == 1) ? W1p
                   : (blockIdx.z == 2) ? W2p : W3;
    __half* dst = o16 + (size_t)blockIdx.z * D_MODEL * D_MODEL;
    int n0 = blockIdx.x * 32, k0 = blockIdx.y * 32;
    int tx = threadIdx.x & 31, ty = threadIdx.x >> 5;
#pragma unroll
    for (int i = 0; i < 32; i += 8)
        t[ty + i][tx] = W[(size_t)(k0 + ty + i) * D_MODEL + n0 + tx];
    __syncthreads();
#pragma unroll
    for (int i = 0; i < 32; i += 8)
        dst[(size_t)(n0 + ty + i) * D_MODEL + k0 + tx] = __float2half_rn(t[tx][ty + i]);
}

__global__ void __launch_bounds__(256) convT_kernel(
    const float* __restrict__ W, __half* __restrict__ o16, int K, int N)
{
    __shared__ float t[32][33];
    int n0 = blockIdx.x * 32, k0 = blockIdx.y * 32;
    int tx = threadIdx.x & 31, ty = threadIdx.x >> 5;
#pragma unroll
    for (int i = 0; i < 32; i += 8)
        t[ty + i][tx] = W[(size_t)(k0 + ty + i) * N + n0 + tx];
    __syncthreads();
#pragma unroll
    for (int i = 0; i < 32; i += 8)
        o16[(size_t)(n0 + ty + i) * K + k0 + tx] = __float2half_rn(t[tx][ty + i]);
}

__global__ void __launch_bounds__(256) conv_kernel(
    const float* __restrict__ in, __half* __restrict__ outp, int n4)
{
    int i = blockIdx.x * 256 + threadIdx.x;
    if (i >= n4) return;
    float4 v = ((const float4*)in)[i];
    ((__half2*)outp)[i * 2]     = __floats2half2_rn(v.x, v.y);
    ((__half2*)outp)[i * 2 + 1] = __floats2half2_rn(v.z, v.w);
}

// ---------------- POS bias MLPs ----------------------------------------------
__global__ void __launch_bounds__(128) posbias_kernel(
    const float* __restrict__ pos,
    const float* __restrict__ qw1, const float* __restrict__ qb1,
    const float* __restrict__ qw2, const float* __restrict__ qb2,
    const float* __restrict__ kw1, const float* __restrict__ kb1,
    const float* __restrict__ kw2, const float* __restrict__ kb2,
    float* __restrict__ qbias, float* __restrict__ kbias)
{
    __shared__ float sw1q[32 * 32], sw2q[32 * 16], sb1q[32], sb2q[16];
    __shared__ float sw1k[32 * 32], sw2k[32 * 16], sb1k[32], sb2k[16];
    int tid = threadIdx.x;
    for (int i = tid; i < 1024; i += 128) { sw1q[i] = qw1[i]; sw1k[i] = kw1[i]; }
    for (int i = tid; i < 512;  i += 128) { sw2q[i] = qw2[i]; sw2k[i] = kw2[i]; }
    if (tid < 32) { sb1q[tid] = qb1[tid]; sb1k[tid] = kb1[tid]; }
    if (tid < 16) { sb2q[tid] = qb2[tid]; sb2k[tid] = kb2[tid]; }
    __syncthreads();

    int token = blockIdx.x * 128 + tid;
    float pf[32];
#pragma unroll
    for (int i = 0; i < 32; i++) pf[i] = pos[(size_t)token * 32 + i];

    float hq[32], hk[32];
#pragma unroll
    for (int j = 0; j < 32; j++) { hq[j] = sb1q[j]; hk[j] = sb1k[j]; }
    for (int i = 0; i < 32; i++) {
        float p = pf[i];
#pragma unroll
        for (int j = 0; j < 32; j++) {
            hq[j] += p * sw1q[i * 32 + j];
            hk[j] += p * sw1k[i * 32 + j];
        }
    }
#pragma unroll
    for (int j = 0; j < 32; j++) {
        hq[j] = fmaxf(hq[j], 0.0f);
        hk[j] = fmaxf(hk[j], 0.0f);
    }
#pragma unroll
    for (int h = 0; h < 16; h++) {
        float oq = sb2q[h], ok = sb2k[h];
        for (int j = 0; j < 32; j++) {
            oq += hq[j] * sw2q[j * 16 + h];
            ok += hk[j] * sw2k[j * 16 + h];
        }
        qbias[(size_t)token * NHEAD + h] = oq;
        kbias[(size_t)token * NHEAD + h] = ok;
    }
}

// ---------------- layernorm (optionally emits fp16) --------------------------
template <int SPLIT>
__global__ void __launch_bounds__(256) ln_kernel(
    const float* __restrict__ in, const float* __restrict__ gam,
    const float* __restrict__ bet, float* __restrict__ out,
    __half* __restrict__ of)
{
    int row = blockIdx.x, tid = threadIdx.x;
    float4 v = ((const float4*)(in + (size_t)row * D_MODEL))[tid];
    float s = v.x + v.y + v.z + v.w;
    float q = v.x * v.x + v.y * v.y + v.z * v.z + v.w * v.w;
#pragma unroll
    for (int off = 16; off; off >>= 1) {
        s += __shfl_xor_sync(0xffffffffu, s, off);
        q += __shfl_xor_sync(0xffffffffu, q, off);
    }
    __shared__ float ws[8], wq[8], stats[2];
    int lane = tid & 31, w = tid >> 5;
    if (lane == 0) { ws[w] = s; wq[w] = q; }
    __syncthreads();
    if (tid == 0) {
        float S = 0.0f, Qq = 0.0f;
        for (int i = 0; i < 8; i++) { S += ws[i]; Qq += wq[i]; }
        float mu  = S * (1.0f / D_MODEL);
        float var = Qq * (1.0f / D_MODEL) - mu * mu;
        stats[0] = mu;
        stats[1] = rsqrtf(var + 1e-5f);
    }
    __syncthreads();
    float mu = stats[0], rs = stats[1];
    float4 gv = ((const float4*)gam)[tid];
    float4 bv = ((const float4*)bet)[tid];
    float4 ov;
    ov.x = (v.x - mu) * rs * gv.x + bv.x;
    ov.y = (v.y - mu) * rs * gv.y + bv.y;
    ov.z = (v.z - mu) * rs * gv.z + bv.z;
    ov.w = (v.w - mu) * rs * gv.w + bv.w;
    ((float4*)(out + (size_t)row * D_MODEL))[tid] = ov;
    if (SPLIT) {
        size_t base = (size_t)row * D_MODEL + tid * 4;
        *(__half2*)(of + base)     = __floats2half2_rn(ov.x, ov.y);
        *(__half2*)(of + base + 2) = __floats2half2_rn(ov.z, ov.w);
    }
}

// ---------------- deterministic entropy reduction ----------------------------
__global__ void __launch_bounds__(256) ent_final_kernel(
    const float* __restrict__ part, float* __restrict__ out, int out_size)
{
    __shared__ float sm[256];
    int tid = threadIdx.x;
    sm[tid] = part[tid] + part[tid + 256];
    __syncthreads();
    for (int off = 128; off; off >>= 1) {
        if (tid < off) sm[tid] += sm[tid + off];
        __syncthreads();
    }
    if (tid == 0 && out_size > OUT_MAIN)
        out[OUT_MAIN] = sm[0] * (1.0f / (B_ * NHEAD * L_));
}

// ---------------- launch -----------------------------------------------------
extern "C" void kernel_launch(void* const* d_in, const int* in_sizes, int n_in,
                              void* d_out, int out_size)
{
    const float* src   = (const float*)d_in[0];
    const float* pos   = (const float*)d_in[1];
    const float* Wq    = (const float*)d_in[2];
    const float* bq    = (const float*)d_in[3];
    const float* Wk    = (const float*)d_in[4];
    const float* bk    = (const float*)d_in[5];
    const float* Wv    = (const float*)d_in[6];
    const float* bv    = (const float*)d_in[7];
    const float* Wo    = (const float*)d_in[8];
    const float* bo    = (const float*)d_in[9];
    const float* pq_w1 = (const float*)d_in[10];
    const float* pq_b1 = (const float*)d_in[11];
    const float* pq_w2 = (const float*)d_in[12];
    const float* pq_b2 = (const float*)d_in[13];
    const float* pk_w1 = (const float*)d_in[14];
    const float* pk_b1 = (const float*)d_in[15];
    const float* pk_w2 = (const float*)d_in[16];
    const float* pk_b2 = (const float*)d_in[17];
    const float* temp  = (const float*)d_in[18];
    const float* ln1g  = (const float*)d_in[19];
    const float* ln1b  = (const float*)d_in[20];
    const float* ln2g  = (const float*)d_in[21];
    const float* ln2b  = (const float*)d_in[22];
    const float* W1    = (const float*)d_in[23];
    const float* b1    = (const float*)d_in[24];
    const float* W2    = (const float*)d_in[25];
    const float* b2    = (const float*)d_in[26];
    float* out = (float*)d_out;

    float *xb, *yb, *qbb, *kbb, *entp, *bqkv;
    cudaGetSymbolAddress((void**)&xb, g_x);
    cudaGetSymbolAddress((void**)&yb, g_y);
    cudaGetSymbolAddress((void**)&qbb, g_qbias);
    cudaGetSymbolAddress((void**)&kbb, g_kbias);
    cudaGetSymbolAddress((void**)&entp, g_entpart);
    cudaGetSymbolAddress((void**)&bqkv, g_bqkv);

    __half *srcf, *qkv, *atf, *xf, *fff;
    __half *w4, *w116, *w216;
    cudaGetSymbolAddress((void**)&srcf, g_src_f);
    cudaGetSymbolAddress((void**)&qkv, g_qkv);
    cudaGetSymbolAddress((void**)&atf, g_at_f);
    cudaGetSymbolAddress((void**)&xf, g_x_f);
    cudaGetSymbolAddress((void**)&fff, g_ff_f);
    cudaGetSymbolAddress((void**)&w4, g_w4);
    cudaGetSymbolAddress((void**)&w116, g_w1);
    cudaGetSymbolAddress((void**)&w216, g_w2);

    __half* wo16 = w4 + 3 * (size_t)D_MODEL * D_MODEL;

    cudaFuncSetAttribute(tcgemm_kernel<1>, cudaFuncAttributeMaxDynamicSharedMemorySize, GEMM_SMEM);
    cudaFuncSetAttribute(tcgemm_kernel<2>, cudaFuncAttributeMaxDynamicSharedMemorySize, GEMM_SMEM);
    cudaFuncSetAttribute(tcgemm_kernel<3>, cudaFuncAttributeMaxDynamicSharedMemorySize, GEMM_SMEM);
    cudaFuncSetAttribute(attn_mma_kernel, cudaFuncAttributeMaxDynamicSharedMemorySize, ASMEM);

    // concat QKV biases (capturable D2D async copies)
    cudaMemcpyAsync(bqkv,                bq, D_MODEL * sizeof(float), cudaMemcpyDeviceToDevice);
    cudaMemcpyAsync(bqkv + D_MODEL,      bk, D_MODEL * sizeof(float), cudaMemcpyDeviceToDevice);
    cudaMemcpyAsync(bqkv + 2 * D_MODEL,  bv, D_MODEL * sizeof(float), cudaMemcpyDeviceToDevice);

    convT4_kernel<<<dim3(32, 32, 4), 256>>>(Wq, Wk, Wv, Wo, w4);
    convT_kernel<<<dim3(D_FF / 32, D_MODEL / 32), 256>>>(W1, w116, D_MODEL, D_FF);
    convT_kernel<<<dim3(D_MODEL / 32, D_FF / 32), 256>>>(W2, w216, D_FF, D_MODEL);

    conv_kernel<<<(M_TOK * D_MODEL / 4 + 255) / 256, 256>>>(src, srcf, M_TOK * D_MODEL / 4);
    posbias_kernel<<<M_TOK / 128, 128>>>(pos, pq_w1, pq_b1, pq_w2, pq_b2,
                                         pk_w1, pk_b1, pk_w2, pk_b2, qbb, kbb);

    // fused QKV projection: [4096,1024] @ [3072,1024]^T -> g_qkv (stride 3072)
    dim3 gQKV(QKVS / BN, M_TOK / BM);   // (24, 32)
    tcgemm_kernel<3><<<gQKV, 256, GEMM_SMEM>>>(srcf, w4, bqkv, (const float*)0,
                                               (float*)0, qkv, M_TOK, QKVS, D_MODEL);

    attn_mma_kernel<<<dim3(L_ / 128, NHEAD, B_), 256, ASMEM>>>(
        qkv, qbb, kbb, temp, atf, entp);

    dim3 gD(D_MODEL / BN, M_TOK / BM);
    tcgemm_kernel<2><<<gD, 256, GEMM_SMEM>>>(atf, wo16, bo, src,
                                             yb, (__half*)0, M_TOK, D_MODEL, D_MODEL);
    ln_kernel<1><<<M_TOK, 256>>>(yb, ln1g, ln1b, xb, xf);

    dim3 gF(D_FF / BN, M_TOK / BM);
    tcgemm_kernel<1><<<gF, 256, GEMM_SMEM>>>(xf, w116, b1, (const float*)0,
                                             (float*)0, fff, M_TOK, D_FF, D_MODEL);
    tcgemm_kernel<2><<<gD, 256, GEMM_SMEM>>>(fff, w216, b2, xb,
                                             yb, (__half*)0, M_TOK, D_MODEL, D_FF);
    ln_kernel<0><<<M_TOK, 256>>>(yb, ln2g, ln2b, out, (__half*)0);

    ent_final_kernel<<<1, 256>>>(entp, out, out_size);
}

// round 11
// speedup vs baseline: 6.9190x; 1.0658x over previous
#include <cuda_runtime.h>
#include <cuda_fp16.h>
#include <math.h>
#include <stdint.h>
#include <string.h>

#define D_MODEL 1024
#define NHEAD 16
#define HEAD_DIM 64
#define B_ 2
#define L_ 2048
#define M_TOK 4096
#define D_FF 4096
#define QKVS 3072
#define OUT_MAIN (M_TOK * D_MODEL)

// ---------------- scratch (device globals; no allocations allowed) ----------
__device__ float g_x[M_TOK * D_MODEL];
__device__ float g_y[M_TOK * D_MODEL];
__device__ float g_qbias[M_TOK * NHEAD];
__device__ float g_kbias[M_TOK * NHEAD];
__device__ float g_bqkv[QKVS];
__device__ float g_entpart[1024];
// fp16 activations
__device__ __half g_src_f[M_TOK * D_MODEL];
__device__ __half g_qkv[M_TOK * QKVS];          // Q | K | V packed per row
__device__ __half g_at_f[M_TOK * D_MODEL];
__device__ __half g_x_f[M_TOK * D_MODEL];
__device__ __half g_ff_f[M_TOK * D_FF];
// fp16 transposed weights [N, K]  (wq,wk,wv,wo packed contiguously)
__device__ __half g_w4[4 * D_MODEL * D_MODEL];
__device__ __half g_w1[D_FF * D_MODEL];
__device__ __half g_w2[D_MODEL * D_FF];

// ======================= PTX helpers (baseline sm_103-legal only) ===========
__device__ __forceinline__ uint32_t smem_u32(const void* p) {
    uint32_t a;
    asm("{ .reg .u64 t; cvta.to.shared.u64 t, %1; cvt.u32.u64 %0, t; }" : "=r"(a) : "l"(p));
    return a;
}
__device__ __forceinline__ void cp16(uint32_t s, const void* g) {
    asm volatile("cp.async.cg.shared.global [%0], [%1], 16;" :: "r"(s), "l"(g));
}
__device__ __forceinline__ void cp4(uint32_t s, const void* g) {
    asm volatile("cp.async.ca.shared.global [%0], [%1], 4;" :: "r"(s), "l"(g));
}
#define CP_COMMIT() asm volatile("cp.async.commit_group;" ::: "memory")

__device__ __forceinline__ void ldsm4(uint32_t* r, uint32_t addr) {
    asm volatile("ldmatrix.sync.aligned.m8n8.x4.shared.b16 {%0,%1,%2,%3}, [%4];"
                 : "=r"(r[0]), "=r"(r[1]), "=r"(r[2]), "=r"(r[3]) : "r"(addr));
}
__device__ __forceinline__ void ldsm4t(uint32_t* r, uint32_t addr) {
    asm volatile("ldmatrix.sync.aligned.m8n8.x4.trans.shared.b16 {%0,%1,%2,%3}, [%4];"
                 : "=r"(r[0]), "=r"(r[1]), "=r"(r[2]), "=r"(r[3]) : "r"(addr));
}
__device__ __forceinline__ void mma16816(float* d, const uint32_t* a, uint32_t b0, uint32_t b1) {
    asm volatile(
        "mma.sync.aligned.m16n8k16.row.col.f32.f16.f16.f32 "
        "{%0,%1,%2,%3}, {%4,%5,%6,%7}, {%8,%9}, {%0,%1,%2,%3};"
        : "+f"(d[0]), "+f"(d[1]), "+f"(d[2]), "+f"(d[3])
        : "r"(a[0]), "r"(a[1]), "r"(a[2]), "r"(a[3]), "r"(b0), "r"(b1));
}
__device__ __forceinline__ uint32_t packh(float a, float b) {
    __half2 t = __floats2half2_rn(a, b);
    uint32_t u; memcpy(&u, &t, 4); return u;
}

// ======================= warp-MMA fp16 GEMM (BKC=64, double buffer) =========
// MODE 0: fp32 +bias  MODE 1: gelu(+bias)->fp16  MODE 2: fp32 +bias+res
// MODE 3: +bias -> fp16
#define BM 128
#define BN 128
#define BKC 64
#define RSTR 144                         // 128B data + 16B pad (conflict-free)
#define TILE_B (128 * RSTR)              // 18432
#define STAGE_B (2 * TILE_B)             // 36864 : A, W
#define GEMM_SMEM (2 * STAGE_B)          // 73728 -> 2 CTAs/SM

__device__ __forceinline__ void g_load_chunk(
    uint32_t smem, int ci, int m0, int n0, int K, int tid,
    const __half* __restrict__ A, const __half* __restrict__ W)
{
    uint32_t sb = smem + (uint32_t)(ci & 1) * STAGE_B;
    size_t kbase = (size_t)ci * BKC;
#pragma unroll
    for (int rep = 0; rep < 8; rep++) {
        int idx = tid + (rep << 8);          // 0..2047
        int t = idx >> 10;                   // 0 = A, 1 = W
        int row = (idx >> 3) & 127;
        int seg = idx & 7;
        const __half* P = (t == 0) ? A : W;
        int r0 = (t == 0) ? m0 : n0;
        cp16(sb + (uint32_t)t * TILE_B + (uint32_t)row * RSTR + (uint32_t)seg * 16,
             P + (size_t)(r0 + row) * K + kbase + seg * 8);
    }
}

template <int MODE>
__global__ void __launch_bounds__(256, 2) tcgemm_kernel(
    const __half* __restrict__ A, const __half* __restrict__ W,
    const float* __restrict__ bias, const float* __restrict__ res,
    float* __restrict__ C, __half* __restrict__ Cf,
    int M, int N, int K)
{
    extern __shared__ char dsm[];
    uint32_t smem = smem_u32(dsm);

    int tid = threadIdx.x;
    int wid = tid >> 5;
    int lane = tid & 31;
    int m0 = blockIdx.y * BM;
    int n0 = blockIdx.x * BN;
    int nchunk = K / BKC;

    int wm = wid & 1;
    int wn = wid >> 1;
    int lr = lane & 15;
    uint32_t lk = (uint32_t)((lane >> 4) << 4);

    float acc[4][4][4];
#pragma unroll
    for (int i = 0; i < 4; i++)
#pragma unroll
        for (int j = 0; j < 4; j++)
#pragma unroll
            for (int c = 0; c < 4; c++) acc[i][j][c] = 0.0f;

    g_load_chunk(smem, 0, m0, n0, K, tid, A, W);
    CP_COMMIT();

    for (int i = 0; i < nchunk; i++) {
        if (i + 1 < nchunk) {
            g_load_chunk(smem, i + 1, m0, n0, K, tid, A, W);
            CP_COMMIT();
            asm volatile("cp.async.wait_group 1;" ::: "memory");
        } else {
            asm volatile("cp.async.wait_group 0;" ::: "memory");
        }
        __syncthreads();

        uint32_t sb = smem + (uint32_t)(i & 1) * STAGE_B;
        uint32_t aBase = sb + (uint32_t)(wm * 64 + lr) * RSTR + lk;
        uint32_t bBase = sb + TILE_B + (uint32_t)(wn * 32 + lr) * RSTR + lk;

#pragma unroll
        for (int ks = 0; ks < 4; ks++) {
            uint32_t koff = (uint32_t)ks * 32;
            uint32_t ah[4][4];
#pragma unroll
            for (int mt = 0; mt < 4; mt++)
                ldsm4(ah[mt], aBase + (uint32_t)(mt * 16) * RSTR + koff);
#pragma unroll
            for (int nt = 0; nt < 2; nt++) {
                uint32_t bb[4];
                ldsm4(bb, bBase + (uint32_t)(nt * 16) * RSTR + koff);
#pragma unroll
                for (int mt = 0; mt < 4; mt++) {
                    mma16816(acc[mt][nt * 2],     ah[mt], bb[0], bb[2]);
                    mma16816(acc[mt][nt * 2 + 1], ah[mt], bb[1], bb[3]);
                }
            }
        }
        __syncthreads();   // protect stage (i+1)&1 before next prefetch overwrites
    }

    int rbase = m0 + wm * 64 + (lane >> 2);
    int cbase = n0 + wn * 32 + (lane & 3) * 2;
#pragma unroll
    for (int mt = 0; mt < 4; mt++) {
#pragma unroll
        for (int n8 = 0; n8 < 4; n8++) {
            int col = cbase + n8 * 8;
            float b0 = bias[col], b1 = bias[col + 1];
#pragma unroll
            for (int half = 0; half < 2; half++) {
                int row = rbase + mt * 16 + half * 8;
                float v0 = acc[mt][n8][half * 2] + b0;
                float v1 = acc[mt][n8][half * 2 + 1] + b1;
                if (MODE == 1) {
                    v0 = 0.5f * v0 * (1.0f + erff(v0 * 0.70710678118654752f));
                    v1 = 0.5f * v1 * (1.0f + erff(v1 * 0.70710678118654752f));
                }
                if (MODE == 2) {
                    const float2 rv = *(const float2*)(res + (size_t)row * N + col);
                    v0 += rv.x; v1 += rv.y;
                }
                if (MODE == 0 || MODE == 2) {
                    float2 o; o.x = v0; o.y = v1;
                    *(float2*)(C + (size_t)row * N + col) = o;
                } else {
                    *(__half2*)(Cf + (size_t)row * N + col) = __floats2half2_rn(v0, v1);
                }
            }
        }
    }
}

// ======================= MMA flash attention (fp16, packed QKV) =============
#define ASTR 144
#define ATILE (64 * ASTR)
#define ASTAGE (2 * ATILE + 256)
#define ASMEM (2 * ASTAGE + 64)

__device__ __forceinline__ void a_load_chunk(
    uint32_t sm0, int ci, size_t tokb, int h, int tid,
    const __half* __restrict__ QKV, const float* __restrict__ kb)
{
    uint32_t st = sm0 + (uint32_t)(ci & 1) * ASTAGE;
    size_t rowb = tokb + (size_t)ci * 64;
#pragma unroll
    for (int r = 0; r < 4; r++) {
        int idx = tid + (r << 8);
        int t = idx >> 9;                  // 0 = K, 1 = V
        int row = (idx >> 3) & 63;
        int seg = idx & 7;
        cp16(st + (uint32_t)t * ATILE + (uint32_t)row * ASTR + (uint32_t)seg * 16,
             QKV + (rowb + row) * QKVS + (t + 1) * D_MODEL + h * HEAD_DIM + seg * 8);
    }
    if (tid < 64)
        cp4(st + 2u * ATILE + (uint32_t)tid * 4, kb + (rowb + tid) * NHEAD + h);
}

__global__ void __launch_bounds__(256, 2) attn_mma_kernel(
    const __half* __restrict__ QKV,
    const float* __restrict__ qb, const float* __restrict__ kb,
    const float* __restrict__ temp,
    __half* __restrict__ Of, float* __restrict__ ent_part)
{
    extern __shared__ char smemv[];
    uint32_t sm0 = smem_u32(smemv);
    float* red = (float*)(smemv + 2 * ASTAGE);

    int tid = threadIdx.x;
    int w = tid >> 5;
    int lane = tid & 31;
    int q0 = blockIdx.x * 128;
    int h = blockIdx.y;
    int b = blockIdx.z;
    size_t tokb = (size_t)b * L_;

    float tmph = fminf(fmaxf(temp[h], 0.1f), 5.0f);
    float inv_t = 1.0f / tmph;
    float sc = 0.125f * inv_t;

    for (int i = tid; i < 128 * 8; i += 256) {
        int row = i >> 3, seg = i & 7;
        cp16(sm0 + (uint32_t)row * ASTR + (uint32_t)seg * 16,
             QKV + (tokb + q0 + row) * QKVS + h * HEAD_DIM + seg * 8);
    }
    CP_COMMIT();
    asm volatile("cp.async.wait_group 0;" ::: "memory");
    __syncthreads();

    uint32_t qfr[4][4];
    {
        uint32_t qbase = sm0 + (uint32_t)(w * 16 + (lane & 15)) * ASTR + (uint32_t)((lane >> 4) << 4);
#pragma unroll
        for (int ks = 0; ks < 4; ks++) ldsm4(qfr[ks], qbase + ks * 32);
    }
    int gid = lane >> 2, tig = lane & 3;
    int r0 = q0 + w * 16 + gid, r1 = r0 + 8;
    float qb0 = qb[(tokb + r0) * NHEAD + h] * inv_t;
    float qb1 = qb[(tokb + r1) * NHEAD + h] * inv_t;
    __syncthreads();

    a_load_chunk(sm0, 0, tokb, h, tid, QKV, kb);
    CP_COMMIT();
    a_load_chunk(sm0, 1, tokb, h, tid, QKV, kb);
    CP_COMMIT();

    float O[8][4];
#pragma unroll
    for (int f = 0; f < 8; f++)
#pragma unroll
        for (int c = 0; c < 4; c++) O[f][c] = 0.0f;
    float m0 = -1e30f, m1 = -1e30f, z0 = 0.0f, z1 = 0.0f, t0 = 0.0f, t1 = 0.0f;

    const int NCH = L_ / 64;
    for (int ci = 0; ci < NCH; ci++) {
        if (ci < NCH - 2)
            asm volatile("cp.async.wait_group 1;" ::: "memory");
        else
            asm volatile("cp.async.wait_group 0;" ::: "memory");
        __syncthreads();

        uint32_t st = sm0 + (uint32_t)(ci & 1) * ASTAGE;
        uint32_t kbh = st + (uint32_t)(lane & 15) * ASTR + (uint32_t)((lane >> 4) << 4);

        float S[8][4];
#pragma unroll
        for (int f = 0; f < 8; f++)
#pragma unroll
            for (int c = 0; c < 4; c++) S[f][c] = 0.0f;

#pragma unroll
        for (int ks = 0; ks < 4; ks++) {
            uint32_t koff = (uint32_t)ks * 32;
#pragma unroll
            for (int nt = 0; nt < 4; nt++) {
                uint32_t bb[4];
                ldsm4(bb, kbh + (uint32_t)(nt * 16) * ASTR + koff);
                mma16816(S[nt * 2],     qfr[ks], bb[0], bb[2]);
                mma16816(S[nt * 2 + 1], qfr[ks], bb[1], bb[3]);
            }
        }

        const float* kbs = (const float*)(smemv + (size_t)((ci & 1) * ASTAGE + 2 * ATILE));
        float mx0 = -1e30f, mx1 = -1e30f;
#pragma unroll
        for (int f = 0; f < 8; f++) {
            float kc0 = kbs[f * 8 + 2 * tig] * inv_t;
            float kc1 = kbs[f * 8 + 2 * tig + 1] * inv_t;
            S[f][0] = S[f][0] * sc + qb0 + kc0;
            S[f][1] = S[f][1] * sc + qb0 + kc1;
            S[f][2] = S[f][2] * sc + qb1 + kc0;
            S[f][3] = S[f][3] * sc + qb1 + kc1;
            mx0 = fmaxf(mx0, fmaxf(S[f][0], S[f][1]));
            mx1 = fmaxf(mx1, fmaxf(S[f][2], S[f][3]));
        }
        mx0 = fmaxf(mx0, __shfl_xor_sync(0xffffffffu, mx0, 1));
        mx0 = fmaxf(mx0, __shfl_xor_sync(0xffffffffu, mx0, 2));
        mx1 = fmaxf(mx1, __shfl_xor_sync(0xffffffffu, mx1, 1));
        mx1 = fmaxf(mx1, __shfl_xor_sync(0xffffffffu, mx1, 2));

        float nm0 = fmaxf(m0, mx0), nm1 = fmaxf(m1, mx1);
        float sc0 = __expf(m0 - nm0), sc1 = __expf(m1 - nm1);
        float zc0 = 0.0f, zc1 = 0.0f, tc0 = 0.0f, tc1 = 0.0f;
        uint32_t pa[4][4];
#pragma unroll
        for (int j = 0; j < 4; j++) {
#pragma unroll
            for (int g = 0; g < 2; g++) {
                int f = 2 * j + g;
                float p0 = __expf(S[f][0] - nm0);
                float p1 = __expf(S[f][1] - nm0);
                float p2 = __expf(S[f][2] - nm1);
                float p3 = __expf(S[f][3] - nm1);
                zc0 += p0 + p1; zc1 += p2 + p3;
                tc0 += p0 * S[f][0] + p1 * S[f][1];
                tc1 += p2 * S[f][2] + p3 * S[f][3];
                pa[j][g * 2]     = packh(p0, p1);
                pa[j][g * 2 + 1] = packh(p2, p3);
            }
        }
        zc0 += __shfl_xor_sync(0xffffffffu, zc0, 1); zc0 += __shfl_xor_sync(0xffffffffu, zc0, 2);
        zc1 += __shfl_xor_sync(0xffffffffu, zc1, 1); zc1 += __shfl_xor_sync(0xffffffffu, zc1, 2);
        tc0 += __shfl_xor_sync(0xffffffffu, tc0, 1); tc0 += __shfl_xor_sync(0xffffffffu, tc0, 2);
        tc1 += __shfl_xor_sync(0xffffffffu, tc1, 1); tc1 += __shfl_xor_sync(0xffffffffu, tc1, 2);
        z0 = z0 * sc0 + zc0; t0 = t0 * sc0 + tc0; m0 = nm0;
        z1 = z1 * sc1 + zc1; t1 = t1 * sc1 + tc1; m1 = nm1;
#pragma unroll
        for (int f = 0; f < 8; f++) {
            O[f][0] *= sc0; O[f][1] *= sc0; O[f][2] *= sc1; O[f][3] *= sc1;
        }

        uint32_t vb = st + ATILE + (uint32_t)(lane & 15) * ASTR + (uint32_t)((lane >> 4) << 4);
#pragma unroll
        for (int j = 0; j < 4; j++) {
            uint32_t vrow = vb + (uint32_t)(j * 16) * ASTR;
#pragma unroll
            for (int hg = 0; hg < 4; hg++) {
                uint32_t v[4];
                ldsm4t(v, vrow + (uint32_t)hg * 32);
                mma16816(O[hg * 2],     pa[j], v[0], v[1]);
                mma16816(O[hg * 2 + 1], pa[j], v[2], v[3]);
            }
        }
        __syncthreads();
        if (ci + 2 < NCH) {
            a_load_chunk(sm0, ci + 2, tokb, h, tid, QKV, kb);
            CP_COMMIT();
        }
    }

    float iz0 = 1.0f / z0, iz1 = 1.0f / z1;
    size_t row0b = (tokb + r0) * D_MODEL, row1b = (tokb + r1) * D_MODEL;
#pragma unroll
    for (int f = 0; f < 8; f++) {
        int col = h * HEAD_DIM + f * 8 + 2 * tig;
        *(__half2*)(Of + row0b + col) = __floats2half2_rn(O[f][0] * iz0, O[f][1] * iz0);
        *(__half2*)(Of + row1b + col) = __floats2half2_rn(O[f][2] * iz1, O[f][3] * iz1);
    }

    float Hv = (m0 + logf(z0) - t0 / z0 + m1 + logf(z1) - t1 / z1) * 0.25f;
#pragma unroll
    for (int off = 16; off; off >>= 1) Hv += __shfl_xor_sync(0xffffffffu, Hv, off);
    if (lane == 0) red[w] = Hv;
    __syncthreads();
    if (tid == 0) {
        float s = 0.0f;
#pragma unroll
        for (int i = 0; i < 8; i++) s += red[i];
        ent_part[((b * NHEAD + h) << 4) + blockIdx.x] = s;
    }
}

// ======================= weight transpose (fp16) ============================
__global__ void __launch_bounds__(256) convT4_kernel(
    const float* __restrict__ W0, const float* __restrict__ W1p,
    const float* __restrict__ W2p, const float* __restrict__ W3,
    __half* __restrict__ o16)
{
    __shared__ float t[32][33];
    const float* W = (blockIdx.z == 0) ? W0 : (blockIdx.z == 1) ? W1p
                   : (blockIdx.z == 2) ? W2p : W3;
    __half* dst = o16 + (size_t)blockIdx.z * D_MODEL * D_MODEL;
    int n0 = blockIdx.x * 32, k0 = blockIdx.y * 32;
    int tx = threadIdx.x & 31, ty = threadIdx.x >> 5;
#pragma unroll
    for (int i = 0; i < 32; i += 8)
        t[ty + i][tx] = W[(size_t)(k0 + ty + i) * D_MODEL + n0 + tx];
    __syncthreads();
#pragma unroll
    for (int i = 0; i < 32; i += 8)
        dst[(size_t)(n0 + ty + i) * D_MODEL + k0 + tx] = __float2half_rn(t[tx][ty + i]);
}

__global__ void __launch_bounds__(256) convT_kernel(
    const float* __restrict__ W, __half* __restrict__ o16, int K, int N)
{
    __shared__ float t[32][33];
    int n0 = blockIdx.x * 32, k0 = blockIdx.y * 32;
    int tx = threadIdx.x & 31, ty = threadIdx.x >> 5;
#pragma unroll
    for (int i = 0; i < 32; i += 8)
        t[ty + i][tx] = W[(size_t)(k0 + ty + i) * N + n0 + tx];
    __syncthreads();
#pragma unroll
    for (int i = 0; i < 32; i += 8)
        o16[(size_t)(n0 + ty + i) * K + k0 + tx] = __float2half_rn(t[tx][ty + i]);
}

__global__ void __launch_bounds__(256) conv_kernel(
    const float* __restrict__ in, __half* __restrict__ outp, int n4)
{
    int i = blockIdx.x * 256 + threadIdx.x;
    if (i >= n4) return;
    float4 v = ((const float4*)in)[i];
    ((__half2*)outp)[i * 2]     = __floats2half2_rn(v.x, v.y);
    ((__half2*)outp)[i * 2 + 1] = __floats2half2_rn(v.z, v.w);
}

// ---------------- POS bias MLPs ----------------------------------------------
__global__ void __launch_bounds__(128) posbias_kernel(
    const float* __restrict__ pos,
    const float* __restrict__ qw1, const float* __restrict__ qb1,
    const float* __restrict__ qw2, const float* __restrict__ qb2,
    const float* __restrict__ kw1, const float* __restrict__ kb1,
    const float* __restrict__ kw2, const float* __restrict__ kb2,
    float* __restrict__ qbias, float* __restrict__ kbias)
{
    __shared__ float sw1q[32 * 32], sw2q[32 * 16], sb1q[32], sb2q[16];
    __shared__ float sw1k[32 * 32], sw2k[32 * 16], sb1k[32], sb2k[16];
    int tid = threadIdx.x;
    for (int i = tid; i < 1024; i += 128) { sw1q[i] = qw1[i]; sw1k[i] = kw1[i]; }
    for (int i = tid; i < 512;  i += 128) { sw2q[i] = qw2[i]; sw2k[i] = kw2[i]; }
    if (tid < 32) { sb1q[tid] = qb1[tid]; sb1k[tid] = kb1[tid]; }
    if (tid < 16) { sb2q[tid] = qb2[tid]; sb2k[tid] = kb2[tid]; }
    __syncthreads();

    int token = blockIdx.x * 128 + tid;
    float pf[32];
#pragma unroll
    for (int i = 0; i < 32; i++) pf[i] = pos[(size_t)token * 32 + i];

    float hq[32], hk[32];
#pragma unroll
    for (int j = 0; j < 32; j++) { hq[j] = sb1q[j]; hk[j] = sb1k[j]; }
    for (int i = 0; i < 32; i++) {
        float p = pf[i];
#pragma unroll
        for (int j = 0; j < 32; j++) {
            hq[j] += p * sw1q[i * 32 + j];
            hk[j] += p * sw1k[i * 32 + j];
        }
    }
#pragma unroll
    for (int j = 0; j < 32; j++) {
        hq[j] = fmaxf(hq[j], 0.0f);
        hk[j] = fmaxf(hk[j], 0.0f);
    }
#pragma unroll
    for (int h = 0; h < 16; h++) {
        float oq = sb2q[h], ok = sb2k[h];
        for (int j = 0; j < 32; j++) {
            oq += hq[j] * sw2q[j * 16 + h];
            ok += hk[j] * sw2k[j * 16 + h];
        }
        qbias[(size_t)token * NHEAD + h] = oq;
        kbias[(size_t)token * NHEAD + h] = ok;
    }
}

// ---------------- layernorm (optionally emits fp16) --------------------------
template <int SPLIT>
__global__ void __launch_bounds__(256) ln_kernel(
    const float* __restrict__ in, const float* __restrict__ gam,
    const float* __restrict__ bet, float* __restrict__ out,
    __half* __restrict__ of)
{
    int row = blockIdx.x, tid = threadIdx.x;
    float4 v = ((const float4*)(in + (size_t)row * D_MODEL))[tid];
    float s = v.x + v.y + v.z + v.w;
    float q = v.x * v.x + v.y * v.y + v.z * v.z + v.w * v.w;
#pragma unroll
    for (int off = 16; off; off >>= 1) {
        s += __shfl_xor_sync(0xffffffffu, s, off);
        q += __shfl_xor_sync(0xffffffffu, q, off);
    }
    __shared__ float ws[8], wq[8], stats[2];
    int lane = tid & 31, w = tid >> 5;
    if (lane == 0) { ws[w] = s; wq[w] = q; }
    __syncthreads();
    if (tid == 0) {
        float S = 0.0f, Qq = 0.0f;
        for (int i = 0; i < 8; i++) { S += ws[i]; Qq += wq[i]; }
        float mu  = S * (1.0f / D_MODEL);
        float var = Qq * (1.0f / D_MODEL) - mu * mu;
        stats[0] = mu;
        stats[1] = rsqrtf(var + 1e-5f);
    }
    __syncthreads();
    float mu = stats[0], rs = stats[1];
    float4 gv = ((const float4*)gam)[tid];
    float4 bv = ((const float4*)bet)[tid];
    float4 ov;
    ov.x = (v.x - mu) * rs * gv.x + bv.x;
    ov.y = (v.y - mu) * rs * gv.y + bv.y;
    ov.z = (v.z - mu) * rs * gv.z + bv.z;
    ov.w = (v.w - mu) * rs * gv.w + bv.w;
    ((float4*)(out + (size_t)row * D_MODEL))[tid] = ov;
    if (SPLIT) {
        size_t base = (size_t)row * D_MODEL + tid * 4;
        *(__half2*)(of + base)     = __floats2half2_rn(ov.x, ov.y);
        *(__half2*)(of + base + 2) = __floats2half2_rn(ov.z, ov.w);
    }
}

// ---------------- deterministic entropy reduction ----------------------------
__global__ void __launch_bounds__(256) ent_final_kernel(
    const float* __restrict__ part, float* __restrict__ out, int out_size)
{
    __shared__ float sm[256];
    int tid = threadIdx.x;
    sm[tid] = part[tid] + part[tid + 256];
    __syncthreads();
    for (int off = 128; off; off >>= 1) {
        if (tid < off) sm[tid] += sm[tid + off];
        __syncthreads();
    }
    if (tid == 0 && out_size > OUT_MAIN)
        out[OUT_MAIN] = sm[0] * (1.0f / (B_ * NHEAD * L_));
}

// ---------------- launch -----------------------------------------------------
extern "C" void kernel_launch(void* const* d_in, const int* in_sizes, int n_in,
                              void* d_out, int out_size)
{
    const float* src   = (const float*)d_in[0];
    const float* pos   = (const float*)d_in[1];
    const float* Wq    = (const float*)d_in[2];
    const float* bq    = (const float*)d_in[3];
    const float* Wk    = (const float*)d_in[4];
    const float* bk    = (const float*)d_in[5];
    const float* Wv    = (const float*)d_in[6];
    const float* bv    = (const float*)d_in[7];
    const float* Wo    = (const float*)d_in[8];
    const float* bo    = (const float*)d_in[9];
    const float* pq_w1 = (const float*)d_in[10];
    const float* pq_b1 = (const float*)d_in[11];
    const float* pq_w2 = (const float*)d_in[12];
    const float* pq_b2 = (const float*)d_in[13];
    const float* pk_w1 = (const float*)d_in[14];
    const float* pk_b1 = (const float*)d_in[15];
    const float* pk_w2 = (const float*)d_in[16];
    const float* pk_b2 = (const float*)d_in[17];
    const float* temp  = (const float*)d_in[18];
    const float* ln1g  = (const float*)d_in[19];
    const float* ln1b  = (const float*)d_in[20];
    const float* ln2g  = (const float*)d_in[21];
    const float* ln2b  = (const float*)d_in[22];
    const float* W1    = (const float*)d_in[23];
    const float* b1    = (const float*)d_in[24];
    const float* W2    = (const float*)d_in[25];
    const float* b2    = (const float*)d_in[26];
    float* out = (float*)d_out;

    float *xb, *yb, *qbb, *kbb, *entp, *bqkv;
    cudaGetSymbolAddress((void**)&xb, g_x);
    cudaGetSymbolAddress((void**)&yb, g_y);
    cudaGetSymbolAddress((void**)&qbb, g_qbias);
    cudaGetSymbolAddress((void**)&kbb, g_kbias);
    cudaGetSymbolAddress((void**)&entp, g_entpart);
    cudaGetSymbolAddress((void**)&bqkv, g_bqkv);

    __half *srcf, *qkv, *atf, *xf, *fff;
    __half *w4, *w116, *w216;
    cudaGetSymbolAddress((void**)&srcf, g_src_f);
    cudaGetSymbolAddress((void**)&qkv, g_qkv);
    cudaGetSymbolAddress((void**)&atf, g_at_f);
    cudaGetSymbolAddress((void**)&xf, g_x_f);
    cudaGetSymbolAddress((void**)&fff, g_ff_f);
    cudaGetSymbolAddress((void**)&w4, g_w4);
    cudaGetSymbolAddress((void**)&w116, g_w1);
    cudaGetSymbolAddress((void**)&w216, g_w2);

    __half* wo16 = w4 + 3 * (size_t)D_MODEL * D_MODEL;

    cudaFuncSetAttribute(tcgemm_kernel<1>, cudaFuncAttributeMaxDynamicSharedMemorySize, GEMM_SMEM);
    cudaFuncSetAttribute(tcgemm_kernel<2>, cudaFuncAttributeMaxDynamicSharedMemorySize, GEMM_SMEM);
    cudaFuncSetAttribute(tcgemm_kernel<3>, cudaFuncAttributeMaxDynamicSharedMemorySize, GEMM_SMEM);
    cudaFuncSetAttribute(attn_mma_kernel, cudaFuncAttributeMaxDynamicSharedMemorySize, ASMEM);

    // concat QKV biases (capturable D2D async copies)
    cudaMemcpyAsync(bqkv,                bq, D_MODEL * sizeof(float), cudaMemcpyDeviceToDevice);
    cudaMemcpyAsync(bqkv + D_MODEL,      bk, D_MODEL * sizeof(float), cudaMemcpyDeviceToDevice);
    cudaMemcpyAsync(bqkv + 2 * D_MODEL,  bv, D_MODEL * sizeof(float), cudaMemcpyDeviceToDevice);

    convT4_kernel<<<dim3(32, 32, 4), 256>>>(Wq, Wk, Wv, Wo, w4);
    convT_kernel<<<dim3(D_FF / 32, D_MODEL / 32), 256>>>(W1, w116, D_MODEL, D_FF);
    convT_kernel<<<dim3(D_MODEL / 32, D_FF / 32), 256>>>(W2, w216, D_FF, D_MODEL);

    conv_kernel<<<(M_TOK * D_MODEL / 4 + 255) / 256, 256>>>(src, srcf, M_TOK * D_MODEL / 4);
    posbias_kernel<<<M_TOK / 128, 128>>>(pos, pq_w1, pq_b1, pq_w2, pq_b2,
                                         pk_w1, pk_b1, pk_w2, pk_b2, qbb, kbb);

    // fused QKV projection
    dim3 gQKV(QKVS / BN, M_TOK / BM);
    tcgemm_kernel<3><<<gQKV, 256, GEMM_SMEM>>>(srcf, w4, bqkv, (const float*)0,
                                               (float*)0, qkv, M_TOK, QKVS, D_MODEL);

    attn_mma_kernel<<<dim3(L_ / 128, NHEAD, B_), 256, ASMEM>>>(
        qkv, qbb, kbb, temp, atf, entp);

    dim3 gD(D_MODEL / BN, M_TOK / BM);
    tcgemm_kernel<2><<<gD, 256, GEMM_SMEM>>>(atf, wo16, bo, src,
                                             yb, (__half*)0, M_TOK, D_MODEL, D_MODEL);
    ln_kernel<1><<<M_TOK, 256>>>(yb, ln1g, ln1b, xb, xf);

    dim3 gF(D_FF / BN, M_TOK / BM);
    tcgemm_kernel<1><<<gF, 256, GEMM_SMEM>>>(xf, w116, b1, (const float*)0,
                                             (float*)0, fff, M_TOK, D_FF, D_MODEL);
    tcgemm_kernel<2><<<gD, 256, GEMM_SMEM>>>(fff, w216, b2, xb,
                                             yb, (__half*)0, M_TOK, D_MODEL, D_FF);
    ln_kernel<0><<<M_TOK, 256>>>(yb, ln2g, ln2b, out, (__half*)0);

    ent_final_kernel<<<1, 256>>>(entp, out, out_size);
}

// round 12
// speedup vs baseline: 7.5750x; 1.0948x over previous
#include <cuda_runtime.h>
#include <cuda_fp16.h>
#include <math.h>
#include <stdint.h>
#include <string.h>

#define D_MODEL 1024
#define NHEAD 16
#define HEAD_DIM 64
#define B_ 2
#define L_ 2048
#define M_TOK 4096
#define D_FF 4096
#define QKVS 3072
#define OUT_MAIN (M_TOK * D_MODEL)

// ---------------- scratch (device globals; no allocations allowed) ----------
__device__ float g_x[M_TOK * D_MODEL];
__device__ float g_y[M_TOK * D_MODEL];
__device__ float g_qbias[M_TOK * NHEAD];
__device__ float g_kbias[M_TOK * NHEAD];
__device__ float g_bqkv[QKVS];
__device__ float g_entpart[1024];
// fp16 activations
__device__ __half g_src_f[M_TOK * D_MODEL];
__device__ __half g_qkv[M_TOK * QKVS];          // Q | K | V packed per row
__device__ __half g_at_f[M_TOK * D_MODEL];
__device__ __half g_x_f[M_TOK * D_MODEL];
__device__ __half g_ff_f[M_TOK * D_FF];
// fp16 transposed weights [N, K]  (wq,wk,wv,wo packed contiguously)
__device__ __half g_w4[4 * D_MODEL * D_MODEL];
__device__ __half g_w1[D_FF * D_MODEL];
__device__ __half g_w2[D_MODEL * D_FF];

// ======================= PTX helpers (baseline sm_103-legal only) ===========
__device__ __forceinline__ uint32_t smem_u32(const void* p) {
    uint32_t a;
    asm("{ .reg .u64 t; cvta.to.shared.u64 t, %1; cvt.u32.u64 %0, t; }" : "=r"(a) : "l"(p));
    return a;
}
__device__ __forceinline__ void cp16(uint32_t s, const void* g) {
    asm volatile("cp.async.cg.shared.global [%0], [%1], 16;" :: "r"(s), "l"(g));
}
__device__ __forceinline__ void cp4(uint32_t s, const void* g) {
    asm volatile("cp.async.ca.shared.global [%0], [%1], 4;" :: "r"(s), "l"(g));
}
#define CP_COMMIT() asm volatile("cp.async.commit_group;" ::: "memory")

__device__ __forceinline__ void ldsm4(uint32_t* r, uint32_t addr) {
    asm volatile("ldmatrix.sync.aligned.m8n8.x4.shared.b16 {%0,%1,%2,%3}, [%4];"
                 : "=r"(r[0]), "=r"(r[1]), "=r"(r[2]), "=r"(r[3]) : "r"(addr));
}
__device__ __forceinline__ void ldsm4t(uint32_t* r, uint32_t addr) {
    asm volatile("ldmatrix.sync.aligned.m8n8.x4.trans.shared.b16 {%0,%1,%2,%3}, [%4];"
                 : "=r"(r[0]), "=r"(r[1]), "=r"(r[2]), "=r"(r[3]) : "r"(addr));
}
__device__ __forceinline__ void mma16816(float* d, const uint32_t* a, uint32_t b0, uint32_t b1) {
    asm volatile(
        "mma.sync.aligned.m16n8k16.row.col.f32.f16.f16.f32 "
        "{%0,%1,%2,%3}, {%4,%5,%6,%7}, {%8,%9}, {%0,%1,%2,%3};"
        : "+f"(d[0]), "+f"(d[1]), "+f"(d[2]), "+f"(d[3])
        : "r"(a[0]), "r"(a[1]), "r"(a[2]), "r"(a[3]), "r"(b0), "r"(b1));
}
__device__ __forceinline__ uint32_t packh(float a, float b) {
    __half2 t = __floats2half2_rn(a, b);
    uint32_t u; memcpy(&u, &t, 4); return u;
}

// ======================= warp-MMA fp16 GEMM =================================
// BKC=64, SW128-swizzled 128B rows, 3 stages, ONE sync per chunk.
// MODE 0: fp32 +bias  MODE 1: gelu(+bias)->fp16  MODE 2: fp32 +bias+res
// MODE 3: +bias -> fp16
#define BM 128
#define BN 128
#define BKC 64
#define TILE_B (128 * 128)               // 16384 (128 rows x 128B, swizzled)
#define STAGE_B (2 * TILE_B)             // 32768 : A, W
#define NSTAGE 3
#define GEMM_SMEM (NSTAGE * STAGE_B)     // 98304 -> 2 CTAs/SM

__device__ __forceinline__ void g_load_chunk(
    uint32_t smem, int ci, int m0, int n0, int K, int tid,
    const __half* __restrict__ A, const __half* __restrict__ W)
{
    uint32_t sb = smem + (uint32_t)(ci % NSTAGE) * STAGE_B;
    size_t kbase = (size_t)ci * BKC;
#pragma unroll
    for (int rep = 0; rep < 8; rep++) {
        int idx = tid + (rep << 8);          // 0..2047
        int t = idx >> 10;                   // 0 = A, 1 = W
        int row = (idx >> 3) & 127;
        int seg = idx & 7;
        const __half* P = (t == 0) ? A : W;
        int r0 = (t == 0) ? m0 : n0;
        uint32_t sw = (uint32_t)((seg << 4) ^ ((row & 7) << 4));
        cp16(sb + (uint32_t)t * TILE_B + (uint32_t)(row << 7) + sw,
             P + (size_t)(r0 + row) * K + kbase + seg * 8);
    }
}

template <int MODE>
__global__ void __launch_bounds__(256, 2) tcgemm_kernel(
    const __half* __restrict__ A, const __half* __restrict__ W,
    const float* __restrict__ bias, const float* __restrict__ res,
    float* __restrict__ C, __half* __restrict__ Cf,
    int M, int N, int K)
{
    extern __shared__ char dsm[];
    uint32_t smem = smem_u32(dsm);

    int tid = threadIdx.x;
    int wid = tid >> 5;
    int lane = tid & 31;
    int m0 = blockIdx.y * BM;
    int n0 = blockIdx.x * BN;
    int nchunk = K / BKC;

    int wm = wid & 1;
    int wn = wid >> 1;
    int lr = lane & 15;
    uint32_t lk = (uint32_t)((lane >> 4) << 4);
    uint32_t swz = (uint32_t)((lr & 7) << 4);   // row&7 invariant across mt/nt (+16 rows)

    float acc[4][4][4];
#pragma unroll
    for (int i = 0; i < 4; i++)
#pragma unroll
        for (int j = 0; j < 4; j++)
#pragma unroll
            for (int c = 0; c < 4; c++) acc[i][j][c] = 0.0f;

    g_load_chunk(smem, 0, m0, n0, K, tid, A, W);
    CP_COMMIT();
    g_load_chunk(smem, 1, m0, n0, K, tid, A, W);
    CP_COMMIT();

    for (int i = 0; i < nchunk; i++) {
        if (i < nchunk - 1)
            asm volatile("cp.async.wait_group 1;" ::: "memory");
        else
            asm volatile("cp.async.wait_group 0;" ::: "memory");
        __syncthreads();

        if (i + 2 < nchunk) {
            g_load_chunk(smem, i + 2, m0, n0, K, tid, A, W);
            CP_COMMIT();
        }

        uint32_t sb = smem + (uint32_t)(i % NSTAGE) * STAGE_B;
        uint32_t aRow = sb + (uint32_t)((wm * 64 + lr) << 7);
        uint32_t bRow = sb + TILE_B + (uint32_t)((wn * 32 + lr) << 7);

#pragma unroll
        for (int ks = 0; ks < 4; ks++) {
            uint32_t col = ((uint32_t)(ks * 32) + lk) ^ swz;
            uint32_t ah[4][4];
#pragma unroll
            for (int mt = 0; mt < 4; mt++)
                ldsm4(ah[mt], aRow + (uint32_t)(mt << 11) + col);
#pragma unroll
            for (int nt = 0; nt < 2; nt++) {
                uint32_t bb[4];
                ldsm4(bb, bRow + (uint32_t)(nt << 11) + col);
#pragma unroll
                for (int mt = 0; mt < 4; mt++) {
                    mma16816(acc[mt][nt * 2],     ah[mt], bb[0], bb[2]);
                    mma16816(acc[mt][nt * 2 + 1], ah[mt], bb[1], bb[3]);
                }
            }
        }
    }

    int rbase = m0 + wm * 64 + (lane >> 2);
    int cbase = n0 + wn * 32 + (lane & 3) * 2;
#pragma unroll
    for (int mt = 0; mt < 4; mt++) {
#pragma unroll
        for (int n8 = 0; n8 < 4; n8++) {
            int col = cbase + n8 * 8;
            float b0 = bias[col], b1 = bias[col + 1];
#pragma unroll
            for (int half = 0; half < 2; half++) {
                int row = rbase + mt * 16 + half * 8;
                float v0 = acc[mt][n8][half * 2] + b0;
                float v1 = acc[mt][n8][half * 2 + 1] + b1;
                if (MODE == 1) {
                    v0 = 0.5f * v0 * (1.0f + erff(v0 * 0.70710678118654752f));
                    v1 = 0.5f * v1 * (1.0f + erff(v1 * 0.70710678118654752f));
                }
                if (MODE == 2) {
                    const float2 rv = *(const float2*)(res + (size_t)row * N + col);
                    v0 += rv.x; v1 += rv.y;
                }
                if (MODE == 0 || MODE == 2) {
                    float2 o; o.x = v0; o.y = v1;
                    *(float2*)(C + (size_t)row * N + col) = o;
                } else {
                    *(__half2*)(Cf + (size_t)row * N + col) = __floats2half2_rn(v0, v1);
                }
            }
        }
    }
}

// ======================= MMA flash attention (fp16, packed QKV) =============
#define ASTR 144
#define ATILE (64 * ASTR)
#define ASTAGE (2 * ATILE + 256)
#define ASMEM (2 * ASTAGE + 64)

__device__ __forceinline__ void a_load_chunk(
    uint32_t sm0, int ci, size_t tokb, int h, int tid,
    const __half* __restrict__ QKV, const float* __restrict__ kb)
{
    uint32_t st = sm0 + (uint32_t)(ci & 1) * ASTAGE;
    size_t rowb = tokb + (size_t)ci * 64;
#pragma unroll
    for (int r = 0; r < 4; r++) {
        int idx = tid + (r << 8);
        int t = idx >> 9;                  // 0 = K, 1 = V
        int row = (idx >> 3) & 63;
        int seg = idx & 7;
        cp16(st + (uint32_t)t * ATILE + (uint32_t)row * ASTR + (uint32_t)seg * 16,
             QKV + (rowb + row) * QKVS + (t + 1) * D_MODEL + h * HEAD_DIM + seg * 8);
    }
    if (tid < 64)
        cp4(st + 2u * ATILE + (uint32_t)tid * 4, kb + (rowb + tid) * NHEAD + h);
}

__global__ void __launch_bounds__(256, 2) attn_mma_kernel(
    const __half* __restrict__ QKV,
    const float* __restrict__ qb, const float* __restrict__ kb,
    const float* __restrict__ temp,
    __half* __restrict__ Of, float* __restrict__ ent_part)
{
    extern __shared__ char smemv[];
    uint32_t sm0 = smem_u32(smemv);
    float* red = (float*)(smemv + 2 * ASTAGE);

    int tid = threadIdx.x;
    int w = tid >> 5;
    int lane = tid & 31;
    int q0 = blockIdx.x * 128;
    int h = blockIdx.y;
    int b = blockIdx.z;
    size_t tokb = (size_t)b * L_;

    float tmph = fminf(fmaxf(temp[h], 0.1f), 5.0f);
    float inv_t = 1.0f / tmph;
    float sc = 0.125f * inv_t;

    for (int i = tid; i < 128 * 8; i += 256) {
        int row = i >> 3, seg = i & 7;
        cp16(sm0 + (uint32_t)row * ASTR + (uint32_t)seg * 16,
             QKV + (tokb + q0 + row) * QKVS + h * HEAD_DIM + seg * 8);
    }
    CP_COMMIT();
    asm volatile("cp.async.wait_group 0;" ::: "memory");
    __syncthreads();

    uint32_t qfr[4][4];
    {
        uint32_t qbase = sm0 + (uint32_t)(w * 16 + (lane & 15)) * ASTR + (uint32_t)((lane >> 4) << 4);
#pragma unroll
        for (int ks = 0; ks < 4; ks++) ldsm4(qfr[ks], qbase + ks * 32);
    }
    int gid = lane >> 2, tig = lane & 3;
    int r0 = q0 + w * 16 + gid, r1 = r0 + 8;
    float qb0 = qb[(tokb + r0) * NHEAD + h] * inv_t;
    float qb1 = qb[(tokb + r1) * NHEAD + h] * inv_t;
    __syncthreads();

    a_load_chunk(sm0, 0, tokb, h, tid, QKV, kb);
    CP_COMMIT();
    a_load_chunk(sm0, 1, tokb, h, tid, QKV, kb);
    CP_COMMIT();

    float O[8][4];
#pragma unroll
    for (int f = 0; f < 8; f++)
#pragma unroll
        for (int c = 0; c < 4; c++) O[f][c] = 0.0f;
    float m0 = -1e30f, m1 = -1e30f, z0 = 0.0f, z1 = 0.0f, t0 = 0.0f, t1 = 0.0f;

    const int NCH = L_ / 64;
    for (int ci = 0; ci < NCH; ci++) {
        if (ci < NCH - 2)
            asm volatile("cp.async.wait_group 1;" ::: "memory");
        else
            asm volatile("cp.async.wait_group 0;" ::: "memory");
        __syncthreads();

        uint32_t st = sm0 + (uint32_t)(ci & 1) * ASTAGE;
        uint32_t kbh = st + (uint32_t)(lane & 15) * ASTR + (uint32_t)((lane >> 4) << 4);

        float S[8][4];
#pragma unroll
        for (int f = 0; f < 8; f++)
#pragma unroll
            for (int c = 0; c < 4; c++) S[f][c] = 0.0f;

#pragma unroll
        for (int ks = 0; ks < 4; ks++) {
            uint32_t koff = (uint32_t)ks * 32;
#pragma unroll
            for (int nt = 0; nt < 4; nt++) {
                uint32_t bb[4];
                ldsm4(bb, kbh + (uint32_t)(nt * 16) * ASTR + koff);
                mma16816(S[nt * 2],     qfr[ks], bb[0], bb[2]);
                mma16816(S[nt * 2 + 1], qfr[ks], bb[1], bb[3]);
            }
        }

        const float* kbs = (const float*)(smemv + (size_t)((ci & 1) * ASTAGE + 2 * ATILE));
        float mx0 = -1e30f, mx1 = -1e30f;
#pragma unroll
        for (int f = 0; f < 8; f++) {
            float kc0 = kbs[f * 8 + 2 * tig] * inv_t;
            float kc1 = kbs[f * 8 + 2 * tig + 1] * inv_t;
            S[f][0] = S[f][0] * sc + qb0 + kc0;
            S[f][1] = S[f][1] * sc + qb0 + kc1;
            S[f][2] = S[f][2] * sc + qb1 + kc0;
            S[f][3] = S[f][3] * sc + qb1 + kc1;
            mx0 = fmaxf(mx0, fmaxf(S[f][0], S[f][1]));
            mx1 = fmaxf(mx1, fmaxf(S[f][2], S[f][3]));
        }
        mx0 = fmaxf(mx0, __shfl_xor_sync(0xffffffffu, mx0, 1));
        mx0 = fmaxf(mx0, __shfl_xor_sync(0xffffffffu, mx0, 2));
        mx1 = fmaxf(mx1, __shfl_xor_sync(0xffffffffu, mx1, 1));
        mx1 = fmaxf(mx1, __shfl_xor_sync(0xffffffffu, mx1, 2));

        float nm0 = fmaxf(m0, mx0), nm1 = fmaxf(m1, mx1);
        float sc0 = __expf(m0 - nm0), sc1 = __expf(m1 - nm1);
        float zc0 = 0.0f, zc1 = 0.0f, tc0 = 0.0f, tc1 = 0.0f;
        uint32_t pa[4][4];
#pragma unroll
        for (int j = 0; j < 4; j++) {
#pragma unroll
            for (int g = 0; g < 2; g++) {
                int f = 2 * j + g;
                float p0 = __expf(S[f][0] - nm0);
                float p1 = __expf(S[f][1] - nm0);
                float p2 = __expf(S[f][2] - nm1);
                float p3 = __expf(S[f][3] - nm1);
                zc0 += p0 + p1; zc1 += p2 + p3;
                tc0 += p0 * S[f][0] + p1 * S[f][1];
                tc1 += p2 * S[f][2] + p3 * S[f][3];
                pa[j][g * 2]     = packh(p0, p1);
                pa[j][g * 2 + 1] = packh(p2, p3);
            }
        }
        zc0 += __shfl_xor_sync(0xffffffffu, zc0, 1); zc0 += __shfl_xor_sync(0xffffffffu, zc0, 2);
        zc1 += __shfl_xor_sync(0xffffffffu, zc1, 1); zc1 += __shfl_xor_sync(0xffffffffu, zc1, 2);
        tc0 += __shfl_xor_sync(0xffffffffu, tc0, 1); tc0 += __shfl_xor_sync(0xffffffffu, tc0, 2);
        tc1 += __shfl_xor_sync(0xffffffffu, tc1, 1); tc1 += __shfl_xor_sync(0xffffffffu, tc1, 2);
        z0 = z0 * sc0 + zc0; t0 = t0 * sc0 + tc0; m0 = nm0;
        z1 = z1 * sc1 + zc1; t1 = t1 * sc1 + tc1; m1 = nm1;
#pragma unroll
        for (int f = 0; f < 8; f++) {
            O[f][0] *= sc0; O[f][1] *= sc0; O[f][2] *= sc1; O[f][3] *= sc1;
        }

        uint32_t vb = st + ATILE + (uint32_t)(lane & 15) * ASTR + (uint32_t)((lane >> 4) << 4);
#pragma unroll
        for (int j = 0; j < 4; j++) {
            uint32_t vrow = vb + (uint32_t)(j * 16) * ASTR;
#pragma unroll
            for (int hg = 0; hg < 4; hg++) {
                uint32_t v[4];
                ldsm4t(v, vrow + (uint32_t)hg * 32);
                mma16816(O[hg * 2],     pa[j], v[0], v[1]);
                mma16816(O[hg * 2 + 1], pa[j], v[2], v[3]);
            }
        }
        __syncthreads();
        if (ci + 2 < NCH) {
            a_load_chunk(sm0, ci + 2, tokb, h, tid, QKV, kb);
            CP_COMMIT();
        }
    }

    float iz0 = 1.0f / z0, iz1 = 1.0f / z1;
    size_t row0b = (tokb + r0) * D_MODEL, row1b = (tokb + r1) * D_MODEL;
#pragma unroll
    for (int f = 0; f < 8; f++) {
        int col = h * HEAD_DIM + f * 8 + 2 * tig;
        *(__half2*)(Of + row0b + col) = __floats2half2_rn(O[f][0] * iz0, O[f][1] * iz0);
        *(__half2*)(Of + row1b + col) = __floats2half2_rn(O[f][2] * iz1, O[f][3] * iz1);
    }

    float Hv = (m0 + logf(z0) - t0 / z0 + m1 + logf(z1) - t1 / z1) * 0.25f;
#pragma unroll
    for (int off = 16; off; off >>= 1) Hv += __shfl_xor_sync(0xffffffffu, Hv, off);
    if (lane == 0) red[w] = Hv;
    __syncthreads();
    if (tid == 0) {
        float s = 0.0f;
#pragma unroll
        for (int i = 0; i < 8; i++) s += red[i];
        ent_part[((b * NHEAD + h) << 4) + blockIdx.x] = s;
    }
}

// ======================= weight transpose (fp16) ============================
__global__ void __launch_bounds__(256) convT4_kernel(
    const float* __restrict__ W0, const float* __restrict__ W1p,
    const float* __restrict__ W2p, const float* __restrict__ W3,
    __half* __restrict__ o16)
{
    __shared__ float t[32][33];
    const float* W = (blockIdx.z == 0) ? W0 : (blockIdx.z == 1) ? W1p
                   : (blockIdx.z == 2) ? W2p : W3;
    __half* dst = o16 + (size_t)blockIdx.z * D_MODEL * D_MODEL;
    int n0 = blockIdx.x * 32, k0 = blockIdx.y * 32;
    int tx = threadIdx.x & 31, ty = threadIdx.x >> 5;
#pragma unroll
    for (int i = 0; i < 32; i += 8)
        t[ty + i][tx] = W[(size_t)(k0 + ty + i) * D_MODEL + n0 + tx];
    __syncthreads();
#pragma unroll
    for (int i = 0; i < 32; i += 8)
        dst[(size_t)(n0 + ty + i) * D_MODEL + k0 + tx] = __float2half_rn(t[tx][ty + i]);
}

__global__ void __launch_bounds__(256) convT_kernel(
    const float* __restrict__ W, __half* __restrict__ o16, int K, int N)
{
    __shared__ float t[32][33];
    int n0 = blockIdx.x * 32, k0 = blockIdx.y * 32;
    int tx = threadIdx.x & 31, ty = threadIdx.x >> 5;
#pragma unroll
    for (int i = 0; i < 32; i += 8)
        t[ty + i][tx] = W[(size_t)(k0 + ty + i) * N + n0 + tx];
    __syncthreads();
#pragma unroll
    for (int i = 0; i < 32; i += 8)
        o16[(size_t)(n0 + ty + i) * K + k0 + tx] = __float2half_rn(t[tx][ty + i]);
}

__global__ void __launch_bounds__(256) conv_kernel(
    const float* __restrict__ in, __half* __restrict__ outp, int n4)
{
    int i = blockIdx.x * 256 + threadIdx.x;
    if (i >= n4) return;
    float4 v = ((const float4*)in)[i];
    ((__half2*)outp)[i * 2]     = __floats2half2_rn(v.x, v.y);
    ((__half2*)outp)[i * 2 + 1] = __floats2half2_rn(v.z, v.w);
}

// ---------------- POS bias MLPs ----------------------------------------------
__global__ void __launch_bounds__(128) posbias_kernel(
    const float* __restrict__ pos,
    const float* __restrict__ qw1, const float* __restrict__ qb1,
    const float* __restrict__ qw2, const float* __restrict__ qb2,
    const float* __restrict__ kw1, const float* __restrict__ kb1,
    const float* __restrict__ kw2, const float* __restrict__ kb2,
    float* __restrict__ qbias, float* __restrict__ kbias)
{
    __shared__ float sw1q[32 * 32], sw2q[32 * 16], sb1q[32], sb2q[16];
    __shared__ float sw1k[32 * 32], sw2k[32 * 16], sb1k[32], sb2k[16];
    int tid = threadIdx.x;
    for (int i = tid; i < 1024; i += 128) { sw1q[i] = qw1[i]; sw1k[i] = kw1[i]; }
    for (int i = tid; i < 512;  i += 128) { sw2q[i] = qw2[i]; sw2k[i] = kw2[i]; }
    if (tid < 32) { sb1q[tid] = qb1[tid]; sb1k[tid] = kb1[tid]; }
    if (tid < 16) { sb2q[tid] = qb2[tid]; sb2k[tid] = kb2[tid]; }
    __syncthreads();

    int token = blockIdx.x * 128 + tid;
    float pf[32];
#pragma unroll
    for (int i = 0; i < 32; i++) pf[i] = pos[(size_t)token * 32 + i];

    float hq[32], hk[32];
#pragma unroll
    for (int j = 0; j < 32; j++) { hq[j] = sb1q[j]; hk[j] = sb1k[j]; }
    for (int i = 0; i < 32; i++) {
        float p = pf[i];
#pragma unroll
        for (int j = 0; j < 32; j++) {
            hq[j] += p * sw1q[i * 32 + j];
            hk[j] += p * sw1k[i * 32 + j];
        }
    }
#pragma unroll
    for (int j = 0; j < 32; j++) {
        hq[j] = fmaxf(hq[j], 0.0f);
        hk[j] = fmaxf(hk[j], 0.0f);
    }
#pragma unroll
    for (int h = 0; h < 16; h++) {
        float oq = sb2q[h], ok = sb2k[h];
        for (int j = 0; j < 32; j++) {
            oq += hq[j] * sw2q[j * 16 + h];
            ok += hk[j] * sw2k[j * 16 + h];
        }
        qbias[(size_t)token * NHEAD + h] = oq;
        kbias[(size_t)token * NHEAD + h] = ok;
    }
}

// ---------------- layernorm (optionally emits fp16) --------------------------
template <int SPLIT>
__global__ void __launch_bounds__(256) ln_kernel(
    const float* __restrict__ in, const float* __restrict__ gam,
    const float* __restrict__ bet, float* __restrict__ out,
    __half* __restrict__ of)
{
    int row = blockIdx.x, tid = threadIdx.x;
    float4 v = ((const float4*)(in + (size_t)row * D_MODEL))[tid];
    float s = v.x + v.y + v.z + v.w;
    float q = v.x * v.x + v.y * v.y + v.z * v.z + v.w * v.w;
#pragma unroll
    for (int off = 16; off; off >>= 1) {
        s += __shfl_xor_sync(0xffffffffu, s, off);
        q += __shfl_xor_sync(0xffffffffu, q, off);
    }
    __shared__ float ws[8], wq[8], stats[2];
    int lane = tid & 31, w = tid >> 5;
    if (lane == 0) { ws[w] = s; wq[w] = q; }
    __syncthreads();
    if (tid == 0) {
        float S = 0.0f, Qq = 0.0f;
        for (int i = 0; i < 8; i++) { S += ws[i]; Qq += wq[i]; }
        float mu  = S * (1.0f / D_MODEL);
        float var = Qq * (1.0f / D_MODEL) - mu * mu;
        stats[0] = mu;
        stats[1] = rsqrtf(var + 1e-5f);
    }
    __syncthreads();
    float mu = stats[0], rs = stats[1];
    float4 gv = ((const float4*)gam)[tid];
    float4 bv = ((const float4*)bet)[tid];
    float4 ov;
    ov.x = (v.x - mu) * rs * gv.x + bv.x;
    ov.y = (v.y - mu) * rs * gv.y + bv.y;
    ov.z = (v.z - mu) * rs * gv.z + bv.z;
    ov.w = (v.w - mu) * rs * gv.w + bv.w;
    ((float4*)(out + (size_t)row * D_MODEL))[tid] = ov;
    if (SPLIT) {
        size_t base = (size_t)row * D_MODEL + tid * 4;
        *(__half2*)(of + base)     = __floats2half2_rn(ov.x, ov.y);
        *(__half2*)(of + base + 2) = __floats2half2_rn(ov.z, ov.w);
    }
}

// ---------------- deterministic entropy reduction ----------------------------
__global__ void __launch_bounds__(256) ent_final_kernel(
    const float* __restrict__ part, float* __restrict__ out, int out_size)
{
    __shared__ float sm[256];
    int tid = threadIdx.x;
    sm[tid] = part[tid] + part[tid + 256];
    __syncthreads();
    for (int off = 128; off; off >>= 1) {
        if (tid < off) sm[tid] += sm[tid + off];
        __syncthreads();
    }
    if (tid == 0 && out_size > OUT_MAIN)
        out[OUT_MAIN] = sm[0] * (1.0f / (B_ * NHEAD * L_));
}

// ---------------- launch -----------------------------------------------------
extern "C" void kernel_launch(void* const* d_in, const int* in_sizes, int n_in,
                              void* d_out, int out_size)
{
    const float* src   = (const float*)d_in[0];
    const float* pos   = (const float*)d_in[1];
    const float* Wq    = (const float*)d_in[2];
    const float* bq    = (const float*)d_in[3];
    const float* Wk    = (const float*)d_in[4];
    const float* bk    = (const float*)d_in[5];
    const float* Wv    = (const float*)d_in[6];
    const float* bv    = (const float*)d_in[7];
    const float* Wo    = (const float*)d_in[8];
    const float* bo    = (const float*)d_in[9];
    const float* pq_w1 = (const float*)d_in[10];
    const float* pq_b1 = (const float*)d_in[11];
    const float* pq_w2 = (const float*)d_in[12];
    const float* pq_b2 = (const float*)d_in[13];
    const float* pk_w1 = (const float*)d_in[14];
    const float* pk_b1 = (const float*)d_in[15];
    const float* pk_w2 = (const float*)d_in[16];
    const float* pk_b2 = (const float*)d_in[17];
    const float* temp  = (const float*)d_in[18];
    const float* ln1g  = (const float*)d_in[19];
    const float* ln1b  = (const float*)d_in[20];
    const float* ln2g  = (const float*)d_in[21];
    const float* ln2b  = (const float*)d_in[22];
    const float* W1    = (const float*)d_in[23];
    const float* b1    = (const float*)d_in[24];
    const float* W2    = (const float*)d_in[25];
    const float* b2    = (const float*)d_in[26];
    float* out = (float*)d_out;

    float *xb, *yb, *qbb, *kbb, *entp, *bqkv;
    cudaGetSymbolAddress((void**)&xb, g_x);
    cudaGetSymbolAddress((void**)&yb, g_y);
    cudaGetSymbolAddress((void**)&qbb, g_qbias);
    cudaGetSymbolAddress((void**)&kbb, g_kbias);
    cudaGetSymbolAddress((void**)&entp, g_entpart);
    cudaGetSymbolAddress((void**)&bqkv, g_bqkv);

    __half *srcf, *qkv, *atf, *xf, *fff;
    __half *w4, *w116, *w216;
    cudaGetSymbolAddress((void**)&srcf, g_src_f);
    cudaGetSymbolAddress((void**)&qkv, g_qkv);
    cudaGetSymbolAddress((void**)&atf, g_at_f);
    cudaGetSymbolAddress((void**)&xf, g_x_f);
    cudaGetSymbolAddress((void**)&fff, g_ff_f);
    cudaGetSymbolAddress((void**)&w4, g_w4);
    cudaGetSymbolAddress((void**)&w116, g_w1);
    cudaGetSymbolAddress((void**)&w216, g_w2);

    __half* wo16 = w4 + 3 * (size_t)D_MODEL * D_MODEL;

    cudaFuncSetAttribute(tcgemm_kernel<1>, cudaFuncAttributeMaxDynamicSharedMemorySize, GEMM_SMEM);
    cudaFuncSetAttribute(tcgemm_kernel<2>, cudaFuncAttributeMaxDynamicSharedMemorySize, GEMM_SMEM);
    cudaFuncSetAttribute(tcgemm_kernel<3>, cudaFuncAttributeMaxDynamicSharedMemorySize, GEMM_SMEM);
    cudaFuncSetAttribute(attn_mma_kernel, cudaFuncAttributeMaxDynamicSharedMemorySize, ASMEM);

    // concat QKV biases (capturable D2D async copies)
    cudaMemcpyAsync(bqkv,                bq, D_MODEL * sizeof(float), cudaMemcpyDeviceToDevice);
    cudaMemcpyAsync(bqkv + D_MODEL,      bk, D_MODEL * sizeof(float), cudaMemcpyDeviceToDevice);
    cudaMemcpyAsync(bqkv + 2 * D_MODEL,  bv, D_MODEL * sizeof(float), cudaMemcpyDeviceToDevice);

    convT4_kernel<<<dim3(32, 32, 4), 256>>>(Wq, Wk, Wv, Wo, w4);
    convT_kernel<<<dim3(D_FF / 32, D_MODEL / 32), 256>>>(W1, w116, D_MODEL, D_FF);
    convT_kernel<<<dim3(D_MODEL / 32, D_FF / 32), 256>>>(W2, w216, D_FF, D_MODEL);

    conv_kernel<<<(M_TOK * D_MODEL / 4 + 255) / 256, 256>>>(src, srcf, M_TOK * D_MODEL / 4);
    posbias_kernel<<<M_TOK / 128, 128>>>(pos, pq_w1, pq_b1, pq_w2, pq_b2,
                                         pk_w1, pk_b1, pk_w2, pk_b2, qbb, kbb);

    // fused QKV projection
    dim3 gQKV(QKVS / BN, M_TOK / BM);
    tcgemm_kernel<3><<<gQKV, 256, GEMM_SMEM>>>(srcf, w4, bqkv, (const float*)0,
                                               (float*)0, qkv, M_TOK, QKVS, D_MODEL);

    attn_mma_kernel<<<dim3(L_ / 128, NHEAD, B_), 256, ASMEM>>>(
        qkv, qbb, kbb, temp, atf, entp);

    dim3 gD(D_MODEL / BN, M_TOK / BM);
    tcgemm_kernel<2><<<gD, 256, GEMM_SMEM>>>(atf, wo16, bo, src,
                                             yb, (__half*)0, M_TOK, D_MODEL, D_MODEL);
    ln_kernel<1><<<M_TOK, 256>>>(yb, ln1g, ln1b, xb, xf);

    dim3 gF(D_FF / BN, M_TOK / BM);
    tcgemm_kernel<1><<<gF, 256, GEMM_SMEM>>>(xf, w116, b1, (const float*)0,
                                             (float*)0, fff, M_TOK, D_FF, D_MODEL);
    tcgemm_kernel<2><<<gD, 256, GEMM_SMEM>>>(fff, w216, b2, xb,
                                             yb, (__half*)0, M_TOK, D_MODEL, D_FF);
    ln_kernel<0><<<M_TOK, 256>>>(yb, ln2g, ln2b, out, (__half*)0);

    ent_final_kernel<<<1, 256>>>(entp, out, out_size);
}

// round 13
// speedup vs baseline: 7.6335x; 1.0077x over previous
#include <cuda_runtime.h>
#include <cuda_fp16.h>
#include <math.h>
#include <stdint.h>
#include <string.h>

#define D_MODEL 1024
#define NHEAD 16
#define HEAD_DIM 64
#define B_ 2
#define L_ 2048
#define M_TOK 4096
#define D_FF 4096
#define QKVS 3072
#define OUT_MAIN (M_TOK * D_MODEL)

// ---------------- scratch (device globals; no allocations allowed) ----------
__device__ float g_x[M_TOK * D_MODEL];
__device__ float g_y[M_TOK * D_MODEL];
__device__ float g_qbias[M_TOK * NHEAD];
__device__ float g_kbias[M_TOK * NHEAD];
__device__ float g_bqkv[QKVS];
__device__ float g_entpart[1024];
// fp16 activations
__device__ __half g_src_f[M_TOK * D_MODEL];
__device__ __half g_qkv[M_TOK * QKVS];          // Q | K | V packed per row
__device__ __half g_at_f[M_TOK * D_MODEL];
__device__ __half g_x_f[M_TOK * D_MODEL];
__device__ __half g_ff_f[M_TOK * D_FF];
// fp16 transposed weights [N, K]  (wq,wk,wv,wo packed contiguously)
__device__ __half g_w4[4 * D_MODEL * D_MODEL];
__device__ __half g_w1[D_FF * D_MODEL];
__device__ __half g_w2[D_MODEL * D_FF];

// ======================= PTX helpers (baseline sm_103-legal only) ===========
__device__ __forceinline__ uint32_t smem_u32(const void* p) {
    uint32_t a;
    asm("{ .reg .u64 t; cvta.to.shared.u64 t, %1; cvt.u32.u64 %0, t; }" : "=r"(a) : "l"(p));
    return a;
}
__device__ __forceinline__ void cp16(uint32_t s, const void* g) {
    asm volatile("cp.async.cg.shared.global [%0], [%1], 16;" :: "r"(s), "l"(g));
}
__device__ __forceinline__ void cp4(uint32_t s, const void* g) {
    asm volatile("cp.async.ca.shared.global [%0], [%1], 4;" :: "r"(s), "l"(g));
}
#define CP_COMMIT() asm volatile("cp.async.commit_group;" ::: "memory")

__device__ __forceinline__ void ldsm4(uint32_t* r, uint32_t addr) {
    asm volatile("ldmatrix.sync.aligned.m8n8.x4.shared.b16 {%0,%1,%2,%3}, [%4];"
                 : "=r"(r[0]), "=r"(r[1]), "=r"(r[2]), "=r"(r[3]) : "r"(addr));
}
__device__ __forceinline__ void ldsm4t(uint32_t* r, uint32_t addr) {
    asm volatile("ldmatrix.sync.aligned.m8n8.x4.trans.shared.b16 {%0,%1,%2,%3}, [%4];"
                 : "=r"(r[0]), "=r"(r[1]), "=r"(r[2]), "=r"(r[3]) : "r"(addr));
}
__device__ __forceinline__ void mma16816(float* d, const uint32_t* a, uint32_t b0, uint32_t b1) {
    asm volatile(
        "mma.sync.aligned.m16n8k16.row.col.f32.f16.f16.f32 "
        "{%0,%1,%2,%3}, {%4,%5,%6,%7}, {%8,%9}, {%0,%1,%2,%3};"
        : "+f"(d[0]), "+f"(d[1]), "+f"(d[2]), "+f"(d[3])
        : "r"(a[0]), "r"(a[1]), "r"(a[2]), "r"(a[3]), "r"(b0), "r"(b1));
}
__device__ __forceinline__ uint32_t packh(float a, float b) {
    __half2 t = __floats2half2_rn(a, b);
    uint32_t u; memcpy(&u, &t, 4); return u;
}

// ======================= warp-MMA fp16 GEMM =================================
// BKC=64, SW128-swizzled 128B rows, 3 stages, ONE sync per chunk.
// MODE 0: fp32 +bias  MODE 1: gelu(+bias)->fp16  MODE 2: fp32 +bias+res
// MODE 3: +bias -> fp16
#define BM 128
#define BN 128
#define BKC 64
#define TILE_B (128 * 128)
#define STAGE_B (2 * TILE_B)
#define NSTAGE 3
#define GEMM_SMEM (NSTAGE * STAGE_B)

__device__ __forceinline__ void g_load_chunk(
    uint32_t smem, int ci, int m0, int n0, int K, int tid,
    const __half* __restrict__ A, const __half* __restrict__ W)
{
    uint32_t sb = smem + (uint32_t)(ci % NSTAGE) * STAGE_B;
    size_t kbase = (size_t)ci * BKC;
#pragma unroll
    for (int rep = 0; rep < 8; rep++) {
        int idx = tid + (rep << 8);
        int t = idx >> 10;
        int row = (idx >> 3) & 127;
        int seg = idx & 7;
        const __half* P = (t == 0) ? A : W;
        int r0 = (t == 0) ? m0 : n0;
        uint32_t sw = (uint32_t)((seg << 4) ^ ((row & 7) << 4));
        cp16(sb + (uint32_t)t * TILE_B + (uint32_t)(row << 7) + sw,
             P + (size_t)(r0 + row) * K + kbase + seg * 8);
    }
}

template <int MODE>
__global__ void __launch_bounds__(256, 2) tcgemm_kernel(
    const __half* __restrict__ A, const __half* __restrict__ W,
    const float* __restrict__ bias, const float* __restrict__ res,
    float* __restrict__ C, __half* __restrict__ Cf,
    int M, int N, int K)
{
    extern __shared__ char dsm[];
    uint32_t smem = smem_u32(dsm);

    int tid = threadIdx.x;
    int wid = tid >> 5;
    int lane = tid & 31;
    int m0 = blockIdx.y * BM;
    int n0 = blockIdx.x * BN;
    int nchunk = K / BKC;

    int wm = wid & 1;
    int wn = wid >> 1;
    int lr = lane & 15;
    uint32_t lk = (uint32_t)((lane >> 4) << 4);
    uint32_t swz = (uint32_t)((lr & 7) << 4);

    float acc[4][4][4];
#pragma unroll
    for (int i = 0; i < 4; i++)
#pragma unroll
        for (int j = 0; j < 4; j++)
#pragma unroll
            for (int c = 0; c < 4; c++) acc[i][j][c] = 0.0f;

    g_load_chunk(smem, 0, m0, n0, K, tid, A, W);
    CP_COMMIT();
    g_load_chunk(smem, 1, m0, n0, K, tid, A, W);
    CP_COMMIT();

    for (int i = 0; i < nchunk; i++) {
        if (i < nchunk - 1)
            asm volatile("cp.async.wait_group 1;" ::: "memory");
        else
            asm volatile("cp.async.wait_group 0;" ::: "memory");
        __syncthreads();

        if (i + 2 < nchunk) {
            g_load_chunk(smem, i + 2, m0, n0, K, tid, A, W);
            CP_COMMIT();
        }

        uint32_t sb = smem + (uint32_t)(i % NSTAGE) * STAGE_B;
        uint32_t aRow = sb + (uint32_t)((wm * 64 + lr) << 7);
        uint32_t bRow = sb + TILE_B + (uint32_t)((wn * 32 + lr) << 7);

#pragma unroll
        for (int ks = 0; ks < 4; ks++) {
            uint32_t col = ((uint32_t)(ks * 32) + lk) ^ swz;
            uint32_t ah[4][4];
#pragma unroll
            for (int mt = 0; mt < 4; mt++)
                ldsm4(ah[mt], aRow + (uint32_t)(mt << 11) + col);
#pragma unroll
            for (int nt = 0; nt < 2; nt++) {
                uint32_t bb[4];
                ldsm4(bb, bRow + (uint32_t)(nt << 11) + col);
#pragma unroll
                for (int mt = 0; mt < 4; mt++) {
                    mma16816(acc[mt][nt * 2],     ah[mt], bb[0], bb[2]);
                    mma16816(acc[mt][nt * 2 + 1], ah[mt], bb[1], bb[3]);
                }
            }
        }
    }

    int rbase = m0 + wm * 64 + (lane >> 2);
    int cbase = n0 + wn * 32 + (lane & 3) * 2;
#pragma unroll
    for (int mt = 0; mt < 4; mt++) {
#pragma unroll
        for (int n8 = 0; n8 < 4; n8++) {
            int col = cbase + n8 * 8;
            float b0 = bias[col], b1 = bias[col + 1];
#pragma unroll
            for (int half = 0; half < 2; half++) {
                int row = rbase + mt * 16 + half * 8;
                float v0 = acc[mt][n8][half * 2] + b0;
                float v1 = acc[mt][n8][half * 2 + 1] + b1;
                if (MODE == 1) {
                    v0 = 0.5f * v0 * (1.0f + erff(v0 * 0.70710678118654752f));
                    v1 = 0.5f * v1 * (1.0f + erff(v1 * 0.70710678118654752f));
                }
                if (MODE == 2) {
                    const float2 rv = *(const float2*)(res + (size_t)row * N + col);
                    v0 += rv.x; v1 += rv.y;
                }
                if (MODE == 0 || MODE == 2) {
                    float2 o; o.x = v0; o.y = v1;
                    *(float2*)(C + (size_t)row * N + col) = o;
                } else {
                    *(__half2*)(Cf + (size_t)row * N + col) = __floats2half2_rn(v0, v1);
                }
            }
        }
    }
}

// ======================= MMA flash attention ================================
// 3-stage K/V pipeline, ONE sync per chunk (GEMM-style schedule).
#define ASTR 144
#define ATILE (64 * ASTR)
#define ASTAGE (2 * ATILE + 256)
#define ANST 3
#define ASMEM (ANST * ASTAGE + 64)

__device__ __forceinline__ void a_load_chunk(
    uint32_t sm0, int ci, size_t tokb, int h, int tid,
    const __half* __restrict__ QKV, const float* __restrict__ kb)
{
    uint32_t st = sm0 + (uint32_t)(ci % ANST) * ASTAGE;
    size_t rowb = tokb + (size_t)ci * 64;
#pragma unroll
    for (int r = 0; r < 4; r++) {
        int idx = tid + (r << 8);
        int t = idx >> 9;                  // 0 = K, 1 = V
        int row = (idx >> 3) & 63;
        int seg = idx & 7;
        cp16(st + (uint32_t)t * ATILE + (uint32_t)row * ASTR + (uint32_t)seg * 16,
             QKV + (rowb + row) * QKVS + (t + 1) * D_MODEL + h * HEAD_DIM + seg * 8);
    }
    if (tid < 64)
        cp4(st + 2u * ATILE + (uint32_t)tid * 4, kb + (rowb + tid) * NHEAD + h);
}

__global__ void __launch_bounds__(256, 2) attn_mma_kernel(
    const __half* __restrict__ QKV,
    const float* __restrict__ qb, const float* __restrict__ kb,
    const float* __restrict__ temp,
    __half* __restrict__ Of, float* __restrict__ ent_part)
{
    extern __shared__ char smemv[];
    uint32_t sm0 = smem_u32(smemv);
    float* red = (float*)(smemv + ANST * ASTAGE);

    int tid = threadIdx.x;
    int w = tid >> 5;
    int lane = tid & 31;
    int q0 = blockIdx.x * 128;
    int h = blockIdx.y;
    int b = blockIdx.z;
    size_t tokb = (size_t)b * L_;

    float tmph = fminf(fmaxf(temp[h], 0.1f), 5.0f);
    float inv_t = 1.0f / tmph;
    float sc = 0.125f * inv_t;

    // stage Q via stage-0 area first (before K/V pipeline starts)
    for (int i = tid; i < 128 * 8; i += 256) {
        int row = i >> 3, seg = i & 7;
        cp16(sm0 + (uint32_t)row * ASTR + (uint32_t)seg * 16,
             QKV + (tokb + q0 + row) * QKVS + h * HEAD_DIM + seg * 8);
    }
    CP_COMMIT();
    asm volatile("cp.async.wait_group 0;" ::: "memory");
    __syncthreads();

    uint32_t qfr[4][4];
    {
        uint32_t qbase = sm0 + (uint32_t)(w * 16 + (lane & 15)) * ASTR + (uint32_t)((lane >> 4) << 4);
#pragma unroll
        for (int ks = 0; ks < 4; ks++) ldsm4(qfr[ks], qbase + ks * 32);
    }
    int gid = lane >> 2, tig = lane & 3;
    int r0 = q0 + w * 16 + gid, r1 = r0 + 8;
    float qb0 = qb[(tokb + r0) * NHEAD + h] * inv_t;
    float qb1 = qb[(tokb + r1) * NHEAD + h] * inv_t;
    __syncthreads();   // done reading Q smem before K/V chunk 0 overwrites

    a_load_chunk(sm0, 0, tokb, h, tid, QKV, kb);
    CP_COMMIT();
    a_load_chunk(sm0, 1, tokb, h, tid, QKV, kb);
    CP_COMMIT();

    float O[8][4];
#pragma unroll
    for (int f = 0; f < 8; f++)
#pragma unroll
        for (int c = 0; c < 4; c++) O[f][c] = 0.0f;
    float m0 = -1e30f, m1 = -1e30f, z0 = 0.0f, z1 = 0.0f, t0 = 0.0f, t1 = 0.0f;

    const int NCH = L_ / 64;
    for (int ci = 0; ci < NCH; ci++) {
        if (ci < NCH - 1)
            asm volatile("cp.async.wait_group 1;" ::: "memory");
        else
            asm volatile("cp.async.wait_group 0;" ::: "memory");
        __syncthreads();

        if (ci + 2 < NCH) {
            a_load_chunk(sm0, ci + 2, tokb, h, tid, QKV, kb);
            CP_COMMIT();
        }

        uint32_t st = sm0 + (uint32_t)(ci % ANST) * ASTAGE;
        uint32_t kbh = st + (uint32_t)(lane & 15) * ASTR + (uint32_t)((lane >> 4) << 4);

        float S[8][4];
#pragma unroll
        for (int f = 0; f < 8; f++)
#pragma unroll
            for (int c = 0; c < 4; c++) S[f][c] = 0.0f;

#pragma unroll
        for (int ks = 0; ks < 4; ks++) {
            uint32_t koff = (uint32_t)ks * 32;
#pragma unroll
            for (int nt = 0; nt < 4; nt++) {
                uint32_t bb[4];
                ldsm4(bb, kbh + (uint32_t)(nt * 16) * ASTR + koff);
                mma16816(S[nt * 2],     qfr[ks], bb[0], bb[2]);
                mma16816(S[nt * 2 + 1], qfr[ks], bb[1], bb[3]);
            }
        }

        const float* kbs = (const float*)(smemv + (size_t)((ci % ANST) * ASTAGE + 2 * ATILE));
        float mx0 = -1e30f, mx1 = -1e30f;
#pragma unroll
        for (int f = 0; f < 8; f++) {
            float kc0 = kbs[f * 8 + 2 * tig] * inv_t;
            float kc1 = kbs[f * 8 + 2 * tig + 1] * inv_t;
            S[f][0] = S[f][0] * sc + qb0 + kc0;
            S[f][1] = S[f][1] * sc + qb0 + kc1;
            S[f][2] = S[f][2] * sc + qb1 + kc0;
            S[f][3] = S[f][3] * sc + qb1 + kc1;
            mx0 = fmaxf(mx0, fmaxf(S[f][0], S[f][1]));
            mx1 = fmaxf(mx1, fmaxf(S[f][2], S[f][3]));
        }
        mx0 = fmaxf(mx0, __shfl_xor_sync(0xffffffffu, mx0, 1));
        mx0 = fmaxf(mx0, __shfl_xor_sync(0xffffffffu, mx0, 2));
        mx1 = fmaxf(mx1, __shfl_xor_sync(0xffffffffu, mx1, 1));
        mx1 = fmaxf(mx1, __shfl_xor_sync(0xffffffffu, mx1, 2));

        float nm0 = fmaxf(m0, mx0), nm1 = fmaxf(m1, mx1);
        float sc0 = __expf(m0 - nm0), sc1 = __expf(m1 - nm1);
        float zc0 = 0.0f, zc1 = 0.0f, tc0 = 0.0f, tc1 = 0.0f;
        uint32_t pa[4][4];
#pragma unroll
        for (int j = 0; j < 4; j++) {
#pragma unroll
            for (int g = 0; g < 2; g++) {
                int f = 2 * j + g;
                float p0 = __expf(S[f][0] - nm0);
                float p1 = __expf(S[f][1] - nm0);
                float p2 = __expf(S[f][2] - nm1);
                float p3 = __expf(S[f][3] - nm1);
                zc0 += p0 + p1; zc1 += p2 + p3;
                tc0 += p0 * S[f][0] + p1 * S[f][1];
                tc1 += p2 * S[f][2] + p3 * S[f][3];
                pa[j][g * 2]     = packh(p0, p1);
                pa[j][g * 2 + 1] = packh(p2, p3);
            }
        }
        zc0 += __shfl_xor_sync(0xffffffffu, zc0, 1); zc0 += __shfl_xor_sync(0xffffffffu, zc0, 2);
        zc1 += __shfl_xor_sync(0xffffffffu, zc1, 1); zc1 += __shfl_xor_sync(0xffffffffu, zc1, 2);
        tc0 += __shfl_xor_sync(0xffffffffu, tc0, 1); tc0 += __shfl_xor_sync(0xffffffffu, tc0, 2);
        tc1 += __shfl_xor_sync(0xffffffffu, tc1, 1); tc1 += __shfl_xor_sync(0xffffffffu, tc1, 2);
        z0 = z0 * sc0 + zc0; t0 = t0 * sc0 + tc0; m0 = nm0;
        z1 = z1 * sc1 + zc1; t1 = t1 * sc1 + tc1; m1 = nm1;
#pragma unroll
        for (int f = 0; f < 8; f++) {
            O[f][0] *= sc0; O[f][1] *= sc0; O[f][2] *= sc1; O[f][3] *= sc1;
        }

        uint32_t vb = st + ATILE + (uint32_t)(lane & 15) * ASTR + (uint32_t)((lane >> 4) << 4);
#pragma unroll
        for (int j = 0; j < 4; j++) {
            uint32_t vrow = vb + (uint32_t)(j * 16) * ASTR;
#pragma unroll
            for (int hg = 0; hg < 4; hg++) {
                uint32_t v[4];
                ldsm4t(v, vrow + (uint32_t)hg * 32);
                mma16816(O[hg * 2],     pa[j], v[0], v[1]);
                mma16816(O[hg * 2 + 1], pa[j], v[2], v[3]);
            }
        }
    }

    float iz0 = 1.0f / z0, iz1 = 1.0f / z1;
    size_t row0b = (tokb + r0) * D_MODEL, row1b = (tokb + r1) * D_MODEL;
#pragma unroll
    for (int f = 0; f < 8; f++) {
        int col = h * HEAD_DIM + f * 8 + 2 * tig;
        *(__half2*)(Of + row0b + col) = __floats2half2_rn(O[f][0] * iz0, O[f][1] * iz0);
        *(__half2*)(Of + row1b + col) = __floats2half2_rn(O[f][2] * iz1, O[f][3] * iz1);
    }

    float Hv = (m0 + logf(z0) - t0 / z0 + m1 + logf(z1) - t1 / z1) * 0.25f;
#pragma unroll
    for (int off = 16; off; off >>= 1) Hv += __shfl_xor_sync(0xffffffffu, Hv, off);
    if (lane == 0) red[w] = Hv;
    __syncthreads();
    if (tid == 0) {
        float s = 0.0f;
#pragma unroll
        for (int i = 0; i < 8; i++) s += red[i];
        ent_part[((b * NHEAD + h) << 4) + blockIdx.x] = s;
    }
}

// ======================= weight transpose (fp16) ============================
__global__ void __launch_bounds__(256) convT4_kernel(
    const float* __restrict__ W0, const float* __restrict__ W1p,
    const float* __restrict__ W2p, const float* __restrict__ W3,
    __half* __restrict__ o16)
{
    __shared__ float t[32][33];
    const float* W = (blockIdx.z == 0) ? W0 : (blockIdx.z == 1) ? W1p
                   : (blockIdx.z == 2) ? W2p : W3;
    __half* dst = o16 + (size_t)blockIdx.z * D_MODEL * D_MODEL;
    int n0 = blockIdx.x * 32, k0 = blockIdx.y * 32;
    int tx = threadIdx.x & 31, ty = threadIdx.x >> 5;
#pragma unroll
    for (int i = 0; i < 32; i += 8)
        t[ty + i][tx] = W[(size_t)(k0 + ty + i) * D_MODEL + n0 + tx];
    __syncthreads();
#pragma unroll
    for (int i = 0; i < 32; i += 8)
        dst[(size_t)(n0 + ty + i) * D_MODEL + k0 + tx] = __float2half_rn(t[tx][ty + i]);
}

__global__ void __launch_bounds__(256) convT_kernel(
    const float* __restrict__ W, __half* __restrict__ o16, int K, int N)
{
    __shared__ float t[32][33];
    int n0 = blockIdx.x * 32, k0 = blockIdx.y * 32;
    int tx = threadIdx.x & 31, ty = threadIdx.x >> 5;
#pragma unroll
    for (int i = 0; i < 32; i += 8)
        t[ty + i][tx] = W[(size_t)(k0 + ty + i) * N + n0 + tx];
    __syncthreads();
#pragma unroll
    for (int i = 0; i < 32; i += 8)
        o16[(size_t)(n0 + ty + i) * K + k0 + tx] = __float2half_rn(t[tx][ty + i]);
}

__global__ void __launch_bounds__(256) conv_kernel(
    const float* __restrict__ in, __half* __restrict__ outp, int n4)
{
    int i = blockIdx.x * 256 + threadIdx.x;
    if (i >= n4) return;
    float4 v = ((const float4*)in)[i];
    ((__half2*)outp)[i * 2]     = __floats2half2_rn(v.x, v.y);
    ((__half2*)outp)[i * 2 + 1] = __floats2half2_rn(v.z, v.w);
}

// ---------------- POS bias MLPs ----------------------------------------------
__global__ void __launch_bounds__(128) posbias_kernel(
    const float* __restrict__ pos,
    const float* __restrict__ qw1, const float* __restrict__ qb1,
    const float* __restrict__ qw2, const float* __restrict__ qb2,
    const float* __restrict__ kw1, const float* __restrict__ kb1,
    const float* __restrict__ kw2, const float* __restrict__ kb2,
    float* __restrict__ qbias, float* __restrict__ kbias)
{
    __shared__ float sw1q[32 * 32], sw2q[32 * 16], sb1q[32], sb2q[16];
    __shared__ float sw1k[32 * 32], sw2k[32 * 16], sb1k[32], sb2k[16];
    int tid = threadIdx.x;
    for (int i = tid; i < 1024; i += 128) { sw1q[i] = qw1[i]; sw1k[i] = kw1[i]; }
    for (int i = tid; i < 512;  i += 128) { sw2q[i] = qw2[i]; sw2k[i] = kw2[i]; }
    if (tid < 32) { sb1q[tid] = qb1[tid]; sb1k[tid] = kb1[tid]; }
    if (tid < 16) { sb2q[tid] = qb2[tid]; sb2k[tid] = kb2[tid]; }
    __syncthreads();

    int token = blockIdx.x * 128 + tid;
    float pf[32];
#pragma unroll
    for (int i = 0; i < 32; i++) pf[i] = pos[(size_t)token * 32 + i];

    float hq[32], hk[32];
#pragma unroll
    for (int j = 0; j < 32; j++) { hq[j] = sb1q[j]; hk[j] = sb1k[j]; }
    for (int i = 0; i < 32; i++) {
        float p = pf[i];
#pragma unroll
        for (int j = 0; j < 32; j++) {
            hq[j] += p * sw1q[i * 32 + j];
            hk[j] += p * sw1k[i * 32 + j];
        }
    }
#pragma unroll
    for (int j = 0; j < 32; j++) {
        hq[j] = fmaxf(hq[j], 0.0f);
        hk[j] = fmaxf(hk[j], 0.0f);
    }
#pragma unroll
    for (int h = 0; h < 16; h++) {
        float oq = sb2q[h], ok = sb2k[h];
        for (int j = 0; j < 32; j++) {
            oq += hq[j] * sw2q[j * 16 + h];
            ok += hk[j] * sw2k[j * 16 + h];
        }
        qbias[(size_t)token * NHEAD + h] = oq;
        kbias[(size_t)token * NHEAD + h] = ok;
    }
}

// ---------------- layernorm (optionally emits fp16) --------------------------
template <int SPLIT>
__global__ void __launch_bounds__(256) ln_kernel(
    const float* __restrict__ in, const float* __restrict__ gam,
    const float* __restrict__ bet, float* __restrict__ out,
    __half* __restrict__ of)
{
    int row = blockIdx.x, tid = threadIdx.x;
    float4 v = ((const float4*)(in + (size_t)row * D_MODEL))[tid];
    float s = v.x + v.y + v.z + v.w;
    float q = v.x * v.x + v.y * v.y + v.z * v.z + v.w * v.w;
#pragma unroll
    for (int off = 16; off; off >>= 1) {
        s += __shfl_xor_sync(0xffffffffu, s, off);
        q += __shfl_xor_sync(0xffffffffu, q, off);
    }
    __shared__ float ws[8], wq[8], stats[2];
    int lane = tid & 31, w = tid >> 5;
    if (lane == 0) { ws[w] = s; wq[w] = q; }
    __syncthreads();
    if (tid == 0) {
        float S = 0.0f, Qq = 0.0f;
        for (int i = 0; i < 8; i++) { S += ws[i]; Qq += wq[i]; }
        float mu  = S * (1.0f / D_MODEL);
        float var = Qq * (1.0f / D_MODEL) - mu * mu;
        stats[0] = mu;
        stats[1] = rsqrtf(var + 1e-5f);
    }
    __syncthreads();
    float mu = stats[0], rs = stats[1];
    float4 gv = ((const float4*)gam)[tid];
    float4 bv = ((const float4*)bet)[tid];
    float4 ov;
    ov.x = (v.x - mu) * rs * gv.x + bv.x;
    ov.y = (v.y - mu) * rs * gv.y + bv.y;
    ov.z = (v.z - mu) * rs * gv.z + bv.z;
    ov.w = (v.w - mu) * rs * gv.w + bv.w;
    ((float4*)(out + (size_t)row * D_MODEL))[tid] = ov;
    if (SPLIT) {
        size_t base = (size_t)row * D_MODEL + tid * 4;
        *(__half2*)(of + base)     = __floats2half2_rn(ov.x, ov.y);
        *(__half2*)(of + base + 2) = __floats2half2_rn(ov.z, ov.w);
    }
}

// ---------------- deterministic entropy reduction ----------------------------
__global__ void __launch_bounds__(256) ent_final_kernel(
    const float* __restrict__ part, float* __restrict__ out, int out_size)
{
    __shared__ float sm[256];
    int tid = threadIdx.x;
    sm[tid] = part[tid] + part[tid + 256];
    __syncthreads();
    for (int off = 128; off; off >>= 1) {
        if (tid < off) sm[tid] += sm[tid + off];
        __syncthreads();
    }
    if (tid == 0 && out_size > OUT_MAIN)
        out[OUT_MAIN] = sm[0] * (1.0f / (B_ * NHEAD * L_));
}

// ---------------- launch -----------------------------------------------------
extern "C" void kernel_launch(void* const* d_in, const int* in_sizes, int n_in,
                              void* d_out, int out_size)
{
    const float* src   = (const float*)d_in[0];
    const float* pos   = (const float*)d_in[1];
    const float* Wq    = (const float*)d_in[2];
    const float* bq    = (const float*)d_in[3];
    const float* Wk    = (const float*)d_in[4];
    const float* bk    = (const float*)d_in[5];
    const float* Wv    = (const float*)d_in[6];
    const float* bv    = (const float*)d_in[7];
    const float* Wo    = (const float*)d_in[8];
    const float* bo    = (const float*)d_in[9];
    const float* pq_w1 = (const float*)d_in[10];
    const float* pq_b1 = (const float*)d_in[11];
    const float* pq_w2 = (const float*)d_in[12];
    const float* pq_b2 = (const float*)d_in[13];
    const float* pk_w1 = (const float*)d_in[14];
    const float* pk_b1 = (const float*)d_in[15];
    const float* pk_w2 = (const float*)d_in[16];
    const float* pk_b2 = (const float*)d_in[17];
    const float* temp  = (const float*)d_in[18];
    const float* ln1g  = (const float*)d_in[19];
    const float* ln1b  = (const float*)d_in[20];
    const float* ln2g  = (const float*)d_in[21];
    const float* ln2b  = (const float*)d_in[22];
    const float* W1    = (const float*)d_in[23];
    const float* b1    = (const float*)d_in[24];
    const float* W2    = (const float*)d_in[25];
    const float* b2    = (const float*)d_in[26];
    float* out = (float*)d_out;

    float *xb, *yb, *qbb, *kbb, *entp, *bqkv;
    cudaGetSymbolAddress((void**)&xb, g_x);
    cudaGetSymbolAddress((void**)&yb, g_y);
    cudaGetSymbolAddress((void**)&qbb, g_qbias);
    cudaGetSymbolAddress((void**)&kbb, g_kbias);
    cudaGetSymbolAddress((void**)&entp, g_entpart);
    cudaGetSymbolAddress((void**)&bqkv, g_bqkv);

    __half *srcf, *qkv, *atf, *xf, *fff;
    __half *w4, *w116, *w216;
    cudaGetSymbolAddress((void**)&srcf, g_src_f);
    cudaGetSymbolAddress((void**)&qkv, g_qkv);
    cudaGetSymbolAddress((void**)&atf, g_at_f);
    cudaGetSymbolAddress((void**)&xf, g_x_f);
    cudaGetSymbolAddress((void**)&fff, g_ff_f);
    cudaGetSymbolAddress((void**)&w4, g_w4);
    cudaGetSymbolAddress((void**)&w116, g_w1);
    cudaGetSymbolAddress((void**)&w216, g_w2);

    __half* wo16 = w4 + 3 * (size_t)D_MODEL * D_MODEL;

    cudaFuncSetAttribute(tcgemm_kernel<1>, cudaFuncAttributeMaxDynamicSharedMemorySize, GEMM_SMEM);
    cudaFuncSetAttribute(tcgemm_kernel<2>, cudaFuncAttributeMaxDynamicSharedMemorySize, GEMM_SMEM);
    cudaFuncSetAttribute(tcgemm_kernel<3>, cudaFuncAttributeMaxDynamicSharedMemorySize, GEMM_SMEM);
    cudaFuncSetAttribute(attn_mma_kernel, cudaFuncAttributeMaxDynamicSharedMemorySize, ASMEM);

    // concat QKV biases (capturable D2D async copies)
    cudaMemcpyAsync(bqkv,                bq, D_MODEL * sizeof(float), cudaMemcpyDeviceToDevice);
    cudaMemcpyAsync(bqkv + D_MODEL,      bk, D_MODEL * sizeof(float), cudaMemcpyDeviceToDevice);
    cudaMemcpyAsync(bqkv + 2 * D_MODEL,  bv, D_MODEL * sizeof(float), cudaMemcpyDeviceToDevice);

    convT4_kernel<<<dim3(32, 32, 4), 256>>>(Wq, Wk, Wv, Wo, w4);
    convT_kernel<<<dim3(D_FF / 32, D_MODEL / 32), 256>>>(W1, w116, D_MODEL, D_FF);
    convT_kernel<<<dim3(D_MODEL / 32, D_FF / 32), 256>>>(W2, w216, D_FF, D_MODEL);

    conv_kernel<<<(M_TOK * D_MODEL / 4 + 255) / 256, 256>>>(src, srcf, M_TOK * D_MODEL / 4);
    posbias_kernel<<<M_TOK / 128, 128>>>(pos, pq_w1, pq_b1, pq_w2, pq_b2,
                                         pk_w1, pk_b1, pk_w2, pk_b2, qbb, kbb);

    // fused QKV projection
    dim3 gQKV(QKVS / BN, M_TOK / BM);
    tcgemm_kernel<3><<<gQKV, 256, GEMM_SMEM>>>(srcf, w4, bqkv, (const float*)0,
                                               (float*)0, qkv, M_TOK, QKVS, D_MODEL);

    attn_mma_kernel<<<dim3(L_ / 128, NHEAD, B_), 256, ASMEM>>>(
        qkv, qbb, kbb, temp, atf, entp);

    dim3 gD(D_MODEL / BN, M_TOK / BM);
    tcgemm_kernel<2><<<gD, 256, GEMM_SMEM>>>(atf, wo16, bo, src,
                                             yb, (__half*)0, M_TOK, D_MODEL, D_MODEL);
    ln_kernel<1><<<M_TOK, 256>>>(yb, ln1g, ln1b, xb, xf);

    dim3 gF(D_FF / BN, M_TOK / BM);
    tcgemm_kernel<1><<<gF, 256, GEMM_SMEM>>>(xf, w116, b1, (const float*)0,
                                             (float*)0, fff, M_TOK, D_FF, D_MODEL);
    tcgemm_kernel<2><<<gD, 256, GEMM_SMEM>>>(fff, w216, b2, xb,
                                             yb, (__half*)0, M_TOK, D_MODEL, D_FF);
    ln_kernel<0><<<M_TOK, 256>>>(yb, ln2g, ln2b, out, (__half*)0);

    ent_final_kernel<<<1, 256>>>(entp, out, out_size);
}

// round 14
// speedup vs baseline: 7.6570x; 1.0031x over previous
#include <cuda_runtime.h>
#include <cuda_fp16.h>
#include <math.h>
#include <stdint.h>
#include <string.h>

#define D_MODEL 1024
#define NHEAD 16
#define HEAD_DIM 64
#define B_ 2
#define L_ 2048
#define M_TOK 4096
#define D_FF 4096
#define QKVS 3072
#define OUT_MAIN (M_TOK * D_MODEL)

// ---------------- scratch (device globals; no allocations allowed) ----------
__device__ float g_x[M_TOK * D_MODEL];
__device__ float g_y[M_TOK * D_MODEL];
__device__ float g_qbias[M_TOK * NHEAD];
__device__ float g_kbias[M_TOK * NHEAD];
__device__ float g_bqkv[QKVS];
__device__ float g_entpart[1024];
// fp16 activations
__device__ __half g_src_f[M_TOK * D_MODEL];
__device__ __half g_qkv[M_TOK * QKVS];          // Q | K | V packed per row
__device__ __half g_at_f[M_TOK * D_MODEL];
__device__ __half g_x_f[M_TOK * D_MODEL];
__device__ __half g_ff_f[M_TOK * D_FF];
// fp16 transposed weights [N, K]  (wq,wk,wv,wo packed contiguously)
__device__ __half g_w4[4 * D_MODEL * D_MODEL];
__device__ __half g_w1[D_FF * D_MODEL];
__device__ __half g_w2[D_MODEL * D_FF];

// ======================= PTX helpers (baseline sm_103-legal only) ===========
__device__ __forceinline__ uint32_t smem_u32(const void* p) {
    uint32_t a;
    asm("{ .reg .u64 t; cvta.to.shared.u64 t, %1; cvt.u32.u64 %0, t; }" : "=r"(a) : "l"(p));
    return a;
}
__device__ __forceinline__ void cp16(uint32_t s, const void* g) {
    asm volatile("cp.async.cg.shared.global [%0], [%1], 16;" :: "r"(s), "l"(g));
}
__device__ __forceinline__ void cp4(uint32_t s, const void* g) {
    asm volatile("cp.async.ca.shared.global [%0], [%1], 4;" :: "r"(s), "l"(g));
}
#define CP_COMMIT() asm volatile("cp.async.commit_group;" ::: "memory")

__device__ __forceinline__ void ldsm4(uint32_t* r, uint32_t addr) {
    asm volatile("ldmatrix.sync.aligned.m8n8.x4.shared.b16 {%0,%1,%2,%3}, [%4];"
                 : "=r"(r[0]), "=r"(r[1]), "=r"(r[2]), "=r"(r[3]) : "r"(addr));
}
__device__ __forceinline__ void ldsm4t(uint32_t* r, uint32_t addr) {
    asm volatile("ldmatrix.sync.aligned.m8n8.x4.trans.shared.b16 {%0,%1,%2,%3}, [%4];"
                 : "=r"(r[0]), "=r"(r[1]), "=r"(r[2]), "=r"(r[3]) : "r"(addr));
}
__device__ __forceinline__ void mma16816(float* d, const uint32_t* a, uint32_t b0, uint32_t b1) {
    asm volatile(
        "mma.sync.aligned.m16n8k16.row.col.f32.f16.f16.f32 "
        "{%0,%1,%2,%3}, {%4,%5,%6,%7}, {%8,%9}, {%0,%1,%2,%3};"
        : "+f"(d[0]), "+f"(d[1]), "+f"(d[2]), "+f"(d[3])
        : "r"(a[0]), "r"(a[1]), "r"(a[2]), "r"(a[3]), "r"(b0), "r"(b1));
}
__device__ __forceinline__ uint32_t packh(float a, float b) {
    __half2 t = __floats2half2_rn(a, b);
    uint32_t u; memcpy(&u, &t, 4); return u;
}

// ======================= warp-MMA fp16 GEMM =================================
// BKC=64, SW128-swizzled 128B rows, 3 stages, ONE sync per chunk.
// MODE 0: fp32 +bias  MODE 1: gelu(+bias)->fp16  MODE 2: fp32 +bias+res
// MODE 3: +bias -> fp16
#define BM 128
#define BN 128
#define BKC 64
#define TILE_B (128 * 128)
#define STAGE_B (2 * TILE_B)
#define NSTAGE 3
#define GEMM_SMEM (NSTAGE * STAGE_B)

__device__ __forceinline__ void g_load_chunk(
    uint32_t smem, int ci, int m0, int n0, int K, int tid,
    const __half* __restrict__ A, const __half* __restrict__ W)
{
    uint32_t sb = smem + (uint32_t)(ci % NSTAGE) * STAGE_B;
    size_t kbase = (size_t)ci * BKC;
#pragma unroll
    for (int rep = 0; rep < 8; rep++) {
        int idx = tid + (rep << 8);
        int t = idx >> 10;
        int row = (idx >> 3) & 127;
        int seg = idx & 7;
        const __half* P = (t == 0) ? A : W;
        int r0 = (t == 0) ? m0 : n0;
        uint32_t sw = (uint32_t)((seg << 4) ^ ((row & 7) << 4));
        cp16(sb + (uint32_t)t * TILE_B + (uint32_t)(row << 7) + sw,
             P + (size_t)(r0 + row) * K + kbase + seg * 8);
    }
}

template <int MODE>
__global__ void __launch_bounds__(256, 2) tcgemm_kernel(
    const __half* __restrict__ A, const __half* __restrict__ W,
    const float* __restrict__ bias, const float* __restrict__ res,
    float* __restrict__ C, __half* __restrict__ Cf,
    int M, int N, int K)
{
    extern __shared__ char dsm[];
    uint32_t smem = smem_u32(dsm);

    int tid = threadIdx.x;
    int wid = tid >> 5;
    int lane = tid & 31;
    int m0 = blockIdx.y * BM;
    int n0 = blockIdx.x * BN;
    int nchunk = K / BKC;

    int wm = wid & 1;
    int wn = wid >> 1;
    int lr = lane & 15;
    uint32_t lk = (uint32_t)((lane >> 4) << 4);
    uint32_t swz = (uint32_t)((lr & 7) << 4);

    float acc[4][4][4];
#pragma unroll
    for (int i = 0; i < 4; i++)
#pragma unroll
        for (int j = 0; j < 4; j++)
#pragma unroll
            for (int c = 0; c < 4; c++) acc[i][j][c] = 0.0f;

    g_load_chunk(smem, 0, m0, n0, K, tid, A, W);
    CP_COMMIT();
    g_load_chunk(smem, 1, m0, n0, K, tid, A, W);
    CP_COMMIT();

    for (int i = 0; i < nchunk; i++) {
        if (i < nchunk - 1)
            asm volatile("cp.async.wait_group 1;" ::: "memory");
        else
            asm volatile("cp.async.wait_group 0;" ::: "memory");
        __syncthreads();

        if (i + 2 < nchunk) {
            g_load_chunk(smem, i + 2, m0, n0, K, tid, A, W);
            CP_COMMIT();
        }

        uint32_t sb = smem + (uint32_t)(i % NSTAGE) * STAGE_B;
        uint32_t aRow = sb + (uint32_t)((wm * 64 + lr) << 7);
        uint32_t bRow = sb + TILE_B + (uint32_t)((wn * 32 + lr) << 7);

#pragma unroll
        for (int ks = 0; ks < 4; ks++) {
            uint32_t col = ((uint32_t)(ks * 32) + lk) ^ swz;
            uint32_t ah[4][4];
#pragma unroll
            for (int mt = 0; mt < 4; mt++)
                ldsm4(ah[mt], aRow + (uint32_t)(mt << 11) + col);
#pragma unroll
            for (int nt = 0; nt < 2; nt++) {
                uint32_t bb[4];
                ldsm4(bb, bRow + (uint32_t)(nt << 11) + col);
#pragma unroll
                for (int mt = 0; mt < 4; mt++) {
                    mma16816(acc[mt][nt * 2],     ah[mt], bb[0], bb[2]);
                    mma16816(acc[mt][nt * 2 + 1], ah[mt], bb[1], bb[3]);
                }
            }
        }
    }

    int rbase = m0 + wm * 64 + (lane >> 2);
    int cbase = n0 + wn * 32 + (lane & 3) * 2;
#pragma unroll
    for (int mt = 0; mt < 4; mt++) {
#pragma unroll
        for (int n8 = 0; n8 < 4; n8++) {
            int col = cbase + n8 * 8;
            float b0 = bias[col], b1 = bias[col + 1];
#pragma unroll
            for (int half = 0; half < 2; half++) {
                int row = rbase + mt * 16 + half * 8;
                float v0 = acc[mt][n8][half * 2] + b0;
                float v1 = acc[mt][n8][half * 2 + 1] + b1;
                if (MODE == 1) {
                    v0 = 0.5f * v0 * (1.0f + erff(v0 * 0.70710678118654752f));
                    v1 = 0.5f * v1 * (1.0f + erff(v1 * 0.70710678118654752f));
                }
                if (MODE == 2) {
                    const float2 rv = *(const float2*)(res + (size_t)row * N + col);
                    v0 += rv.x; v1 += rv.y;
                }
                if (MODE == 0 || MODE == 2) {
                    float2 o; o.x = v0; o.y = v1;
                    *(float2*)(C + (size_t)row * N + col) = o;
                } else {
                    *(__half2*)(Cf + (size_t)row * N + col) = __floats2half2_rn(v0, v1);
                }
            }
        }
    }
}

// ======================= MMA flash attention ================================
// 3-stage K/V pipeline; Q staged in stage-2 area so Q/c0/c1 loads overlap.
#define ASTR 144
#define ATILE (64 * ASTR)
#define ASTAGE (2 * ATILE + 256)
#define ANST 3
#define ASMEM (ANST * ASTAGE + 64)

__device__ __forceinline__ void a_load_chunk(
    uint32_t sm0, int ci, size_t tokb, int h, int tid,
    const __half* __restrict__ QKV, const float* __restrict__ kb)
{
    uint32_t st = sm0 + (uint32_t)(ci % ANST) * ASTAGE;
    size_t rowb = tokb + (size_t)ci * 64;
#pragma unroll
    for (int r = 0; r < 4; r++) {
        int idx = tid + (r << 8);
        int t = idx >> 9;                  // 0 = K, 1 = V
        int row = (idx >> 3) & 63;
        int seg = idx & 7;
        cp16(st + (uint32_t)t * ATILE + (uint32_t)row * ASTR + (uint32_t)seg * 16,
             QKV + (rowb + row) * QKVS + (t + 1) * D_MODEL + h * HEAD_DIM + seg * 8);
    }
    if (tid < 64)
        cp4(st + 2u * ATILE + (uint32_t)tid * 4, kb + (rowb + tid) * NHEAD + h);
}

__global__ void __launch_bounds__(256, 2) attn_mma_kernel(
    const __half* __restrict__ QKV,
    const float* __restrict__ qb, const float* __restrict__ kb,
    const float* __restrict__ temp,
    __half* __restrict__ Of, float* __restrict__ ent_part)
{
    extern __shared__ char smemv[];
    uint32_t sm0 = smem_u32(smemv);
    float* red = (float*)(smemv + ANST * ASTAGE);

    int tid = threadIdx.x;
    int w = tid >> 5;
    int lane = tid & 31;
    int q0 = blockIdx.x * 128;
    int h = blockIdx.y;
    int b = blockIdx.z;
    size_t tokb = (size_t)b * L_;

    float tmph = fminf(fmaxf(temp[h], 0.1f), 5.0f);
    float inv_t = 1.0f / tmph;
    float sc = 0.125f * inv_t;

    // Q into stage-2 area (chunk 2 is the first to reuse it, after loop sync 0)
    uint32_t qarea = sm0 + 2u * ASTAGE;
    for (int i = tid; i < 128 * 8; i += 256) {
        int row = i >> 3, seg = i & 7;
        cp16(qarea + (uint32_t)row * ASTR + (uint32_t)seg * 16,
             QKV + (tokb + q0 + row) * QKVS + h * HEAD_DIM + seg * 8);
    }
    CP_COMMIT();
    a_load_chunk(sm0, 0, tokb, h, tid, QKV, kb);
    CP_COMMIT();
    a_load_chunk(sm0, 1, tokb, h, tid, QKV, kb);
    CP_COMMIT();

    asm volatile("cp.async.wait_group 2;" ::: "memory");   // Q complete
    __syncthreads();

    uint32_t qfr[4][4];
    {
        uint32_t qbase = qarea + (uint32_t)(w * 16 + (lane & 15)) * ASTR + (uint32_t)((lane >> 4) << 4);
#pragma unroll
        for (int ks = 0; ks < 4; ks++) ldsm4(qfr[ks], qbase + ks * 32);
    }
    int gid = lane >> 2, tig = lane & 3;
    int r0 = q0 + w * 16 + gid, r1 = r0 + 8;
    float qb0 = qb[(tokb + r0) * NHEAD + h] * inv_t;
    float qb1 = qb[(tokb + r1) * NHEAD + h] * inv_t;

    float O[8][4];
#pragma unroll
    for (int f = 0; f < 8; f++)
#pragma unroll
        for (int c = 0; c < 4; c++) O[f][c] = 0.0f;
    float m0 = -1e30f, m1 = -1e30f, z0 = 0.0f, z1 = 0.0f, t0 = 0.0f, t1 = 0.0f;

    const int NCH = L_ / 64;
    for (int ci = 0; ci < NCH; ci++) {
        if (ci < NCH - 1)
            asm volatile("cp.async.wait_group 1;" ::: "memory");
        else
            asm volatile("cp.async.wait_group 0;" ::: "memory");
        __syncthreads();   // at ci=0 this also fences Q-frag extraction vs chunk-2 prefetch

        if (ci + 2 < NCH) {
            a_load_chunk(sm0, ci + 2, tokb, h, tid, QKV, kb);
            CP_COMMIT();
        }

        uint32_t st = sm0 + (uint32_t)(ci % ANST) * ASTAGE;
        uint32_t kbh = st + (uint32_t)(lane & 15) * ASTR + (uint32_t)((lane >> 4) << 4);

        float S[8][4];
#pragma unroll
        for (int f = 0; f < 8; f++)
#pragma unroll
            for (int c = 0; c < 4; c++) S[f][c] = 0.0f;

#pragma unroll
        for (int ks = 0; ks < 4; ks++) {
            uint32_t koff = (uint32_t)ks * 32;
#pragma unroll
            for (int nt = 0; nt < 4; nt++) {
                uint32_t bb[4];
                ldsm4(bb, kbh + (uint32_t)(nt * 16) * ASTR + koff);
                mma16816(S[nt * 2],     qfr[ks], bb[0], bb[2]);
                mma16816(S[nt * 2 + 1], qfr[ks], bb[1], bb[3]);
            }
        }

        const float* kbs = (const float*)(smemv + (size_t)((ci % ANST) * ASTAGE + 2 * ATILE));
        float mx0 = -1e30f, mx1 = -1e30f;
#pragma unroll
        for (int f = 0; f < 8; f++) {
            float kc0 = kbs[f * 8 + 2 * tig] * inv_t;
            float kc1 = kbs[f * 8 + 2 * tig + 1] * inv_t;
            S[f][0] = S[f][0] * sc + qb0 + kc0;
            S[f][1] = S[f][1] * sc + qb0 + kc1;
            S[f][2] = S[f][2] * sc + qb1 + kc0;
            S[f][3] = S[f][3] * sc + qb1 + kc1;
            mx0 = fmaxf(mx0, fmaxf(S[f][0], S[f][1]));
            mx1 = fmaxf(mx1, fmaxf(S[f][2], S[f][3]));
        }
        mx0 = fmaxf(mx0, __shfl_xor_sync(0xffffffffu, mx0, 1));
        mx0 = fmaxf(mx0, __shfl_xor_sync(0xffffffffu, mx0, 2));
        mx1 = fmaxf(mx1, __shfl_xor_sync(0xffffffffu, mx1, 1));
        mx1 = fmaxf(mx1, __shfl_xor_sync(0xffffffffu, mx1, 2));

        float nm0 = fmaxf(m0, mx0), nm1 = fmaxf(m1, mx1);
        float sc0 = __expf(m0 - nm0), sc1 = __expf(m1 - nm1);
        float zc0 = 0.0f, zc1 = 0.0f, tc0 = 0.0f, tc1 = 0.0f;
        uint32_t pa[4][4];
#pragma unroll
        for (int j = 0; j < 4; j++) {
#pragma unroll
            for (int g = 0; g < 2; g++) {
                int f = 2 * j + g;
                float p0 = __expf(S[f][0] - nm0);
                float p1 = __expf(S[f][1] - nm0);
                float p2 = __expf(S[f][2] - nm1);
                float p3 = __expf(S[f][3] - nm1);
                zc0 += p0 + p1; zc1 += p2 + p3;
                tc0 += p0 * S[f][0] + p1 * S[f][1];
                tc1 += p2 * S[f][2] + p3 * S[f][3];
                pa[j][g * 2]     = packh(p0, p1);
                pa[j][g * 2 + 1] = packh(p2, p3);
            }
        }
        zc0 += __shfl_xor_sync(0xffffffffu, zc0, 1); zc0 += __shfl_xor_sync(0xffffffffu, zc0, 2);
        zc1 += __shfl_xor_sync(0xffffffffu, zc1, 1); zc1 += __shfl_xor_sync(0xffffffffu, zc1, 2);
        tc0 += __shfl_xor_sync(0xffffffffu, tc0, 1); tc0 += __shfl_xor_sync(0xffffffffu, tc0, 2);
        tc1 += __shfl_xor_sync(0xffffffffu, tc1, 1); tc1 += __shfl_xor_sync(0xffffffffu, tc1, 2);
        z0 = z0 * sc0 + zc0; t0 = t0 * sc0 + tc0; m0 = nm0;
        z1 = z1 * sc1 + zc1; t1 = t1 * sc1 + tc1; m1 = nm1;
#pragma unroll
        for (int f = 0; f < 8; f++) {
            O[f][0] *= sc0; O[f][1] *= sc0; O[f][2] *= sc1; O[f][3] *= sc1;
        }

        uint32_t vb = st + ATILE + (uint32_t)(lane & 15) * ASTR + (uint32_t)((lane >> 4) << 4);
#pragma unroll
        for (int j = 0; j < 4; j++) {
            uint32_t vrow = vb + (uint32_t)(j * 16) * ASTR;
#pragma unroll
            for (int hg = 0; hg < 4; hg++) {
                uint32_t v[4];
                ldsm4t(v, vrow + (uint32_t)hg * 32);
                mma16816(O[hg * 2],     pa[j], v[0], v[1]);
                mma16816(O[hg * 2 + 1], pa[j], v[2], v[3]);
            }
        }
    }

    float iz0 = 1.0f / z0, iz1 = 1.0f / z1;
    size_t row0b = (tokb + r0) * D_MODEL, row1b = (tokb + r1) * D_MODEL;
#pragma unroll
    for (int f = 0; f < 8; f++) {
        int col = h * HEAD_DIM + f * 8 + 2 * tig;
        *(__half2*)(Of + row0b + col) = __floats2half2_rn(O[f][0] * iz0, O[f][1] * iz0);
        *(__half2*)(Of + row1b + col) = __floats2half2_rn(O[f][2] * iz1, O[f][3] * iz1);
    }

    float Hv = (m0 + logf(z0) - t0 / z0 + m1 + logf(z1) - t1 / z1) * 0.25f;
#pragma unroll
    for (int off = 16; off; off >>= 1) Hv += __shfl_xor_sync(0xffffffffu, Hv, off);
    if (lane == 0) red[w] = Hv;
    __syncthreads();
    if (tid == 0) {
        float s = 0.0f;
#pragma unroll
        for (int i = 0; i < 8; i++) s += red[i];
        ent_part[((b * NHEAD + h) << 4) + blockIdx.x] = s;
    }
}

// ======================= all weight transposes in ONE launch ================
// blocks [0,4096): wq/wk/wv/wo slabs; [4096,8192): W1; [8192,12288): W2
__global__ void __launch_bounds__(256) convAll_kernel(
    const float* __restrict__ Wq, const float* __restrict__ Wk,
    const float* __restrict__ Wv, const float* __restrict__ Wo,
    const float* __restrict__ W1, const float* __restrict__ W2,
    __half* __restrict__ w4, __half* __restrict__ w1o, __half* __restrict__ w2o)
{
    __shared__ float t[32][33];
    int id = blockIdx.x;
    const float* W; __half* dst; int K, N, n0, k0;
    if (id < 4096) {
        int slab = id >> 10, tt = id & 1023;
        W = (slab == 0) ? Wq : (slab == 1) ? Wk : (slab == 2) ? Wv : Wo;
        dst = w4 + (size_t)slab * D_MODEL * D_MODEL;
        K = D_MODEL; N = D_MODEL;
        n0 = (tt & 31) << 5; k0 = (tt >> 5) << 5;
    } else if (id < 8192) {
        int tt = id - 4096;
        W = W1; dst = w1o; K = D_MODEL; N = D_FF;
        n0 = (tt & 127) << 5; k0 = (tt >> 7) << 5;
    } else {
        int tt = id - 8192;
        W = W2; dst = w2o; K = D_FF; N = D_MODEL;
        n0 = (tt & 31) << 5; k0 = (tt >> 5) << 5;
    }
    int tx = threadIdx.x & 31, ty = threadIdx.x >> 5;
#pragma unroll
    for (int i = 0; i < 32; i += 8)
        t[ty + i][tx] = W[(size_t)(k0 + ty + i) * N + n0 + tx];
    __syncthreads();
#pragma unroll
    for (int i = 0; i < 32; i += 8)
        dst[(size_t)(n0 + ty + i) * K + k0 + tx] = __float2half_rn(t[tx][ty + i]);
}

// src -> fp16, plus last block concatenates QKV biases
__global__ void __launch_bounds__(256) conv_kernel(
    const float* __restrict__ in, __half* __restrict__ outp, int n4,
    const float* __restrict__ bq, const float* __restrict__ bk,
    const float* __restrict__ bv, float* __restrict__ bqkv)
{
    if (blockIdx.x == gridDim.x - 1) {
        int tid = threadIdx.x;
        for (int i = tid; i < D_MODEL; i += 256) {
            bqkv[i] = bq[i];
            bqkv[i + D_MODEL] = bk[i];
            bqkv[i + 2 * D_MODEL] = bv[i];
        }
        return;
    }
    int i = blockIdx.x * 256 + threadIdx.x;
    if (i >= n4) return;
    float4 v = ((const float4*)in)[i];
    ((__half2*)outp)[i * 2]     = __floats2half2_rn(v.x, v.y);
    ((__half2*)outp)[i * 2 + 1] = __floats2half2_rn(v.z, v.w);
}

// ---------------- POS bias MLPs ----------------------------------------------
__global__ void __launch_bounds__(128) posbias_kernel(
    const float* __restrict__ pos,
    const float* __restrict__ qw1, const float* __restrict__ qb1,
    const float* __restrict__ qw2, const float* __restrict__ qb2,
    const float* __restrict__ kw1, const float* __restrict__ kb1,
    const float* __restrict__ kw2, const float* __restrict__ kb2,
    float* __restrict__ qbias, float* __restrict__ kbias)
{
    __shared__ float sw1q[32 * 32], sw2q[32 * 16], sb1q[32], sb2q[16];
    __shared__ float sw1k[32 * 32], sw2k[32 * 16], sb1k[32], sb2k[16];
    int tid = threadIdx.x;
    for (int i = tid; i < 1024; i += 128) { sw1q[i] = qw1[i]; sw1k[i] = kw1[i]; }
    for (int i = tid; i < 512;  i += 128) { sw2q[i] = qw2[i]; sw2k[i] = kw2[i]; }
    if (tid < 32) { sb1q[tid] = qb1[tid]; sb1k[tid] = kb1[tid]; }
    if (tid < 16) { sb2q[tid] = qb2[tid]; sb2k[tid] = kb2[tid]; }
    __syncthreads();

    int token = blockIdx.x * 128 + tid;
    float pf[32];
#pragma unroll
    for (int i = 0; i < 32; i++) pf[i] = pos[(size_t)token * 32 + i];

    float hq[32], hk[32];
#pragma unroll
    for (int j = 0; j < 32; j++) { hq[j] = sb1q[j]; hk[j] = sb1k[j]; }
    for (int i = 0; i < 32; i++) {
        float p = pf[i];
#pragma unroll
        for (int j = 0; j < 32; j++) {
            hq[j] += p * sw1q[i * 32 + j];
            hk[j] += p * sw1k[i * 32 + j];
        }
    }
#pragma unroll
    for (int j = 0; j < 32; j++) {
        hq[j] = fmaxf(hq[j], 0.0f);
        hk[j] = fmaxf(hk[j], 0.0f);
    }
#pragma unroll
    for (int h = 0; h < 16; h++) {
        float oq = sb2q[h], ok = sb2k[h];
        for (int j = 0; j < 32; j++) {
            oq += hq[j] * sw2q[j * 16 + h];
            ok += hk[j] * sw2k[j * 16 + h];
        }
        qbias[(size_t)token * NHEAD + h] = oq;
        kbias[(size_t)token * NHEAD + h] = ok;
    }
}

// ---------------- layernorm (optionally emits fp16) --------------------------
template <int SPLIT>
__global__ void __launch_bounds__(256) ln_kernel(
    const float* __restrict__ in, const float* __restrict__ gam,
    const float* __restrict__ bet, float* __restrict__ out,
    __half* __restrict__ of)
{
    int row = blockIdx.x, tid = threadIdx.x;
    float4 v = ((const float4*)(in + (size_t)row * D_MODEL))[tid];
    float s = v.x + v.y + v.z + v.w;
    float q = v.x * v.x + v.y * v.y + v.z * v.z + v.w * v.w;
#pragma unroll
    for (int off = 16; off; off >>= 1) {
        s += __shfl_xor_sync(0xffffffffu, s, off);
        q += __shfl_xor_sync(0xffffffffu, q, off);
    }
    __shared__ float ws[8], wq[8], stats[2];
    int lane = tid & 31, w = tid >> 5;
    if (lane == 0) { ws[w] = s; wq[w] = q; }
    __syncthreads();
    if (tid == 0) {
        float S = 0.0f, Qq = 0.0f;
        for (int i = 0; i < 8; i++) { S += ws[i]; Qq += wq[i]; }
        float mu  = S * (1.0f / D_MODEL);
        float var = Qq * (1.0f / D_MODEL) - mu * mu;
        stats[0] = mu;
        stats[1] = rsqrtf(var + 1e-5f);
    }
    __syncthreads();
    float mu = stats[0], rs = stats[1];
    float4 gv = ((const float4*)gam)[tid];
    float4 bv = ((const float4*)bet)[tid];
    float4 ov;
    ov.x = (v.x - mu) * rs * gv.x + bv.x;
    ov.y = (v.y - mu) * rs * gv.y + bv.y;
    ov.z = (v.z - mu) * rs * gv.z + bv.z;
    ov.w = (v.w - mu) * rs * gv.w + bv.w;
    ((float4*)(out + (size_t)row * D_MODEL))[tid] = ov;
    if (SPLIT) {
        size_t base = (size_t)row * D_MODEL + tid * 4;
        *(__half2*)(of + base)     = __floats2half2_rn(ov.x, ov.y);
        *(__half2*)(of + base + 2) = __floats2half2_rn(ov.z, ov.w);
    }
}

// ---------------- deterministic entropy reduction ----------------------------
__global__ void __launch_bounds__(256) ent_final_kernel(
    const float* __restrict__ part, float* __restrict__ out, int out_size)
{
    __shared__ float sm[256];
    int tid = threadIdx.x;
    sm[tid] = part[tid] + part[tid + 256];
    __syncthreads();
    for (int off = 128; off; off >>= 1) {
        if (tid < off) sm[tid] += sm[tid + off];
        __syncthreads();
    }
    if (tid == 0 && out_size > OUT_MAIN)
        out[OUT_MAIN] = sm[0] * (1.0f / (B_ * NHEAD * L_));
}

// ---------------- launch -----------------------------------------------------
extern "C" void kernel_launch(void* const* d_in, const int* in_sizes, int n_in,
                              void* d_out, int out_size)
{
    const float* src   = (const float*)d_in[0];
    const float* pos   = (const float*)d_in[1];
    const float* Wq    = (const float*)d_in[2];
    const float* bq    = (const float*)d_in[3];
    const float* Wk    = (const float*)d_in[4];
    const float* bk    = (const float*)d_in[5];
    const float* Wv    = (const float*)d_in[6];
    const float* bv    = (const float*)d_in[7];
    const float* Wo    = (const float*)d_in[8];
    const float* bo    = (const float*)d_in[9];
    const float* pq_w1 = (const float*)d_in[10];
    const float* pq_b1 = (const float*)d_in[11];
    const float* pq_w2 = (const float*)d_in[12];
    const float* pq_b2 = (const float*)d_in[13];
    const float* pk_w1 = (const float*)d_in[14];
    const float* pk_b1 = (const float*)d_in[15];
    const float* pk_w2 = (const float*)d_in[16];
    const float* pk_b2 = (const float*)d_in[17];
    const float* temp  = (const float*)d_in[18];
    const float* ln1g  = (const float*)d_in[19];
    const float* ln1b  = (const float*)d_in[20];
    const float* ln2g  = (const float*)d_in[21];
    const float* ln2b  = (const float*)d_in[22];
    const float* W1    = (const float*)d_in[23];
    const float* b1    = (const float*)d_in[24];
    const float* W2    = (const float*)d_in[25];
    const float* b2    = (const float*)d_in[26];
    float* out = (float*)d_out;

    float *xb, *yb, *qbb, *kbb, *entp, *bqkv;
    cudaGetSymbolAddress((void**)&xb, g_x);
    cudaGetSymbolAddress((void**)&yb, g_y);
    cudaGetSymbolAddress((void**)&qbb, g_qbias);
    cudaGetSymbolAddress((void**)&kbb, g_kbias);
    cudaGetSymbolAddress((void**)&entp, g_entpart);
    cudaGetSymbolAddress((void**)&bqkv, g_bqkv);

    __half *srcf, *qkv, *atf, *xf, *fff;
    __half *w4, *w116, *w216;
    cudaGetSymbolAddress((void**)&srcf, g_src_f);
    cudaGetSymbolAddress((void**)&qkv, g_qkv);
    cudaGetSymbolAddress((void**)&atf, g_at_f);
    cudaGetSymbolAddress((void**)&xf, g_x_f);
    cudaGetSymbolAddress((void**)&fff, g_ff_f);
    cudaGetSymbolAddress((void**)&w4, g_w4);
    cudaGetSymbolAddress((void**)&w116, g_w1);
    cudaGetSymbolAddress((void**)&w216, g_w2);

    __half* wo16 = w4 + 3 * (size_t)D_MODEL * D_MODEL;

    cudaFuncSetAttribute(tcgemm_kernel<1>, cudaFuncAttributeMaxDynamicSharedMemorySize, GEMM_SMEM);
    cudaFuncSetAttribute(tcgemm_kernel<2>, cudaFuncAttributeMaxDynamicSharedMemorySize, GEMM_SMEM);
    cudaFuncSetAttribute(tcgemm_kernel<3>, cudaFuncAttributeMaxDynamicSharedMemorySize, GEMM_SMEM);
    cudaFuncSetAttribute(attn_mma_kernel, cudaFuncAttributeMaxDynamicSharedMemorySize, ASMEM);

    // all weight transposes in one launch
    convAll_kernel<<<12288, 256>>>(Wq, Wk, Wv, Wo, W1, W2, w4, w116, w216);

    // src -> fp16 (+ bias concat in last block)
    conv_kernel<<<M_TOK * D_MODEL / 4 / 256 + 1, 256>>>(src, srcf, M_TOK * D_MODEL / 4,
                                                        bq, bk, bv, bqkv);
    posbias_kernel<<<M_TOK / 128, 128>>>(pos, pq_w1, pq_b1, pq_w2, pq_b2,
                                         pk_w1, pk_b1, pk_w2, pk_b2, qbb, kbb);

    // fused QKV projection
    dim3 gQKV(QKVS / BN, M_TOK / BM);
    tcgemm_kernel<3><<<gQKV, 256, GEMM_SMEM>>>(srcf, w4, bqkv, (const float*)0,
                                               (float*)0, qkv, M_TOK, QKVS, D_MODEL);

    attn_mma_kernel<<<dim3(L_ / 128, NHEAD, B_), 256, ASMEM>>>(
        qkv, qbb, kbb, temp, atf, entp);

    dim3 gD(D_MODEL / BN, M_TOK / BM);
    tcgemm_kernel<2><<<gD, 256, GEMM_SMEM>>>(atf, wo16, bo, src,
                                             yb, (__half*)0, M_TOK, D_MODEL, D_MODEL);
    ln_kernel<1><<<M_TOK, 256>>>(yb, ln1g, ln1b, xb, xf);

    dim3 gF(D_FF / BN, M_TOK / BM);
    tcgemm_kernel<1><<<gF, 256, GEMM_SMEM>>>(xf, w116, b1, (const float*)0,
                                             (float*)0, fff, M_TOK, D_FF, D_MODEL);
    tcgemm_kernel<2><<<gD, 256, GEMM_SMEM>>>(fff, w216, b2, xb,
                                             yb, (__half*)0, M_TOK, D_MODEL, D_FF);
    ln_kernel<0><<<M_TOK, 256>>>(yb, ln2g, ln2b, out, (__half*)0);

    ent_final_kernel<<<1, 256>>>(entp, out, out_size);
}